// round 8
// baseline (speedup 1.0000x reference)
#include <cuda_runtime.h>
#include <math.h>

#define NR  16385
#define NPD 16640
#define NH  8
#define DH  64
#define LM  256
#define KC  13          // split-K chunks for a3@v (13*1280 = 16640)

// ---------------- scratch (device globals, allocation-free) ----------------
__device__ float g_h  [NR  * 512];
__device__ float g_h2 [NR  * 512];
__device__ float g_xp [NPD * 512];
__device__ float g_qkv[NPD * 1536];
__device__ float g_ao [NR  * 512];
__device__ float g_ql [NH * LM * DH];
__device__ float g_kl [NH * LM * DH];
__device__ float g_a2 [NH * LM * LM];
__device__ float g_z  [NH * LM * LM];
__device__ float g_zb [NH * LM * LM];
__device__ float g_az [NH * LM * LM];
__device__ float g_t1 [NH * LM * LM];
__device__ float g_t2 [NH * LM * LM];
__device__ float g_a3 [NH * LM * NPD];
__device__ float g_p3 [KC * NH * LM * DH];
__device__ float g_o3 [NH * LM * DH];
__device__ float g_w2 [NH * LM * DH];
__device__ float g_mx [2 * NH];
__device__ float g_den;

// ---------------- reductions ----------------
__device__ __forceinline__ float wSum(float v){
#pragma unroll
  for(int o=16;o>0;o>>=1) v += __shfl_xor_sync(0xffffffffu,v,o);
  return v;
}
__device__ __forceinline__ float wMax(float v){
#pragma unroll
  for(int o=16;o>0;o>>=1) v = fmaxf(v,__shfl_xor_sync(0xffffffffu,v,o));
  return v;
}
__device__ __forceinline__ float bSum(float v, float* red){
  int w=threadIdx.x>>5, l=threadIdx.x&31, nw=(blockDim.x+31)>>5;
  v=wSum(v); if(l==0) red[w]=v; __syncthreads();
  if(w==0){ float r=(l<nw)?red[l]:0.f; r=wSum(r); if(l==0) red[0]=r; }
  __syncthreads(); float r=red[0]; __syncthreads(); return r;
}
__device__ __forceinline__ float bMax(float v, float* red){
  int w=threadIdx.x>>5, l=threadIdx.x&31, nw=(blockDim.x+31)>>5;
  v=wMax(v); if(l==0) red[w]=v; __syncthreads();
  if(w==0){ float r=(l<nw)?red[l]:-3.4e38f; r=wMax(r); if(l==0) red[0]=r; }
  __syncthreads(); float r=red[0]; __syncthreads(); return r;
}

// ---------------- generic SGEMM: C=A@B (+epilogue). N%128==0, K%8==0 -------
// MODE 0: C=AB   MODE 1: C=relu(AB+bias)   MODE 2: C += AB + bias
template<int MODE>
__global__ __launch_bounds__(256) void sgemm_k(
    const float* __restrict__ A, const float* __restrict__ B, float* __restrict__ Cd,
    const float* __restrict__ bias, int M, int N, int K)
{
  __shared__ float As[8][128];
  __shared__ float Bs[8][128];
  int t=threadIdx.x, row0=blockIdx.y*128, col0=blockIdx.x*128;
  int tx=t&15, ty=t>>4;
  int arow=t>>1, acol=(t&1)*4;
  int brow=t>>5, bcol=(t&31)*4;
  float acc[8][8];
#pragma unroll
  for(int i=0;i<8;i++)
#pragma unroll
    for(int j=0;j<8;j++) acc[i][j]=0.f;
  bool aval=(row0+arow)<M;
  const float* Ap=A+(size_t)(row0+arow)*K+acol;
  const float* Bp=B+(size_t)brow*N+col0+bcol;
  for(int k0=0;k0<K;k0+=8){
    float4 av=make_float4(0,0,0,0);
    if(aval) av=*(const float4*)(Ap+k0);
    As[acol][arow]=av.x; As[acol+1][arow]=av.y; As[acol+2][arow]=av.z; As[acol+3][arow]=av.w;
    *(float4*)&Bs[brow][bcol]=*(const float4*)(Bp+(size_t)k0*N);
    __syncthreads();
#pragma unroll
    for(int k=0;k<8;k++){
      float a[8],b[8];
      *(float4*)a    =*(const float4*)&As[k][ty*8];
      *(float4*)(a+4)=*(const float4*)&As[k][ty*8+4];
      *(float4*)b    =*(const float4*)&Bs[k][tx*8];
      *(float4*)(b+4)=*(const float4*)&Bs[k][tx*8+4];
#pragma unroll
      for(int i=0;i<8;i++)
#pragma unroll
        for(int j=0;j<8;j++) acc[i][j]+=a[i]*b[j];
    }
    __syncthreads();
  }
#pragma unroll
  for(int i=0;i<8;i++){
    int r=row0+ty*8+i; if(r>=M) continue;
    size_t off=(size_t)r*N+col0+tx*8;
#pragma unroll
    for(int j=0;j<8;j++){
      float v=acc[i][j]; int cc=col0+tx*8+j;
      if(MODE==1){ v+=bias[cc]; v=v>0.f?v:0.f; Cd[off+j]=v; }
      else if(MODE==2){ Cd[off+j]+=v+bias[cc]; }
      else Cd[off+j]=v;
    }
  }
}

// ------------- batched 8-head GEMM: C = c0*(A@B) + c1*A, A is 256x256 ------
__global__ __launch_bounds__(256) void g256_k(
    const float* __restrict__ A, const float* __restrict__ B, float* __restrict__ Cd,
    int N, float c0, float c1)
{
  __shared__ float As[16][64];
  __shared__ float Bs[16][64];
  const float* Ah=A+(size_t)blockIdx.z*65536;
  const float* Bh=B+(size_t)blockIdx.z*256*N;
  float* Ch=Cd+(size_t)blockIdx.z*256*N;
  int t=threadIdx.x, tx=t&15, ty=t>>4;
  int row0=blockIdx.y*64, col0=blockIdx.x*64;
  int arow=t>>2, acol=(t&3)*4;
  int brow=t>>4, bcol=(t&15)*4;
  float acc[4][4];
#pragma unroll
  for(int i=0;i<4;i++)
#pragma unroll
    for(int j=0;j<4;j++) acc[i][j]=0.f;
  for(int k0=0;k0<256;k0+=16){
    float4 av=*(const float4*)(Ah+(size_t)(row0+arow)*256+k0+acol);
    As[acol][arow]=av.x; As[acol+1][arow]=av.y; As[acol+2][arow]=av.z; As[acol+3][arow]=av.w;
    *(float4*)&Bs[brow][bcol]=*(const float4*)(Bh+(size_t)(k0+brow)*N+col0+bcol);
    __syncthreads();
#pragma unroll
    for(int k=0;k<16;k++){
      float a[4],b[4];
      *(float4*)a=*(const float4*)&As[k][ty*4];
      *(float4*)b=*(const float4*)&Bs[k][tx*4];
#pragma unroll
      for(int i=0;i<4;i++)
#pragma unroll
        for(int j=0;j<4;j++) acc[i][j]+=a[i]*b[j];
    }
    __syncthreads();
  }
#pragma unroll
  for(int i=0;i<4;i++){
    int r=row0+ty*4+i;
#pragma unroll
    for(int j=0;j<4;j++){
      int cc=col0+tx*4+j;
      float v=c0*acc[i][j];
      if(c1!=0.f) v+=c1*Ah[(size_t)r*256+cc];
      Ch[(size_t)r*N+cc]=v;
    }
  }
}

// ------------- LayerNorm + front-pad to NPD rows ---------------------------
__global__ __launch_bounds__(256) void ln_pad_k(const float* __restrict__ hin,
    const float* __restrict__ g, const float* __restrict__ b)
{
  int row=blockIdx.x, t=threadIdx.x;
  float* out=g_xp+(size_t)row*512;
  if(row<255){ out[t]=0.f; out[t+256]=0.f; return; }
  __shared__ float red[32];
  const float* x=hin+(size_t)(row-255)*512;
  float v0=x[t], v1=x[t+256];
  float mean=bSum(v0+v1,red)*(1.f/512.f);
  float d0=v0-mean, d1=v1-mean;
  float var=bSum(d0*d0+d1*d1,red)*(1.f/512.f);
  float rs=1.f/sqrtf(var+1e-5f);
  out[t]=d0*rs*g[t]+b[t];
  out[t+256]=d1*rs*g[t+256]+b[t+256];
}

// ------------- landmarks: mean of 65 consecutive rows ----------------------
__global__ void landmarks_k()
{
  int m=blockIdx.x, h=blockIdx.y, d=threadIdx.x;
  const float* base=g_qkv+(size_t)(m*65)*1536+h*64+d;
  float sq=0.f, sk=0.f;
  for(int j=0;j<65;j++){ sq+=base[(size_t)j*1536]; sk+=base[(size_t)j*1536+512]; }
  g_ql[(h*LM+m)*DH+d]=sq*(0.125f/65.f);
  g_kl[(h*LM+m)*DH+d]=sk*(1.f/65.f);
}

// ------------- a2 = softmax(q_l @ k_l^T) -----------------------------------
__global__ __launch_bounds__(256) void a2_k()
{
  int i=blockIdx.x, h=blockIdx.y, j=threadIdx.x;
  __shared__ float q[DH]; __shared__ float red[32];
  if(j<DH) q[j]=g_ql[(h*LM+i)*DH+j];
  __syncthreads();
  const float* kr=&g_kl[(h*LM+j)*DH];
  float s=0.f;
#pragma unroll
  for(int d=0;d<DH;d++) s+=q[d]*kr[d];
  float mx=bMax(s,red);
  float p=expf(s-mx);
  float ss=bSum(p,red);
  g_a2[((size_t)(h*LM+i))*LM+j]=p/ss;
}

// ------------- pinv init: row/col-sum maxima, denom, z0 = a2^T/den ---------
__global__ __launch_bounds__(256) void sums_k()
{
  int h=blockIdx.x, t=threadIdx.x;
  __shared__ float red[32];
  const float* a=g_a2+(size_t)h*LM*LM;
  float rs=0.f, cs=0.f;
  for(int j=0;j<LM;j++){ rs+=fabsf(a[(size_t)t*LM+j]); cs+=fabsf(a[(size_t)j*LM+t]); }
  float rm=bMax(rs,red), cm=bMax(cs,red);
  if(t==0){ g_mx[h]=rm; g_mx[NH+h]=cm; }
}
__global__ void denom_k()
{
  int t=threadIdx.x;
  float rm=(t<NH)?g_mx[t]:-3.4e38f, cm=(t<NH)?g_mx[NH+t]:-3.4e38f;
  rm=wMax(rm); cm=wMax(cm);
  if(t==0) g_den=rm*cm;
}
__global__ __launch_bounds__(256) void zinit_k()
{
  int i=blockIdx.x, h=blockIdx.y, j=threadIdx.x;
  float inv=1.f/g_den;
  g_z[((size_t)h*LM+i)*LM+j]=g_a2[((size_t)h*LM+j)*LM+i]*inv;
}

// ------------- a3 logits: q_l(256x64) @ k^T (per head) ---------------------
__global__ __launch_bounds__(256) void qkT_k()
{
  __shared__ float As[8][128];
  __shared__ float Bs[8][128];
  int t=threadIdx.x, h=blockIdx.z;
  int col0=blockIdx.x*128, row0=blockIdx.y*128;
  int tx=t&15, ty=t>>4;
  int arow=t>>1, acol=(t&1)*4;
  int bj=t&127, kh=t>>7;
  float acc[8][8];
#pragma unroll
  for(int i=0;i<8;i++)
#pragma unroll
    for(int j=0;j<8;j++) acc[i][j]=0.f;
  for(int k0=0;k0<64;k0+=8){
    float4 av=*(const float4*)(g_ql+(size_t)h*LM*DH+(size_t)(row0+arow)*64+k0+acol);
    As[acol][arow]=av.x; As[acol+1][arow]=av.y; As[acol+2][arow]=av.z; As[acol+3][arow]=av.w;
    float4 bv=*(const float4*)(g_qkv+(size_t)(col0+bj)*1536+512+h*64+k0+kh*4);
    Bs[kh*4][bj]=bv.x; Bs[kh*4+1][bj]=bv.y; Bs[kh*4+2][bj]=bv.z; Bs[kh*4+3][bj]=bv.w;
    __syncthreads();
#pragma unroll
    for(int k=0;k<8;k++){
      float a[8],b[8];
      *(float4*)a    =*(const float4*)&As[k][ty*8];
      *(float4*)(a+4)=*(const float4*)&As[k][ty*8+4];
      *(float4*)b    =*(const float4*)&Bs[k][tx*8];
      *(float4*)(b+4)=*(const float4*)&Bs[k][tx*8+4];
#pragma unroll
      for(int i=0;i<8;i++)
#pragma unroll
        for(int j=0;j<8;j++) acc[i][j]+=a[i]*b[j];
    }
    __syncthreads();
  }
#pragma unroll
  for(int i=0;i<8;i++){
    size_t off=((size_t)h*LM+row0+ty*8+i)*NPD+col0+tx*8;
#pragma unroll
    for(int j=0;j<8;j++) g_a3[off+j]=acc[i][j];
  }
}

// ------------- a3 row softmax over 16640 keys ------------------------------
__global__ __launch_bounds__(256) void a3soft_k()
{
  int i=blockIdx.x, h=blockIdx.y, t=threadIdx.x;
  __shared__ float red[32];
  float* p=g_a3+((size_t)h*LM+i)*NPD;
  float m=-3.4e38f;
  for(int j=t;j<NPD;j+=256) m=fmaxf(m,p[j]);
  float M=bMax(m,red);
  float s=0.f;
  for(int j=t;j<NPD;j+=256) s+=__expf(p[j]-M);
  float S=bSum(s,red);
  float inv=1.f/S;
  for(int j=t;j<NPD;j+=256) p[j]=__expf(p[j]-M)*inv;
}

// ------------- a3v split-K: partial[kc] = a3[:,chunk] @ v[chunk,:] ---------
__global__ __launch_bounds__(256) void a3v_k()
{
  __shared__ float As[16][64];
  __shared__ float Bs[16][64];
  int t=threadIdx.x, h=blockIdx.y, kc=blockIdx.z;
  int m0=blockIdx.x*64, kbase=kc*1280;
  int tx=t&15, ty=t>>4;
  int arow=t>>2, acol=(t&3)*4;
  int brow=t>>4, bcol=(t&15)*4;
  float acc[4][4];
#pragma unroll
  for(int i=0;i<4;i++)
#pragma unroll
    for(int j=0;j<4;j++) acc[i][j]=0.f;
  const float* Ah=g_a3+((size_t)h*LM+m0)*NPD;
  for(int k0=0;k0<1280;k0+=16){
    float4 av=*(const float4*)(Ah+(size_t)arow*NPD+kbase+k0+acol);
    As[acol][arow]=av.x; As[acol+1][arow]=av.y; As[acol+2][arow]=av.z; As[acol+3][arow]=av.w;
    *(float4*)&Bs[brow][bcol]=*(const float4*)(g_qkv+(size_t)(kbase+k0+brow)*1536+1024+h*64+bcol);
    __syncthreads();
#pragma unroll
    for(int k=0;k<16;k++){
      float a[4],b[4];
      *(float4*)a=*(const float4*)&As[k][ty*4];
      *(float4*)b=*(const float4*)&Bs[k][tx*4];
#pragma unroll
      for(int i=0;i<4;i++)
#pragma unroll
        for(int j=0;j<4;j++) acc[i][j]+=a[i]*b[j];
    }
    __syncthreads();
  }
#pragma unroll
  for(int i=0;i<4;i++)
#pragma unroll
    for(int j=0;j<4;j++)
      g_p3[((size_t)kc*NH+h)*LM*DH+(size_t)(m0+ty*4+i)*DH+tx*4+j]=acc[i][j];
}
__global__ void a3vred_k()
{
  int idx=blockIdx.x*256+threadIdx.x;
  float s=0.f;
  for(int kc=0;kc<KC;kc++) s+=g_p3[(size_t)kc*NH*LM*DH+idx];
  g_o3[idx]=s;
}

// ------------- fused a1@W2 + depthwise-33 residual -------------------------
#define CH 128
__global__ __launch_bounds__(256) void a1res_k(const float* __restrict__ rw,
                                               int row_start, int row_cnt)
{
  extern __shared__ float sm[];
  float* kls=sm;               // 256*65
  float* w2s=sm+16640;         // 256*65
  float* vs =sm+33280;         // 160*64
  float* rws=sm+43520;         // 33
  float* qs =sm+43560;         // 64
  float* ps =sm+43624;         // 256
  float* op =sm+43880;         // 256
  float* red=sm+44136;         // 32
  int t=threadIdx.x, h=blockIdx.y;
  int i0=row_start+blockIdx.x*CH;
  for(int idx=t;idx<LM*DH;idx+=256){
    int j=idx>>6, d=idx&63;
    kls[j*65+d]=g_kl[((size_t)h*LM+j)*DH+d];
    w2s[j*65+d]=g_w2[((size_t)h*LM+j)*DH+d];
  }
  for(int idx=t;idx<160*64;idx+=256){
    int rr=idx>>6, d=idx&63, gr=i0-16+rr;
    vs[rr*64+d]=(gr>=0&&gr<NPD)?g_qkv[(size_t)gr*1536+1024+h*64+d]:0.f;
  }
  if(t<33) rws[t]=rw[h*33+t];
  __syncthreads();
  for(int ii=0;ii<CH;ii++){
    int i=i0+ii;
    if(i>=row_start+row_cnt) break;
    if(t<64) qs[t]=g_qkv[(size_t)i*1536+h*64+t]*0.125f;
    __syncthreads();
    float l=0.f;
#pragma unroll
    for(int d=0;d<DH;d++) l+=qs[d]*kls[t*65+d];
    float M=bMax(l,red);
    float p=__expf(l-M);
    float S=bSum(p,red);
    ps[t]=p/S;
    __syncthreads();
    {
      int g=t>>6, d=t&63;
      float o=0.f;
#pragma unroll 8
      for(int j=g*64;j<g*64+64;j++) o+=ps[j]*w2s[j*65+d];
      op[g*64+d]=o;
    }
    __syncthreads();
    if(t<64){
      float o=op[t]+op[64+t]+op[128+t]+op[192+t];
#pragma unroll
      for(int tap=0;tap<33;tap++) o+=vs[(ii+tap)*64+t]*rws[tap];
      g_ao[(size_t)(i-255)*512+h*64+t]=o;
    }
    __syncthreads();
  }
}

// ------------- PPEG: cf + dw7 + dw5 + dw3 ----------------------------------
__global__ __launch_bounds__(256) void ppeg_k(
    const float* __restrict__ w7, const float* __restrict__ b7,
    const float* __restrict__ w5, const float* __restrict__ b5,
    const float* __restrict__ w3, const float* __restrict__ b3)
{
  extern __shared__ float sm[];
  float* sin_=sm;          // 22*22*65
  float* w7s=sm+31460;     // 49*64
  float* w5s=sm+34596;     // 25*64
  float* w3s=sm+36196;     // 9*64
  float* bs =sm+36772;     // 64
  int t=threadIdx.x;
  int ty0=(blockIdx.x>>3)*16, tx0=(blockIdx.x&7)*16;
  int cbase=blockIdx.y*64;
  for(int idx=t;idx<22*22*64;idx+=256){
    int c=idx&63, pp=idx>>6, yy=pp/22, xx=pp%22;
    int gy=ty0+yy-3, gx=tx0+xx-3;
    sin_[(yy*22+xx)*65+c]=(gy>=0&&gy<128&&gx>=0&&gx<128)?
        g_h[(size_t)(1+gy*128+gx)*512+cbase+c]:0.f;
  }
  for(int idx=t;idx<49*64;idx+=256){ int c=idx&63,k=idx>>6; w7s[k*64+c]=w7[(cbase+c)*49+k]; }
  for(int idx=t;idx<25*64;idx+=256){ int c=idx&63,k=idx>>6; w5s[k*64+c]=w5[(cbase+c)*25+k]; }
  for(int idx=t;idx<9*64;idx+=256){ int c=idx&63,k=idx>>6; w3s[k*64+c]=w3[(cbase+c)*9+k]; }
  if(t<64) bs[t]=b7[cbase+t]+b5[cbase+t]+b3[cbase+t];
  __syncthreads();
  int py=t>>4, px=t&15;
  for(int c=0;c<64;c++){
    float acc=sin_[((py+3)*22+px+3)*65+c]+bs[c];
#pragma unroll
    for(int ky=0;ky<7;ky++)
#pragma unroll
      for(int kx=0;kx<7;kx++)
        acc+=sin_[((py+ky)*22+px+kx)*65+c]*w7s[(ky*7+kx)*64+c];
#pragma unroll
    for(int ky=0;ky<5;ky++)
#pragma unroll
      for(int kx=0;kx<5;kx++)
        acc+=sin_[((py+1+ky)*22+px+1+kx)*65+c]*w5s[(ky*5+kx)*64+c];
#pragma unroll
    for(int ky=0;ky<3;ky++)
#pragma unroll
      for(int kx=0;kx<3;kx++)
        acc+=sin_[((py+2+ky)*22+px+2+kx)*65+c]*w3s[(ky*3+kx)*64+c];
    g_h2[(size_t)(1+(ty0+py)*128+tx0+px)*512+cbase+c]=acc;
  }
}

// ------------- small helpers -----------------------------------------------
__global__ void clscopy_k(const float* __restrict__ cls){ g_h[threadIdx.x]=cls[threadIdx.x]; }
__global__ void row0cpy_k(){ g_h2[threadIdx.x]=g_h[threadIdx.x]; }

// ------------- final: cls out-proj + residual + LN + fc2 -------------------
__global__ __launch_bounds__(512) void final_k(
    const float* __restrict__ outw, const float* __restrict__ outb,
    const float* __restrict__ ng, const float* __restrict__ nb,
    const float* __restrict__ fw, const float* __restrict__ fb,
    float* __restrict__ out)
{
  __shared__ float sh[512]; __shared__ float red[32];
  int t=threadIdx.x;
  float acc=0.f;
  for(int k=0;k<512;k++) acc+=g_ao[k]*outw[(size_t)k*512+t];
  float row=g_h2[t]+acc+outb[t];
  float mean=bSum(row,red)*(1.f/512.f);
  float d=row-mean;
  float var=bSum(d*d,red)*(1.f/512.f);
  float y=d*(1.f/sqrtf(var+1e-5f))*ng[t]+nb[t];
  sh[t]=y;
  __syncthreads();
  if(t<4){
    float o=fb[t];
    for(int c=0;c<512;c++) o+=sh[c]*fw[c*4+t];
    out[t]=o;
  }
}

// ---------------- host orchestration ----------------------------------------
static void* sym(const void* s){ void* p=nullptr; cudaGetSymbolAddress(&p,s); return p; }

static void attn_layer(const float* hin, const float* ng, const float* nbi,
                       const float* qkvw, const float* outw, const float* outb,
                       const float* resw, int layer2,
                       float* ph, float* pxp, float* pqkv, float* pao,
                       float* pa2, float* pz, float* pzb, float* paz,
                       float* pt1, float* pt2, float* po3, float* pw2,
                       size_t a1sm)
{
  ln_pad_k<<<NPD,256>>>(hin,ng,nbi);
  sgemm_k<0><<<dim3(1536/128,130),256>>>(pxp,qkvw,pqkv,nullptr,NPD,1536,512);
  landmarks_k<<<dim3(LM,NH),64>>>();
  a2_k<<<dim3(LM,NH),256>>>();
  sums_k<<<NH,256>>>();
  denom_k<<<1,32>>>();
  zinit_k<<<dim3(LM,NH),256>>>();
  float* zc=pz; float* zn=pzb;
  for(int it=0;it<6;it++){
    g256_k<<<dim3(4,4,NH),256>>>(pa2,zc,paz,256,1.f,0.f);
    g256_k<<<dim3(4,4,NH),256>>>(paz,paz,pt1,256,-1.f,7.f);
    g256_k<<<dim3(4,4,NH),256>>>(paz,pt1,pt2,256,-1.f,15.f);
    g256_k<<<dim3(4,4,NH),256>>>(zc,pt2,zn,256,-0.25f,3.25f);
    float* tmp=zc; zc=zn; zn=tmp;
  }
  qkT_k<<<dim3(130,2,NH),256>>>();
  a3soft_k<<<dim3(LM,NH),256>>>();
  a3v_k<<<dim3(4,NH,KC),256>>>();
  a3vred_k<<<NH*LM*DH/256,256>>>();
  g256_k<<<dim3(1,4,NH),256>>>(zc,po3,pw2,64,1.f,0.f);
  if(!layer2){
    a1res_k<<<dim3((NR+CH-1)/CH,NH),256,a1sm>>>(resw,255,NR);
    sgemm_k<2><<<dim3(4,(NR+127)/128),256>>>(pao,outw,ph,outb,NR,512,512);
  }else{
    a1res_k<<<dim3(1,NH),256,a1sm>>>(resw,255,1);
  }
}

extern "C" void kernel_launch(void* const* d_in, const int* in_sizes, int n_in,
                              void* d_out, int out_size)
{
  // Common prefix (both orderings agree on 0..9):
  const float* x     =(const float*)d_in[0];
  const float* fc1w  =(const float*)d_in[1];
  const float* fc1b  =(const float*)d_in[2];
  const float* cls   =(const float*)d_in[3];
  const float* l1ng  =(const float*)d_in[4];
  const float* l1nb  =(const float*)d_in[5];
  const float* l1qkv =(const float*)d_in[6];
  const float* l1ow  =(const float*)d_in[7];
  const float* l1ob  =(const float*)d_in[8];
  const float* l1rw  =(const float*)d_in[9];

  // Detect ordering of indices 10..21 from element counts:
  //   signature order: ppeg (w7=25088 elems) at 10, l2 at 16..21
  //   dict order:      l2 (norm_g=512 elems) at 10, ppeg at 16..21
  int ppegBase, l2Base;
  if (in_sizes[10] == 25088) { ppegBase = 10; l2Base = 16; }
  else                       { l2Base = 10; ppegBase = 16; }

  const float* w7   =(const float*)d_in[ppegBase+0];
  const float* b7   =(const float*)d_in[ppegBase+1];
  const float* w5   =(const float*)d_in[ppegBase+2];
  const float* b5   =(const float*)d_in[ppegBase+3];
  const float* w3   =(const float*)d_in[ppegBase+4];
  const float* b3   =(const float*)d_in[ppegBase+5];
  const float* l2ng =(const float*)d_in[l2Base+0];
  const float* l2nb =(const float*)d_in[l2Base+1];
  const float* l2qkv=(const float*)d_in[l2Base+2];
  const float* l2ow =(const float*)d_in[l2Base+3];
  const float* l2ob =(const float*)d_in[l2Base+4];
  const float* l2rw =(const float*)d_in[l2Base+5];
  const float* nng  =(const float*)d_in[22];
  const float* nnb  =(const float*)d_in[23];
  const float* fc2w =(const float*)d_in[24];
  const float* fc2b =(const float*)d_in[25];
  float* out=(float*)d_out;

  float* ph  =(float*)sym(g_h);
  float* ph2 =(float*)sym(g_h2);
  float* pxp =(float*)sym(g_xp);
  float* pqkv=(float*)sym(g_qkv);
  float* pao =(float*)sym(g_ao);
  float* pa2 =(float*)sym(g_a2);
  float* pz  =(float*)sym(g_z);
  float* pzb =(float*)sym(g_zb);
  float* paz =(float*)sym(g_az);
  float* pt1 =(float*)sym(g_t1);
  float* pt2 =(float*)sym(g_t2);
  float* po3 =(float*)sym(g_o3);
  float* pw2 =(float*)sym(g_w2);

  const size_t A1SM=44168*sizeof(float);   // ~176.7 KB
  const size_t PPSM=36836*sizeof(float);   // ~147.3 KB
  cudaFuncSetAttribute(a1res_k,cudaFuncAttributeMaxDynamicSharedMemorySize,(int)A1SM);
  cudaFuncSetAttribute(ppeg_k, cudaFuncAttributeMaxDynamicSharedMemorySize,(int)PPSM);

  // fc1 + cls
  sgemm_k<1><<<dim3(4,128),256>>>(x,fc1w,ph+512,fc1b,16384,512,1024);
  clscopy_k<<<1,512>>>(cls);
  // layer 1
  attn_layer(ph,l1ng,l1nb,l1qkv,l1ow,l1ob,l1rw,0,
             ph,pxp,pqkv,pao,pa2,pz,pzb,paz,pt1,pt2,po3,pw2,A1SM);
  // PPEG
  row0cpy_k<<<1,512>>>();
  ppeg_k<<<dim3(64,8),256,PPSM>>>(w7,b7,w5,b5,w3,b3);
  // layer 2 (only cls row of attention output needed)
  attn_layer(ph2,l2ng,l2nb,l2qkv,l2ow,l2ob,l2rw,1,
             ph2,pxp,pqkv,pao,pa2,pz,pzb,paz,pt1,pt2,po3,pw2,A1SM);
  // final: out-proj row + residual + LN + fc2
  final_k<<<1,512>>>(l2ow,l2ob,nng,nnb,fc2w,fc2b,out);
}

// round 11
// speedup vs baseline: 1.4298x; 1.4298x over previous
#include <cuda_runtime.h>
#include <math.h>

#define NR  16385
#define NPD 16640
#define NH  8
#define DH  64
#define LM  256
#define KC  13          // split-K chunks for a3@v (13*1280 = 16640)

// ---------------- scratch (device globals, allocation-free) ----------------
__device__ float g_h  [NR  * 512];
__device__ float g_h2 [NR  * 512];
__device__ float g_xp [NPD * 512];
__device__ float g_qkv[NPD * 1536];
__device__ float g_ao [NR  * 512];
__device__ float g_ql [NH * LM * DH];
__device__ float g_kl [NH * LM * DH];
__device__ float g_a2 [NH * LM * LM];
__device__ float g_z  [NH * LM * LM];
__device__ float g_zb [NH * LM * LM];
__device__ float g_az [NH * LM * LM];
__device__ float g_t1 [NH * LM * LM];
__device__ float g_t2 [NH * LM * LM];
__device__ float g_a3 [NH * LM * NPD];
__device__ float g_p3 [KC * NH * LM * DH];
__device__ float g_o3 [NH * LM * DH];
__device__ float g_w2 [NH * LM * DH];
__device__ float g_mx [2 * NH];
__device__ float g_den;

// ---------------- reductions ----------------
__device__ __forceinline__ float wSum(float v){
#pragma unroll
  for(int o=16;o>0;o>>=1) v += __shfl_xor_sync(0xffffffffu,v,o);
  return v;
}
__device__ __forceinline__ float wMax(float v){
#pragma unroll
  for(int o=16;o>0;o>>=1) v = fmaxf(v,__shfl_xor_sync(0xffffffffu,v,o));
  return v;
}
__device__ __forceinline__ float bSum(float v, float* red){
  int w=threadIdx.x>>5, l=threadIdx.x&31, nw=(blockDim.x+31)>>5;
  v=wSum(v); if(l==0) red[w]=v; __syncthreads();
  if(w==0){ float r=(l<nw)?red[l]:0.f; r=wSum(r); if(l==0) red[0]=r; }
  __syncthreads(); float r=red[0]; __syncthreads(); return r;
}
__device__ __forceinline__ float bMax(float v, float* red){
  int w=threadIdx.x>>5, l=threadIdx.x&31, nw=(blockDim.x+31)>>5;
  v=wMax(v); if(l==0) red[w]=v; __syncthreads();
  if(w==0){ float r=(l<nw)?red[l]:-3.4e38f; r=wMax(r); if(l==0) red[0]=r; }
  __syncthreads(); float r=red[0]; __syncthreads(); return r;
}
// dual reductions (blockDim == 256)
__device__ __forceinline__ float2 bMax2(float a, float b, float* red){
  int w=threadIdx.x>>5, l=threadIdx.x&31;
#pragma unroll
  for(int o=16;o>0;o>>=1){
    a=fmaxf(a,__shfl_xor_sync(0xffffffffu,a,o));
    b=fmaxf(b,__shfl_xor_sync(0xffffffffu,b,o));
  }
  if(l==0){ red[w]=a; red[32+w]=b; }
  __syncthreads();
  if(w==0){
    float x=(l<8)?red[l]:-3.4e38f;
    float y=(l<8)?red[32+l]:-3.4e38f;
#pragma unroll
    for(int o=4;o>0;o>>=1){
      x=fmaxf(x,__shfl_xor_sync(0xffffffffu,x,o));
      y=fmaxf(y,__shfl_xor_sync(0xffffffffu,y,o));
    }
    if(l==0){ red[0]=x; red[32]=y; }
  }
  __syncthreads();
  float2 r=make_float2(red[0],red[32]);
  __syncthreads();
  return r;
}
__device__ __forceinline__ float2 bSum2(float a, float b, float* red){
  int w=threadIdx.x>>5, l=threadIdx.x&31;
#pragma unroll
  for(int o=16;o>0;o>>=1){
    a+=__shfl_xor_sync(0xffffffffu,a,o);
    b+=__shfl_xor_sync(0xffffffffu,b,o);
  }
  if(l==0){ red[w]=a; red[32+w]=b; }
  __syncthreads();
  if(w==0){
    float x=(l<8)?red[l]:0.f;
    float y=(l<8)?red[32+l]:0.f;
#pragma unroll
    for(int o=4;o>0;o>>=1){
      x+=__shfl_xor_sync(0xffffffffu,x,o);
      y+=__shfl_xor_sync(0xffffffffu,y,o);
    }
    if(l==0){ red[0]=x; red[32]=y; }
  }
  __syncthreads();
  float2 r=make_float2(red[0],red[32]);
  __syncthreads();
  return r;
}

// ---------------- TF32 mma helpers ----------------
__device__ __forceinline__ unsigned f2tf(float f){
  unsigned u; asm("cvt.rna.tf32.f32 %0, %1;" : "=r"(u) : "f"(f)); return u;
}
__device__ __forceinline__ void mma8(float* c, const unsigned* a, const unsigned* b){
  asm volatile("mma.sync.aligned.m16n8k8.row.col.f32.tf32.tf32.f32 "
    "{%0,%1,%2,%3}, {%4,%5,%6,%7}, {%8,%9}, {%0,%1,%2,%3};"
    : "+f"(c[0]),"+f"(c[1]),"+f"(c[2]),"+f"(c[3])
    : "r"(a[0]),"r"(a[1]),"r"(a[2]),"r"(a[3]), "r"(b[0]),"r"(b[1]));
}

// ---------------- TF32 GEMM: C=A@B (+epilogue). N%128==0, K%16==0 ----------
// MODE 0: C=AB   MODE 1: C=relu(AB+bias)   MODE 2: C += AB + bias
// BM=BN=128, BK=16, 256 threads, warp tile 32x64 (warps 4m x 2n)
template<int MODE>
__global__ __launch_bounds__(256) void gemm_tf32(
    const float* __restrict__ A, const float* __restrict__ B, float* __restrict__ Cd,
    const float* __restrict__ bias, int M, int N, int K)
{
  __shared__ unsigned As[16*136];
  __shared__ unsigned Bs[16*136];
  int t=threadIdx.x, lane=t&31, wid=t>>5;
  int row0=blockIdx.y*128, col0=blockIdx.x*128;
  int m_off=32*(wid&3), n_off=64*(wid>>2);
  int lq=lane>>2, lr=lane&3;
  // loader indices
  int ar=t>>1, akq=(t&1)*8;           // A: row ar, k cols akq..akq+7
  int bkr=t>>4, bnc=(t&15)*8;         // B: k row bkr, n cols bnc..bnc+7
  bool aval=(row0+ar)<M;
  const float* Ap=A+(size_t)(row0+ar)*K;
  const float* Bp=B+(size_t)bkr*N+col0+bnc;

  float c[2][8][4];
#pragma unroll
  for(int mt=0;mt<2;mt++)
#pragma unroll
    for(int nt=0;nt<8;nt++)
#pragma unroll
      for(int i=0;i<4;i++) c[mt][nt][i]=0.f;

  for(int k0=0;k0<K;k0+=16){
    float4 x0=make_float4(0,0,0,0), x1=make_float4(0,0,0,0);
    if(aval){
      x0=*(const float4*)(Ap+k0+akq);
      x1=*(const float4*)(Ap+k0+akq+4);
    }
    float4 y0=*(const float4*)(Bp+(size_t)k0*N);
    float4 y1=*(const float4*)(Bp+(size_t)k0*N+4);
    As[(akq+0)*136+ar]=f2tf(x0.x); As[(akq+1)*136+ar]=f2tf(x0.y);
    As[(akq+2)*136+ar]=f2tf(x0.z); As[(akq+3)*136+ar]=f2tf(x0.w);
    As[(akq+4)*136+ar]=f2tf(x1.x); As[(akq+5)*136+ar]=f2tf(x1.y);
    As[(akq+6)*136+ar]=f2tf(x1.z); As[(akq+7)*136+ar]=f2tf(x1.w);
    Bs[bkr*136+bnc+0]=f2tf(y0.x); Bs[bkr*136+bnc+1]=f2tf(y0.y);
    Bs[bkr*136+bnc+2]=f2tf(y0.z); Bs[bkr*136+bnc+3]=f2tf(y0.w);
    Bs[bkr*136+bnc+4]=f2tf(y1.x); Bs[bkr*136+bnc+5]=f2tf(y1.y);
    Bs[bkr*136+bnc+6]=f2tf(y1.z); Bs[bkr*136+bnc+7]=f2tf(y1.w);
    __syncthreads();
#pragma unroll
    for(int kk=0;kk<2;kk++){
      int ks=kk*8;
      unsigned a[2][4], b[8][2];
#pragma unroll
      for(int mt=0;mt<2;mt++){
        int m=m_off+16*mt+lq;
        a[mt][0]=As[(ks+lr)*136+m];
        a[mt][1]=As[(ks+lr)*136+m+8];
        a[mt][2]=As[(ks+4+lr)*136+m];
        a[mt][3]=As[(ks+4+lr)*136+m+8];
      }
#pragma unroll
      for(int nt=0;nt<8;nt++){
        int n=n_off+8*nt+lq;
        b[nt][0]=Bs[(ks+lr)*136+n];
        b[nt][1]=Bs[(ks+4+lr)*136+n];
      }
#pragma unroll
      for(int mt=0;mt<2;mt++)
#pragma unroll
        for(int nt=0;nt<8;nt++) mma8(c[mt][nt],a[mt],b[nt]);
    }
    __syncthreads();
  }
  // epilogue
#pragma unroll
  for(int mt=0;mt<2;mt++){
    int rA=row0+m_off+16*mt+lq;
    int rB=rA+8;
#pragma unroll
    for(int nt=0;nt<8;nt++){
      int cg=col0+n_off+8*nt+2*lr;
#pragma unroll
      for(int half=0;half<2;half++){
        int r=half?rB:rA;
        if(r<M){
          size_t off=(size_t)r*N+cg;
          float v0=c[mt][nt][half*2], v1=c[mt][nt][half*2+1];
          if(MODE==1){
            v0+=bias[cg];   v0=v0>0.f?v0:0.f;
            v1+=bias[cg+1]; v1=v1>0.f?v1:0.f;
            Cd[off]=v0; Cd[off+1]=v1;
          }else if(MODE==2){
            Cd[off]  +=v0+bias[cg];
            Cd[off+1]+=v1+bias[cg+1];
          }else{
            Cd[off]=v0; Cd[off+1]=v1;
          }
        }
      }
    }
  }
}

// ---------- batched 8-head TF32 GEMM: C = c0*(A@B) + c1*A, A 256x256 -------
// BM=BN=64, BK=16, 128 threads, warp tile 32x32 (warps 2m x 2n)
__global__ __launch_bounds__(128) void g256t(
    const float* __restrict__ A, const float* __restrict__ B, float* __restrict__ Cd,
    int N, float c0, float c1)
{
  __shared__ unsigned As[16*72];
  __shared__ unsigned Bs[16*72];
  const float* Ah=A+(size_t)blockIdx.z*65536;
  const float* Bh=B+(size_t)blockIdx.z*256*N;
  float* Ch=Cd+(size_t)blockIdx.z*256*N;
  int t=threadIdx.x, lane=t&31, wid=t>>5;
  int row0=blockIdx.y*64, col0=blockIdx.x*64;
  int m_off=32*(wid&1), n_off=32*(wid>>1);
  int lq=lane>>2, lr=lane&3;
  int ar=t>>1, akq=(t&1)*8;
  int bkr=t>>3, bnc=(t&7)*8;
  const float* Ap=Ah+(size_t)(row0+ar)*256;
  const float* Bp=Bh+(size_t)bkr*N+col0+bnc;

  float c[2][4][4];
#pragma unroll
  for(int mt=0;mt<2;mt++)
#pragma unroll
    for(int nt=0;nt<4;nt++)
#pragma unroll
      for(int i=0;i<4;i++) c[mt][nt][i]=0.f;

  for(int k0=0;k0<256;k0+=16){
    float4 x0=*(const float4*)(Ap+k0+akq);
    float4 x1=*(const float4*)(Ap+k0+akq+4);
    float4 y0=*(const float4*)(Bp+(size_t)k0*N);
    float4 y1=*(const float4*)(Bp+(size_t)k0*N+4);
    As[(akq+0)*72+ar]=f2tf(x0.x); As[(akq+1)*72+ar]=f2tf(x0.y);
    As[(akq+2)*72+ar]=f2tf(x0.z); As[(akq+3)*72+ar]=f2tf(x0.w);
    As[(akq+4)*72+ar]=f2tf(x1.x); As[(akq+5)*72+ar]=f2tf(x1.y);
    As[(akq+6)*72+ar]=f2tf(x1.z); As[(akq+7)*72+ar]=f2tf(x1.w);
    Bs[bkr*72+bnc+0]=f2tf(y0.x); Bs[bkr*72+bnc+1]=f2tf(y0.y);
    Bs[bkr*72+bnc+2]=f2tf(y0.z); Bs[bkr*72+bnc+3]=f2tf(y0.w);
    Bs[bkr*72+bnc+4]=f2tf(y1.x); Bs[bkr*72+bnc+5]=f2tf(y1.y);
    Bs[bkr*72+bnc+6]=f2tf(y1.z); Bs[bkr*72+bnc+7]=f2tf(y1.w);
    __syncthreads();
#pragma unroll
    for(int kk=0;kk<2;kk++){
      int ks=kk*8;
      unsigned a[2][4], b[4][2];
#pragma unroll
      for(int mt=0;mt<2;mt++){
        int m=m_off+16*mt+lq;
        a[mt][0]=As[(ks+lr)*72+m];
        a[mt][1]=As[(ks+lr)*72+m+8];
        a[mt][2]=As[(ks+4+lr)*72+m];
        a[mt][3]=As[(ks+4+lr)*72+m+8];
      }
#pragma unroll
      for(int nt=0;nt<4;nt++){
        int n=n_off+8*nt+lq;
        b[nt][0]=Bs[(ks+lr)*72+n];
        b[nt][1]=Bs[(ks+4+lr)*72+n];
      }
#pragma unroll
      for(int mt=0;mt<2;mt++)
#pragma unroll
        for(int nt=0;nt<4;nt++) mma8(c[mt][nt],a[mt],b[nt]);
    }
    __syncthreads();
  }
#pragma unroll
  for(int mt=0;mt<2;mt++){
#pragma unroll
    for(int nt=0;nt<4;nt++){
      int cg=col0+n_off+8*nt+2*lr;
#pragma unroll
      for(int half=0;half<2;half++){
        int r=row0+m_off+16*mt+lq+half*8;
        size_t off=(size_t)r*N+cg;
        float v0=c0*c[mt][nt][half*2], v1=c0*c[mt][nt][half*2+1];
        if(c1!=0.f){
          v0+=c1*Ah[(size_t)r*256+cg];
          v1+=c1*Ah[(size_t)r*256+cg+1];
        }
        Ch[off]=v0; Ch[off+1]=v1;
      }
    }
  }
}

// ------------- LayerNorm + front-pad to NPD rows ---------------------------
__global__ __launch_bounds__(256) void ln_pad_k(const float* __restrict__ hin,
    const float* __restrict__ g, const float* __restrict__ b)
{
  int row=blockIdx.x, t=threadIdx.x;
  float* out=g_xp+(size_t)row*512;
  if(row<255){ out[t]=0.f; out[t+256]=0.f; return; }
  __shared__ float red[32];
  const float* x=hin+(size_t)(row-255)*512;
  float v0=x[t], v1=x[t+256];
  float mean=bSum(v0+v1,red)*(1.f/512.f);
  float d0=v0-mean, d1=v1-mean;
  float var=bSum(d0*d0+d1*d1,red)*(1.f/512.f);
  float rs=1.f/sqrtf(var+1e-5f);
  out[t]=d0*rs*g[t]+b[t];
  out[t+256]=d1*rs*g[t+256]+b[t+256];
}

// ------------- landmarks: mean of 65 consecutive rows ----------------------
__global__ void landmarks_k()
{
  int m=blockIdx.x, h=blockIdx.y, d=threadIdx.x;
  const float* base=g_qkv+(size_t)(m*65)*1536+h*64+d;
  float sq=0.f, sk=0.f;
  for(int j=0;j<65;j++){ sq+=base[(size_t)j*1536]; sk+=base[(size_t)j*1536+512]; }
  g_ql[(h*LM+m)*DH+d]=sq*(0.125f/65.f);
  g_kl[(h*LM+m)*DH+d]=sk*(1.f/65.f);
}

// ------------- a2 = softmax(q_l @ k_l^T) -----------------------------------
__global__ __launch_bounds__(256) void a2_k()
{
  int i=blockIdx.x, h=blockIdx.y, j=threadIdx.x;
  __shared__ float q[DH]; __shared__ float red[32];
  if(j<DH) q[j]=g_ql[(h*LM+i)*DH+j];
  __syncthreads();
  const float* kr=&g_kl[(h*LM+j)*DH];
  float s=0.f;
#pragma unroll
  for(int d=0;d<DH;d++) s+=q[d]*kr[d];
  float mx=bMax(s,red);
  float p=expf(s-mx);
  float ss=bSum(p,red);
  g_a2[((size_t)(h*LM+i))*LM+j]=p/ss;
}

// ------------- pinv init: row/col-sum maxima, denom, z0 = a2^T/den ---------
__global__ __launch_bounds__(256) void sums_k()
{
  int h=blockIdx.x, t=threadIdx.x;
  __shared__ float red[32];
  const float* a=g_a2+(size_t)h*LM*LM;
  float rs=0.f, cs=0.f;
  for(int j=0;j<LM;j++){ rs+=fabsf(a[(size_t)t*LM+j]); cs+=fabsf(a[(size_t)j*LM+t]); }
  float rm=bMax(rs,red), cm=bMax(cs,red);
  if(t==0){ g_mx[h]=rm; g_mx[NH+h]=cm; }
}
__global__ void denom_k()
{
  int t=threadIdx.x;
  float rm=(t<NH)?g_mx[t]:-3.4e38f, cm=(t<NH)?g_mx[NH+t]:-3.4e38f;
  rm=wMax(rm); cm=wMax(cm);
  if(t==0) g_den=rm*cm;
}
__global__ __launch_bounds__(256) void zinit_k()
{
  int i=blockIdx.x, h=blockIdx.y, j=threadIdx.x;
  float inv=1.f/g_den;
  g_z[((size_t)h*LM+i)*LM+j]=g_a2[((size_t)h*LM+j)*LM+i]*inv;
}

// ------------- a3 logits: q_l(256x64) @ k^T (per head) ---------------------
__global__ __launch_bounds__(256) void qkT_k()
{
  __shared__ float As[8][128];
  __shared__ float Bs[8][128];
  int t=threadIdx.x, h=blockIdx.z;
  int col0=blockIdx.x*128, row0=blockIdx.y*128;
  int tx=t&15, ty=t>>4;
  int arow=t>>1, acol=(t&1)*4;
  int bj=t&127, kh=t>>7;
  float acc[8][8];
#pragma unroll
  for(int i=0;i<8;i++)
#pragma unroll
    for(int j=0;j<8;j++) acc[i][j]=0.f;
  for(int k0=0;k0<64;k0+=8){
    float4 av=*(const float4*)(g_ql+(size_t)h*LM*DH+(size_t)(row0+arow)*64+k0+acol);
    As[acol][arow]=av.x; As[acol+1][arow]=av.y; As[acol+2][arow]=av.z; As[acol+3][arow]=av.w;
    float4 bv=*(const float4*)(g_qkv+(size_t)(col0+bj)*1536+512+h*64+k0+kh*4);
    Bs[kh*4][bj]=bv.x; Bs[kh*4+1][bj]=bv.y; Bs[kh*4+2][bj]=bv.z; Bs[kh*4+3][bj]=bv.w;
    __syncthreads();
#pragma unroll
    for(int k=0;k<8;k++){
      float a[8],b[8];
      *(float4*)a    =*(const float4*)&As[k][ty*8];
      *(float4*)(a+4)=*(const float4*)&As[k][ty*8+4];
      *(float4*)b    =*(const float4*)&Bs[k][tx*8];
      *(float4*)(b+4)=*(const float4*)&Bs[k][tx*8+4];
#pragma unroll
      for(int i=0;i<8;i++)
#pragma unroll
        for(int j=0;j<8;j++) acc[i][j]+=a[i]*b[j];
    }
    __syncthreads();
  }
#pragma unroll
  for(int i=0;i<8;i++){
    size_t off=((size_t)h*LM+row0+ty*8+i)*NPD+col0+tx*8;
#pragma unroll
    for(int j=0;j<8;j++) g_a3[off+j]=acc[i][j];
  }
}

// ------------- a3 row softmax over 16640 keys ------------------------------
__global__ __launch_bounds__(256) void a3soft_k()
{
  int i=blockIdx.x, h=blockIdx.y, t=threadIdx.x;
  __shared__ float red[32];
  float* p=g_a3+((size_t)h*LM+i)*NPD;
  float m=-3.4e38f;
  for(int j=t;j<NPD;j+=256) m=fmaxf(m,p[j]);
  float M=bMax(m,red);
  float s=0.f;
  for(int j=t;j<NPD;j+=256) s+=__expf(p[j]-M);
  float S=bSum(s,red);
  float inv=1.f/S;
  for(int j=t;j<NPD;j+=256) p[j]=__expf(p[j]-M)*inv;
}

// ------------- a3v split-K: partial[kc] = a3[:,chunk] @ v[chunk,:] ---------
__global__ __launch_bounds__(256) void a3v_k()
{
  __shared__ float As[16][64];
  __shared__ float Bs[16][64];
  int t=threadIdx.x, h=blockIdx.y, kc=blockIdx.z;
  int m0=blockIdx.x*64, kbase=kc*1280;
  int tx=t&15, ty=t>>4;
  int arow=t>>2, acol=(t&3)*4;
  int brow=t>>4, bcol=(t&15)*4;
  float acc[4][4];
#pragma unroll
  for(int i=0;i<4;i++)
#pragma unroll
    for(int j=0;j<4;j++) acc[i][j]=0.f;
  const float* Ah=g_a3+((size_t)h*LM+m0)*NPD;
  for(int k0=0;k0<1280;k0+=16){
    float4 av=*(const float4*)(Ah+(size_t)arow*NPD+kbase+k0+acol);
    As[acol][arow]=av.x; As[acol+1][arow]=av.y; As[acol+2][arow]=av.z; As[acol+3][arow]=av.w;
    *(float4*)&Bs[brow][bcol]=*(const float4*)(g_qkv+(size_t)(kbase+k0+brow)*1536+1024+h*64+bcol);
    __syncthreads();
#pragma unroll
    for(int k=0;k<16;k++){
      float a[4],b[4];
      *(float4*)a=*(const float4*)&As[k][ty*4];
      *(float4*)b=*(const float4*)&Bs[k][tx*4];
#pragma unroll
      for(int i=0;i<4;i++)
#pragma unroll
        for(int j=0;j<4;j++) acc[i][j]+=a[i]*b[j];
    }
    __syncthreads();
  }
#pragma unroll
  for(int i=0;i<4;i++)
#pragma unroll
    for(int j=0;j<4;j++)
      g_p3[((size_t)kc*NH+h)*LM*DH+(size_t)(m0+ty*4+i)*DH+tx*4+j]=acc[i][j];
}
__global__ void a3vred_k()
{
  int idx=blockIdx.x*256+threadIdx.x;
  float s=0.f;
  for(int kc=0;kc<KC;kc++) s+=g_p3[(size_t)kc*NH*LM*DH+idx];
  g_o3[idx]=s;
}

// ------------- fused a1@W2 + depthwise-33 residual (2 rows/iter) -----------
#define CH 128
__global__ __launch_bounds__(256) void a1res_k(const float* __restrict__ rw,
                                               int row_start, int row_cnt)
{
  extern __shared__ float sm[];
  float* kls=sm;               // 256*65 = 16640
  float* w2s=sm+16640;         // 16640
  float* vs =sm+33280;         // 160*64 = 10240 -> 43520
  float* rws=sm+43520;         // 33 (pad 40)    -> 43560
  float* qs =sm+43560;         // 128            -> 43688
  float* ps =sm+43688;         // 256            -> 43944
  float* ps2=sm+43944;         // 256            -> 44200
  float* op0=sm+44200;         // 256            -> 44456
  float* op1=sm+44456;         // 256            -> 44712
  float* red=sm+44712;         // 64             -> 44776
  int t=threadIdx.x, h=blockIdx.y;
  int i0=row_start+blockIdx.x*CH;
  int rend=row_start+row_cnt;
  for(int idx=t;idx<LM*DH;idx+=256){
    int j=idx>>6, d=idx&63;
    kls[j*65+d]=g_kl[((size_t)h*LM+j)*DH+d];
    w2s[j*65+d]=g_w2[((size_t)h*LM+j)*DH+d];
  }
  for(int idx=t;idx<160*64;idx+=256){
    int rr=idx>>6, d=idx&63, gr=i0-16+rr;
    vs[rr*64+d]=(gr>=0&&gr<NPD)?g_qkv[(size_t)gr*1536+1024+h*64+d]:0.f;
  }
  if(t<33) rws[t]=rw[h*33+t];
  __syncthreads();
  for(int ii=0;ii<CH;ii+=2){
    int i=i0+ii;
    if(i>=rend) break;
    bool v1=(i+1<rend);
    if(t<64) qs[t]=g_qkv[(size_t)i*1536+h*64+t]*0.125f;
    else if(t<128) qs[t]=v1?g_qkv[(size_t)(i+1)*1536+h*64+(t-64)]*0.125f:0.f;
    __syncthreads();
    float l0=0.f, l1=0.f;
#pragma unroll
    for(int d=0;d<DH;d++){
      float kv=kls[t*65+d];
      l0+=qs[d]*kv;
      l1+=qs[64+d]*kv;
    }
    float2 M=bMax2(l0,v1?l1:l0,red);
    float p0=__expf(l0-M.x), p1=__expf(l1-M.y);
    float2 S=bSum2(p0,p1,red);
    ps[t]=p0/S.x; ps2[t]=p1/S.y;
    __syncthreads();
    {
      int g=t>>6, d=t&63;
      float o0=0.f, o1=0.f;
#pragma unroll 8
      for(int j=g*64;j<g*64+64;j++){
        float w=w2s[j*65+d];
        o0+=ps[j]*w;
        o1+=ps2[j]*w;
      }
      op0[g*64+d]=o0;
      op1[g*64+d]=o1;
    }
    __syncthreads();
    if(t<128){
      int rr=t>>6, d=t&63;
      if(rr==0||v1){
        float* opp=rr?op1:op0;
        float o=opp[d]+opp[64+d]+opp[128+d]+opp[192+d];
#pragma unroll
        for(int tap=0;tap<33;tap++) o+=vs[(ii+rr+tap)*64+d]*rws[tap];
        g_ao[(size_t)(i+rr-255)*512+h*64+d]=o;
      }
    }
    __syncthreads();
  }
}

// ------------- PPEG: cf + dw7 + dw5 + dw3 ----------------------------------
__global__ __launch_bounds__(256) void ppeg_k(
    const float* __restrict__ w7, const float* __restrict__ b7,
    const float* __restrict__ w5, const float* __restrict__ b5,
    const float* __restrict__ w3, const float* __restrict__ b3)
{
  extern __shared__ float sm[];
  float* sin_=sm;          // 22*22*65
  float* w7s=sm+31460;     // 49*64
  float* w5s=sm+34596;     // 25*64
  float* w3s=sm+36196;     // 9*64
  float* bs =sm+36772;     // 64
  int t=threadIdx.x;
  int ty0=(blockIdx.x>>3)*16, tx0=(blockIdx.x&7)*16;
  int cbase=blockIdx.y*64;
  for(int idx=t;idx<22*22*64;idx+=256){
    int c=idx&63, pp=idx>>6, yy=pp/22, xx=pp%22;
    int gy=ty0+yy-3, gx=tx0+xx-3;
    sin_[(yy*22+xx)*65+c]=(gy>=0&&gy<128&&gx>=0&&gx<128)?
        g_h[(size_t)(1+gy*128+gx)*512+cbase+c]:0.f;
  }
  for(int idx=t;idx<49*64;idx+=256){ int c=idx&63,k=idx>>6; w7s[k*64+c]=w7[(cbase+c)*49+k]; }
  for(int idx=t;idx<25*64;idx+=256){ int c=idx&63,k=idx>>6; w5s[k*64+c]=w5[(cbase+c)*25+k]; }
  for(int idx=t;idx<9*64;idx+=256){ int c=idx&63,k=idx>>6; w3s[k*64+c]=w3[(cbase+c)*9+k]; }
  if(t<64) bs[t]=b7[cbase+t]+b5[cbase+t]+b3[cbase+t];
  __syncthreads();
  int py=t>>4, px=t&15;
  for(int c=0;c<64;c++){
    float acc=sin_[((py+3)*22+px+3)*65+c]+bs[c];
#pragma unroll
    for(int ky=0;ky<7;ky++)
#pragma unroll
      for(int kx=0;kx<7;kx++)
        acc+=sin_[((py+ky)*22+px+kx)*65+c]*w7s[(ky*7+kx)*64+c];
#pragma unroll
    for(int ky=0;ky<5;ky++)
#pragma unroll
      for(int kx=0;kx<5;kx++)
        acc+=sin_[((py+1+ky)*22+px+1+kx)*65+c]*w5s[(ky*5+kx)*64+c];
#pragma unroll
    for(int ky=0;ky<3;ky++)
#pragma unroll
      for(int kx=0;kx<3;kx++)
        acc+=sin_[((py+2+ky)*22+px+2+kx)*65+c]*w3s[(ky*3+kx)*64+c];
    g_h2[(size_t)(1+(ty0+py)*128+tx0+px)*512+cbase+c]=acc;
  }
}

// ------------- small helpers -----------------------------------------------
__global__ void clscopy_k(const float* __restrict__ cls){ g_h[threadIdx.x]=cls[threadIdx.x]; }
__global__ void row0cpy_k(){ g_h2[threadIdx.x]=g_h[threadIdx.x]; }

// ------------- final: cls out-proj + residual + LN + fc2 -------------------
__global__ __launch_bounds__(512) void final_k(
    const float* __restrict__ outw, const float* __restrict__ outb,
    const float* __restrict__ ng, const float* __restrict__ nb,
    const float* __restrict__ fw, const float* __restrict__ fb,
    float* __restrict__ out)
{
  __shared__ float sh[512]; __shared__ float red[32];
  int t=threadIdx.x;
  float acc=0.f;
  for(int k=0;k<512;k++) acc+=g_ao[k]*outw[(size_t)k*512+t];
  float row=g_h2[t]+acc+outb[t];
  float mean=bSum(row,red)*(1.f/512.f);
  float d=row-mean;
  float var=bSum(d*d,red)*(1.f/512.f);
  float y=d*(1.f/sqrtf(var+1e-5f))*ng[t]+nb[t];
  sh[t]=y;
  __syncthreads();
  if(t<4){
    float o=fb[t];
    for(int c=0;c<512;c++) o+=sh[c]*fw[c*4+t];
    out[t]=o;
  }
}

// ---------------- host orchestration ----------------------------------------
static void* sym(const void* s){ void* p=nullptr; cudaGetSymbolAddress(&p,s); return p; }

static void attn_layer(const float* hin, const float* ng, const float* nbi,
                       const float* qkvw, const float* outw, const float* outb,
                       const float* resw, int layer2,
                       float* ph, float* pxp, float* pqkv, float* pao,
                       float* pa2, float* pz, float* pzb, float* paz,
                       float* pt1, float* pt2, float* po3, float* pw2,
                       size_t a1sm)
{
  ln_pad_k<<<NPD,256>>>(hin,ng,nbi);
  gemm_tf32<0><<<dim3(1536/128,130),256>>>(pxp,qkvw,pqkv,nullptr,NPD,1536,512);
  landmarks_k<<<dim3(LM,NH),64>>>();
  a2_k<<<dim3(LM,NH),256>>>();
  sums_k<<<NH,256>>>();
  denom_k<<<1,32>>>();
  zinit_k<<<dim3(LM,NH),256>>>();
  float* zc=pz; float* zn=pzb;
  for(int it=0;it<6;it++){
    g256t<<<dim3(4,4,NH),128>>>(pa2,zc,paz,256,1.f,0.f);
    g256t<<<dim3(4,4,NH),128>>>(paz,paz,pt1,256,-1.f,7.f);
    g256t<<<dim3(4,4,NH),128>>>(paz,pt1,pt2,256,-1.f,15.f);
    g256t<<<dim3(4,4,NH),128>>>(zc,pt2,zn,256,-0.25f,3.25f);
    float* tmp=zc; zc=zn; zn=tmp;
  }
  qkT_k<<<dim3(130,2,NH),256>>>();
  a3soft_k<<<dim3(LM,NH),256>>>();
  a3v_k<<<dim3(4,NH,KC),256>>>();
  a3vred_k<<<NH*LM*DH/256,256>>>();
  g256t<<<dim3(1,4,NH),128>>>(zc,po3,pw2,64,1.f,0.f);
  if(!layer2){
    a1res_k<<<dim3((NR+CH-1)/CH,NH),256,a1sm>>>(resw,255,NR);
    gemm_tf32<2><<<dim3(4,(NR+127)/128),256>>>(pao,outw,ph,outb,NR,512,512);
  }else{
    a1res_k<<<dim3(1,NH),256,a1sm>>>(resw,255,1);
  }
}

extern "C" void kernel_launch(void* const* d_in, const int* in_sizes, int n_in,
                              void* d_out, int out_size)
{
  // Common prefix (both orderings agree on 0..9):
  const float* x     =(const float*)d_in[0];
  const float* fc1w  =(const float*)d_in[1];
  const float* fc1b  =(const float*)d_in[2];
  const float* cls   =(const float*)d_in[3];
  const float* l1ng  =(const float*)d_in[4];
  const float* l1nb  =(const float*)d_in[5];
  const float* l1qkv =(const float*)d_in[6];
  const float* l1ow  =(const float*)d_in[7];
  const float* l1ob  =(const float*)d_in[8];
  const float* l1rw  =(const float*)d_in[9];

  int ppegBase, l2Base;
  if (in_sizes[10] == 25088) { ppegBase = 10; l2Base = 16; }
  else                       { l2Base = 10; ppegBase = 16; }

  const float* w7   =(const float*)d_in[ppegBase+0];
  const float* b7   =(const float*)d_in[ppegBase+1];
  const float* w5   =(const float*)d_in[ppegBase+2];
  const float* b5   =(const float*)d_in[ppegBase+3];
  const float* w3   =(const float*)d_in[ppegBase+4];
  const float* b3   =(const float*)d_in[ppegBase+5];
  const float* l2ng =(const float*)d_in[l2Base+0];
  const float* l2nb =(const float*)d_in[l2Base+1];
  const float* l2qkv=(const float*)d_in[l2Base+2];
  const float* l2ow =(const float*)d_in[l2Base+3];
  const float* l2ob =(const float*)d_in[l2Base+4];
  const float* l2rw =(const float*)d_in[l2Base+5];
  const float* nng  =(const float*)d_in[22];
  const float* nnb  =(const float*)d_in[23];
  const float* fc2w =(const float*)d_in[24];
  const float* fc2b =(const float*)d_in[25];
  float* out=(float*)d_out;

  float* ph  =(float*)sym(g_h);
  float* ph2 =(float*)sym(g_h2);
  float* pxp =(float*)sym(g_xp);
  float* pqkv=(float*)sym(g_qkv);
  float* pao =(float*)sym(g_ao);
  float* pa2 =(float*)sym(g_a2);
  float* pz  =(float*)sym(g_z);
  float* pzb =(float*)sym(g_zb);
  float* paz =(float*)sym(g_az);
  float* pt1 =(float*)sym(g_t1);
  float* pt2 =(float*)sym(g_t2);
  float* po3 =(float*)sym(g_o3);
  float* pw2 =(float*)sym(g_w2);

  const size_t A1SM=44776*sizeof(float);   // ~179.1 KB
  const size_t PPSM=36836*sizeof(float);   // ~147.3 KB
  cudaFuncSetAttribute(a1res_k,cudaFuncAttributeMaxDynamicSharedMemorySize,(int)A1SM);
  cudaFuncSetAttribute(ppeg_k, cudaFuncAttributeMaxDynamicSharedMemorySize,(int)PPSM);

  // fc1 + cls
  gemm_tf32<1><<<dim3(4,128),256>>>(x,fc1w,ph+512,fc1b,16384,512,1024);
  clscopy_k<<<1,512>>>(cls);
  // layer 1
  attn_layer(ph,l1ng,l1nb,l1qkv,l1ow,l1ob,l1rw,0,
             ph,pxp,pqkv,pao,pa2,pz,pzb,paz,pt1,pt2,po3,pw2,A1SM);
  // PPEG
  row0cpy_k<<<1,512>>>();
  ppeg_k<<<dim3(64,8),256,PPSM>>>(w7,b7,w5,b5,w3,b3);
  // layer 2 (only cls row of attention output needed)
  attn_layer(ph2,l2ng,l2nb,l2qkv,l2ow,l2ob,l2rw,1,
             ph2,pxp,pqkv,pao,pa2,pz,pzb,paz,pt1,pt2,po3,pw2,A1SM);
  // final: out-proj row + residual + LN + fc2
  final_k<<<1,512>>>(l2ow,l2ob,nng,nnb,fc2w,fc2b,out);
}

// round 13
// speedup vs baseline: 1.5013x; 1.0500x over previous
#include <cuda_runtime.h>
#include <math.h>

#define NR  16385
#define NPD 16640
#define NH  8
#define DH  64
#define LM  256
#define KC  13          // split-K chunks for a3@v (13*1280 = 16640)

// ---------------- scratch (device globals, allocation-free) ----------------
__device__ float g_h  [NR  * 512];
__device__ float g_h2 [NR  * 512];
__device__ float g_xp [NPD * 512];
__device__ float g_qkv[NPD * 1536];
__device__ float g_ao [NR  * 512];
__device__ float g_ql [NH * LM * DH];
__device__ float g_kl [NH * LM * DH];
__device__ float g_a2 [NH * LM * LM];
__device__ float g_z  [NH * LM * LM];
__device__ float g_zb [NH * LM * LM];
__device__ float g_az [NH * LM * LM];
__device__ float g_t1 [NH * LM * LM];
__device__ float g_t2 [NH * LM * LM];
__device__ float g_a3 [NH * LM * NPD];
__device__ float g_p3 [KC * NH * LM * DH];
__device__ float g_o3 [NH * LM * DH];
__device__ float g_w2 [NH * LM * DH];
__device__ float g_mx [2 * NH];
__device__ float g_den;
__device__ unsigned g_cnt;   // zero-init; self-resetting barrier counter
__device__ unsigned g_phs;   // monotone phase flag

// ---------------- reductions ----------------
__device__ __forceinline__ float wSum(float v){
#pragma unroll
  for(int o=16;o>0;o>>=1) v += __shfl_xor_sync(0xffffffffu,v,o);
  return v;
}
__device__ __forceinline__ float wMax(float v){
#pragma unroll
  for(int o=16;o>0;o>>=1) v = fmaxf(v,__shfl_xor_sync(0xffffffffu,v,o));
  return v;
}
__device__ __forceinline__ float bSum(float v, float* red){
  int w=threadIdx.x>>5, l=threadIdx.x&31, nw=(blockDim.x+31)>>5;
  v=wSum(v); if(l==0) red[w]=v; __syncthreads();
  if(w==0){ float r=(l<nw)?red[l]:0.f; r=wSum(r); if(l==0) red[0]=r; }
  __syncthreads(); float r=red[0]; __syncthreads(); return r;
}
__device__ __forceinline__ float bMax(float v, float* red){
  int w=threadIdx.x>>5, l=threadIdx.x&31, nw=(blockDim.x+31)>>5;
  v=wMax(v); if(l==0) red[w]=v; __syncthreads();
  if(w==0){ float r=(l<nw)?red[l]:-3.4e38f; r=wMax(r); if(l==0) red[0]=r; }
  __syncthreads(); float r=red[0]; __syncthreads(); return r;
}
// dual reductions (blockDim == 256)
__device__ __forceinline__ float2 bMax2(float a, float b, float* red){
  int w=threadIdx.x>>5, l=threadIdx.x&31;
#pragma unroll
  for(int o=16;o>0;o>>=1){
    a=fmaxf(a,__shfl_xor_sync(0xffffffffu,a,o));
    b=fmaxf(b,__shfl_xor_sync(0xffffffffu,b,o));
  }
  if(l==0){ red[w]=a; red[32+w]=b; }
  __syncthreads();
  if(w==0){
    float x=(l<8)?red[l]:-3.4e38f;
    float y=(l<8)?red[32+l]:-3.4e38f;
#pragma unroll
    for(int o=4;o>0;o>>=1){
      x=fmaxf(x,__shfl_xor_sync(0xffffffffu,x,o));
      y=fmaxf(y,__shfl_xor_sync(0xffffffffu,y,o));
    }
    if(l==0){ red[0]=x; red[32]=y; }
  }
  __syncthreads();
  float2 r=make_float2(red[0],red[32]);
  __syncthreads();
  return r;
}
__device__ __forceinline__ float2 bSum2(float a, float b, float* red){
  int w=threadIdx.x>>5, l=threadIdx.x&31;
#pragma unroll
  for(int o=16;o>0;o>>=1){
    a+=__shfl_xor_sync(0xffffffffu,a,o);
    b+=__shfl_xor_sync(0xffffffffu,b,o);
  }
  if(l==0){ red[w]=a; red[32+w]=b; }
  __syncthreads();
  if(w==0){
    float x=(l<8)?red[l]:0.f;
    float y=(l<8)?red[32+l]:0.f;
#pragma unroll
    for(int o=4;o>0;o>>=1){
      x+=__shfl_xor_sync(0xffffffffu,x,o);
      y+=__shfl_xor_sync(0xffffffffu,y,o);
    }
    if(l==0){ red[0]=x; red[32]=y; }
  }
  __syncthreads();
  float2 r=make_float2(red[0],red[32]);
  __syncthreads();
  return r;
}

// ---------------- TF32 mma helpers ----------------
__device__ __forceinline__ unsigned f2tf(float f){
  unsigned u; asm("cvt.rna.tf32.f32 %0, %1;" : "=r"(u) : "f"(f)); return u;
}
__device__ __forceinline__ void mma8(float* c, const unsigned* a, const unsigned* b){
  asm volatile("mma.sync.aligned.m16n8k8.row.col.f32.tf32.tf32.f32 "
    "{%0,%1,%2,%3}, {%4,%5,%6,%7}, {%8,%9}, {%0,%1,%2,%3};"
    : "+f"(c[0]),"+f"(c[1]),"+f"(c[2]),"+f"(c[3])
    : "r"(a[0]),"r"(a[1]),"r"(a[2]),"r"(a[3]), "r"(b[0]),"r"(b[1]));
}

// ---------------- TF32 GEMM: C=A@B (+epilogue). N%128==0, K%16==0 ----------
// MODE 0: C=AB   MODE 1: C=relu(AB+bias)   MODE 2: C += AB + bias
template<int MODE>
__global__ __launch_bounds__(256) void gemm_tf32(
    const float* __restrict__ A, const float* __restrict__ B, float* __restrict__ Cd,
    const float* __restrict__ bias, int M, int N, int K)
{
  __shared__ unsigned As[16*136];
  __shared__ unsigned Bs[16*136];
  int t=threadIdx.x, lane=t&31, wid=t>>5;
  int row0=blockIdx.y*128, col0=blockIdx.x*128;
  int m_off=32*(wid&3), n_off=64*(wid>>2);
  int lq=lane>>2, lr=lane&3;
  int ar=t>>1, akq=(t&1)*8;
  int bkr=t>>4, bnc=(t&15)*8;
  bool aval=(row0+ar)<M;
  const float* Ap=A+(size_t)(row0+ar)*K;
  const float* Bp=B+(size_t)bkr*N+col0+bnc;

  float c[2][8][4];
#pragma unroll
  for(int mt=0;mt<2;mt++)
#pragma unroll
    for(int nt=0;nt<8;nt++)
#pragma unroll
      for(int i=0;i<4;i++) c[mt][nt][i]=0.f;

  for(int k0=0;k0<K;k0+=16){
    float4 x0=make_float4(0,0,0,0), x1=make_float4(0,0,0,0);
    if(aval){
      x0=*(const float4*)(Ap+k0+akq);
      x1=*(const float4*)(Ap+k0+akq+4);
    }
    float4 y0=*(const float4*)(Bp+(size_t)k0*N);
    float4 y1=*(const float4*)(Bp+(size_t)k0*N+4);
    As[(akq+0)*136+ar]=f2tf(x0.x); As[(akq+1)*136+ar]=f2tf(x0.y);
    As[(akq+2)*136+ar]=f2tf(x0.z); As[(akq+3)*136+ar]=f2tf(x0.w);
    As[(akq+4)*136+ar]=f2tf(x1.x); As[(akq+5)*136+ar]=f2tf(x1.y);
    As[(akq+6)*136+ar]=f2tf(x1.z); As[(akq+7)*136+ar]=f2tf(x1.w);
    Bs[bkr*136+bnc+0]=f2tf(y0.x); Bs[bkr*136+bnc+1]=f2tf(y0.y);
    Bs[bkr*136+bnc+2]=f2tf(y0.z); Bs[bkr*136+bnc+3]=f2tf(y0.w);
    Bs[bkr*136+bnc+4]=f2tf(y1.x); Bs[bkr*136+bnc+5]=f2tf(y1.y);
    Bs[bkr*136+bnc+6]=f2tf(y1.z); Bs[bkr*136+bnc+7]=f2tf(y1.w);
    __syncthreads();
#pragma unroll
    for(int kk=0;kk<2;kk++){
      int ks=kk*8;
      unsigned a[2][4], b[8][2];
#pragma unroll
      for(int mt=0;mt<2;mt++){
        int m=m_off+16*mt+lq;
        a[mt][0]=As[(ks+lr)*136+m];
        a[mt][1]=As[(ks+lr)*136+m+8];
        a[mt][2]=As[(ks+4+lr)*136+m];
        a[mt][3]=As[(ks+4+lr)*136+m+8];
      }
#pragma unroll
      for(int nt=0;nt<8;nt++){
        int n=n_off+8*nt+lq;
        b[nt][0]=Bs[(ks+lr)*136+n];
        b[nt][1]=Bs[(ks+4+lr)*136+n];
      }
#pragma unroll
      for(int mt=0;mt<2;mt++)
#pragma unroll
        for(int nt=0;nt<8;nt++) mma8(c[mt][nt],a[mt],b[nt]);
    }
    __syncthreads();
  }
#pragma unroll
  for(int mt=0;mt<2;mt++){
    int rA=row0+m_off+16*mt+lq;
    int rB=rA+8;
#pragma unroll
    for(int nt=0;nt<8;nt++){
      int cg=col0+n_off+8*nt+2*lr;
#pragma unroll
      for(int half=0;half<2;half++){
        int r=half?rB:rA;
        if(r<M){
          size_t off=(size_t)r*N+cg;
          float v0=c[mt][nt][half*2], v1=c[mt][nt][half*2+1];
          if(MODE==1){
            v0+=bias[cg];   v0=v0>0.f?v0:0.f;
            v1+=bias[cg+1]; v1=v1>0.f?v1:0.f;
            Cd[off]=v0; Cd[off+1]=v1;
          }else if(MODE==2){
            Cd[off]  +=v0+bias[cg];
            Cd[off+1]+=v1+bias[cg+1];
          }else{
            Cd[off]=v0; Cd[off+1]=v1;
          }
        }
      }
    }
  }
}

// ---------------- qkT TF32: a3 logits = q_l(256x64) @ k^T ------------------
// grid (130 keys/128, 2 qrows/128, NH), 256 threads
__global__ __launch_bounds__(256) void qkT_t()
{
  __shared__ unsigned As[16*136];
  __shared__ unsigned Bs[16*136];
  int t=threadIdx.x, lane=t&31, wid=t>>5;
  int h=blockIdx.z;
  int col0=blockIdx.x*128, row0=blockIdx.y*128;
  int m_off=32*(wid&3), n_off=64*(wid>>2);
  int lq=lane>>2, lr=lane&3;
  int ar=t>>1, akq=(t&1)*8;
  int bj=t&127, kh=(t>>7)*8;
  const float* Ap=g_ql+(size_t)h*LM*DH+(size_t)(row0+ar)*64;
  const float* Bp=g_qkv+(size_t)(col0+bj)*1536+512+h*64+kh;

  float c[2][8][4];
#pragma unroll
  for(int mt=0;mt<2;mt++)
#pragma unroll
    for(int nt=0;nt<8;nt++)
#pragma unroll
      for(int i=0;i<4;i++) c[mt][nt][i]=0.f;

  for(int k0=0;k0<64;k0+=16){
    float4 x0=*(const float4*)(Ap+k0+akq);
    float4 x1=*(const float4*)(Ap+k0+akq+4);
    float4 y0=*(const float4*)(Bp+k0);
    float4 y1=*(const float4*)(Bp+k0+4);
    As[(akq+0)*136+ar]=f2tf(x0.x); As[(akq+1)*136+ar]=f2tf(x0.y);
    As[(akq+2)*136+ar]=f2tf(x0.z); As[(akq+3)*136+ar]=f2tf(x0.w);
    As[(akq+4)*136+ar]=f2tf(x1.x); As[(akq+5)*136+ar]=f2tf(x1.y);
    As[(akq+6)*136+ar]=f2tf(x1.z); As[(akq+7)*136+ar]=f2tf(x1.w);
    Bs[(kh+0)*136+bj]=f2tf(y0.x); Bs[(kh+1)*136+bj]=f2tf(y0.y);
    Bs[(kh+2)*136+bj]=f2tf(y0.z); Bs[(kh+3)*136+bj]=f2tf(y0.w);
    Bs[(kh+4)*136+bj]=f2tf(y1.x); Bs[(kh+5)*136+bj]=f2tf(y1.y);
    Bs[(kh+6)*136+bj]=f2tf(y1.z); Bs[(kh+7)*136+bj]=f2tf(y1.w);
    __syncthreads();
#pragma unroll
    for(int kk=0;kk<2;kk++){
      int ks=kk*8;
      unsigned a[2][4], b[8][2];
#pragma unroll
      for(int mt=0;mt<2;mt++){
        int m=m_off+16*mt+lq;
        a[mt][0]=As[(ks+lr)*136+m];
        a[mt][1]=As[(ks+lr)*136+m+8];
        a[mt][2]=As[(ks+4+lr)*136+m];
        a[mt][3]=As[(ks+4+lr)*136+m+8];
      }
#pragma unroll
      for(int nt=0;nt<8;nt++){
        int n=n_off+8*nt+lq;
        b[nt][0]=Bs[(ks+lr)*136+n];
        b[nt][1]=Bs[(ks+4+lr)*136+n];
      }
#pragma unroll
      for(int mt=0;mt<2;mt++)
#pragma unroll
        for(int nt=0;nt<8;nt++) mma8(c[mt][nt],a[mt],b[nt]);
    }
    __syncthreads();
  }
#pragma unroll
  for(int mt=0;mt<2;mt++){
#pragma unroll
    for(int nt=0;nt<8;nt++){
      int cg=col0+n_off+8*nt+2*lr;
#pragma unroll
      for(int half=0;half<2;half++){
        int r=row0+m_off+16*mt+lq+half*8;
        size_t off=((size_t)h*LM+r)*NPD+cg;
        g_a3[off]  =c[mt][nt][half*2];
        g_a3[off+1]=c[mt][nt][half*2+1];
      }
    }
  }
}

// ---------------- TF32 64x64 step for Newton / g256 ------------------------
__device__ __forceinline__ void gemm64_tc(unsigned* As, unsigned* Bs,
    const float* __restrict__ Ah, const float* __restrict__ Bh, float* __restrict__ Ch,
    float c0, float c1, int row0, int col0)
{
  int t=threadIdx.x, lane=t&31, wid=t>>5;
  int m_off=32*(wid&1), n_off=32*(wid>>1);
  int lq=lane>>2, lr=lane&3;
  int ar=t>>1, akq=(t&1)*8;
  int bkr=t>>3, bnc=(t&7)*8;
  const float* Ap=Ah+(size_t)(row0+ar)*256;
  const float* Bp=Bh+(size_t)bkr*256+col0+bnc;
  float c[2][4][4];
#pragma unroll
  for(int mt=0;mt<2;mt++)
#pragma unroll
    for(int nt=0;nt<4;nt++)
#pragma unroll
      for(int i=0;i<4;i++) c[mt][nt][i]=0.f;
  for(int k0=0;k0<256;k0+=16){
    float4 x0=*(const float4*)(Ap+k0+akq);
    float4 x1=*(const float4*)(Ap+k0+akq+4);
    float4 y0=*(const float4*)(Bp+(size_t)k0*256);
    float4 y1=*(const float4*)(Bp+(size_t)k0*256+4);
    As[(akq+0)*72+ar]=f2tf(x0.x); As[(akq+1)*72+ar]=f2tf(x0.y);
    As[(akq+2)*72+ar]=f2tf(x0.z); As[(akq+3)*72+ar]=f2tf(x0.w);
    As[(akq+4)*72+ar]=f2tf(x1.x); As[(akq+5)*72+ar]=f2tf(x1.y);
    As[(akq+6)*72+ar]=f2tf(x1.z); As[(akq+7)*72+ar]=f2tf(x1.w);
    Bs[bkr*72+bnc+0]=f2tf(y0.x); Bs[bkr*72+bnc+1]=f2tf(y0.y);
    Bs[bkr*72+bnc+2]=f2tf(y0.z); Bs[bkr*72+bnc+3]=f2tf(y0.w);
    Bs[bkr*72+bnc+4]=f2tf(y1.x); Bs[bkr*72+bnc+5]=f2tf(y1.y);
    Bs[bkr*72+bnc+6]=f2tf(y1.z); Bs[bkr*72+bnc+7]=f2tf(y1.w);
    __syncthreads();
#pragma unroll
    for(int kk=0;kk<2;kk++){
      int ks=kk*8;
      unsigned a[2][4], b[4][2];
#pragma unroll
      for(int mt=0;mt<2;mt++){
        int m=m_off+16*mt+lq;
        a[mt][0]=As[(ks+lr)*72+m];
        a[mt][1]=As[(ks+lr)*72+m+8];
        a[mt][2]=As[(ks+4+lr)*72+m];
        a[mt][3]=As[(ks+4+lr)*72+m+8];
      }
#pragma unroll
      for(int nt=0;nt<4;nt++){
        int n=n_off+8*nt+lq;
        b[nt][0]=Bs[(ks+lr)*72+n];
        b[nt][1]=Bs[(ks+4+lr)*72+n];
      }
#pragma unroll
      for(int mt=0;mt<2;mt++)
#pragma unroll
        for(int nt=0;nt<4;nt++) mma8(c[mt][nt],a[mt],b[nt]);
    }
    __syncthreads();
  }
#pragma unroll
  for(int mt=0;mt<2;mt++){
#pragma unroll
    for(int nt=0;nt<4;nt++){
      int cg=col0+n_off+8*nt+2*lr;
#pragma unroll
      for(int half=0;half<2;half++){
        int r=row0+m_off+16*mt+lq+half*8;
        size_t off=(size_t)r*256+cg;
        float v0=c0*c[mt][nt][half*2], v1=c0*c[mt][nt][half*2+1];
        if(c1!=0.f){
          v0+=c1*Ah[off];
          v1+=c1*Ah[off+1];
        }
        Ch[off]=v0; Ch[off+1]=v1;
      }
    }
  }
}

// ---------------- grid barrier (self-resetting; replay-safe) ----------------
#define NWT_BLOCKS 128
__device__ __forceinline__ void gridbar(unsigned &phase){
  __syncthreads();
  if(threadIdx.x==0){
    __threadfence();
    unsigned old=atomicInc(&g_cnt,NWT_BLOCKS-1u);
    unsigned target=phase+1u;
    if(old==NWT_BLOCKS-1u){
      atomicExch(&g_phs,target);
    }else{
      while(atomicAdd(&g_phs,0u)!=target) __nanosleep(64);
    }
    __threadfence();
  }
  __syncthreads();
  phase++;
}

// ---------------- persistent Newton pinv: 6 iters x 4 GEMMs -----------------
__global__ __launch_bounds__(128) void nwt_k()
{
  __shared__ unsigned As[16*72];
  __shared__ unsigned Bs[16*72];
  __shared__ unsigned ph0;
  int t=threadIdx.x;
  int h=blockIdx.x>>4, tile=blockIdx.x&15;
  int row0=(tile>>2)*64, col0=(tile&3)*64;
  if(t==0) ph0=atomicAdd(&g_phs,0u);
  __syncthreads();
  unsigned phase=ph0;
  size_t ho=(size_t)h*65536;
  float* z =g_z +ho;
  float* zn=g_zb+ho;
#pragma unroll 1
  for(int it=0;it<6;it++){
    gemm64_tc(As,Bs,g_a2+ho,z,        g_az+ho, 1.f,  0.f,  row0,col0); gridbar(phase);
    gemm64_tc(As,Bs,g_az+ho,g_az+ho,  g_t1+ho,-1.f,  7.f,  row0,col0); gridbar(phase);
    gemm64_tc(As,Bs,g_az+ho,g_t1+ho,  g_t2+ho,-1.f, 15.f,  row0,col0); gridbar(phase);
    gemm64_tc(As,Bs,z,      g_t2+ho,  zn,     -0.25f,3.25f,row0,col0); gridbar(phase);
    float* tmp=z; z=zn; zn=tmp;
  }
}

// ---------- batched 8-head TF32 GEMM (for w2 = z@o3, N=64) ------------------
__global__ __launch_bounds__(128) void g256t(
    const float* __restrict__ A, const float* __restrict__ B, float* __restrict__ Cd,
    int N, float c0, float c1)
{
  __shared__ unsigned As[16*72];
  __shared__ unsigned Bs[16*72];
  const float* Ah=A+(size_t)blockIdx.z*65536;
  const float* Bh=B+(size_t)blockIdx.z*256*N;
  float* Ch=Cd+(size_t)blockIdx.z*256*N;
  int t=threadIdx.x, lane=t&31, wid=t>>5;
  int row0=blockIdx.y*64, col0=blockIdx.x*64;
  int m_off=32*(wid&1), n_off=32*(wid>>1);
  int lq=lane>>2, lr=lane&3;
  int ar=t>>1, akq=(t&1)*8;
  int bkr=t>>3, bnc=(t&7)*8;
  const float* Ap=Ah+(size_t)(row0+ar)*256;
  const float* Bp=Bh+(size_t)bkr*N+col0+bnc;
  float c[2][4][4];
#pragma unroll
  for(int mt=0;mt<2;mt++)
#pragma unroll
    for(int nt=0;nt<4;nt++)
#pragma unroll
      for(int i=0;i<4;i++) c[mt][nt][i]=0.f;
  for(int k0=0;k0<256;k0+=16){
    float4 x0=*(const float4*)(Ap+k0+akq);
    float4 x1=*(const float4*)(Ap+k0+akq+4);
    float4 y0=*(const float4*)(Bp+(size_t)k0*N);
    float4 y1=*(const float4*)(Bp+(size_t)k0*N+4);
    As[(akq+0)*72+ar]=f2tf(x0.x); As[(akq+1)*72+ar]=f2tf(x0.y);
    As[(akq+2)*72+ar]=f2tf(x0.z); As[(akq+3)*72+ar]=f2tf(x0.w);
    As[(akq+4)*72+ar]=f2tf(x1.x); As[(akq+5)*72+ar]=f2tf(x1.y);
    As[(akq+6)*72+ar]=f2tf(x1.z); As[(akq+7)*72+ar]=f2tf(x1.w);
    Bs[bkr*72+bnc+0]=f2tf(y0.x); Bs[bkr*72+bnc+1]=f2tf(y0.y);
    Bs[bkr*72+bnc+2]=f2tf(y0.z); Bs[bkr*72+bnc+3]=f2tf(y0.w);
    Bs[bkr*72+bnc+4]=f2tf(y1.x); Bs[bkr*72+bnc+5]=f2tf(y1.y);
    Bs[bkr*72+bnc+6]=f2tf(y1.z); Bs[bkr*72+bnc+7]=f2tf(y1.w);
    __syncthreads();
#pragma unroll
    for(int kk=0;kk<2;kk++){
      int ks=kk*8;
      unsigned a[2][4], b[4][2];
#pragma unroll
      for(int mt=0;mt<2;mt++){
        int m=m_off+16*mt+lq;
        a[mt][0]=As[(ks+lr)*72+m];
        a[mt][1]=As[(ks+lr)*72+m+8];
        a[mt][2]=As[(ks+4+lr)*72+m];
        a[mt][3]=As[(ks+4+lr)*72+m+8];
      }
#pragma unroll
      for(int nt=0;nt<4;nt++){
        int n=n_off+8*nt+lq;
        b[nt][0]=Bs[(ks+lr)*72+n];
        b[nt][1]=Bs[(ks+4+lr)*72+n];
      }
#pragma unroll
      for(int mt=0;mt<2;mt++)
#pragma unroll
        for(int nt=0;nt<4;nt++) mma8(c[mt][nt],a[mt],b[nt]);
    }
    __syncthreads();
  }
#pragma unroll
  for(int mt=0;mt<2;mt++){
#pragma unroll
    for(int nt=0;nt<4;nt++){
      int cg=col0+n_off+8*nt+2*lr;
#pragma unroll
      for(int half=0;half<2;half++){
        int r=row0+m_off+16*mt+lq+half*8;
        size_t off=(size_t)r*N+cg;
        float v0=c0*c[mt][nt][half*2], v1=c0*c[mt][nt][half*2+1];
        if(c1!=0.f){
          v0+=c1*Ah[(size_t)r*256+cg];
          v1+=c1*Ah[(size_t)r*256+cg+1];
        }
        Ch[off]=v0; Ch[off+1]=v1;
      }
    }
  }
}

// ---------------- a3v TF32 split-K: partial = a3[:,chunk] @ v[chunk,:] ------
// grid (4 m, NH, KC), 128 threads
__global__ __launch_bounds__(128) void a3v_t()
{
  __shared__ unsigned As[16*72];
  __shared__ unsigned Bs[16*72];
  int t=threadIdx.x, lane=t&31, wid=t>>5;
  int h=blockIdx.y, kc=blockIdx.z;
  int row0=blockIdx.x*64, kbase=kc*1280;
  int m_off=32*(wid&1), n_off=32*(wid>>1);
  int lq=lane>>2, lr=lane&3;
  int ar=t>>1, akq=(t&1)*8;
  int bkr=t>>3, bnc=(t&7)*8;
  const float* Ap=g_a3+((size_t)h*LM+row0+ar)*NPD+kbase;
  const float* Bp=g_qkv+(size_t)(kbase+bkr)*1536+1024+h*64+bnc;
  float c[2][4][4];
#pragma unroll
  for(int mt=0;mt<2;mt++)
#pragma unroll
    for(int nt=0;nt<4;nt++)
#pragma unroll
      for(int i=0;i<4;i++) c[mt][nt][i]=0.f;
  for(int k0=0;k0<1280;k0+=16){
    float4 x0=*(const float4*)(Ap+k0+akq);
    float4 x1=*(const float4*)(Ap+k0+akq+4);
    float4 y0=*(const float4*)(Bp+(size_t)k0*1536);
    float4 y1=*(const float4*)(Bp+(size_t)k0*1536+4);
    As[(akq+0)*72+ar]=f2tf(x0.x); As[(akq+1)*72+ar]=f2tf(x0.y);
    As[(akq+2)*72+ar]=f2tf(x0.z); As[(akq+3)*72+ar]=f2tf(x0.w);
    As[(akq+4)*72+ar]=f2tf(x1.x); As[(akq+5)*72+ar]=f2tf(x1.y);
    As[(akq+6)*72+ar]=f2tf(x1.z); As[(akq+7)*72+ar]=f2tf(x1.w);
    Bs[bkr*72+bnc+0]=f2tf(y0.x); Bs[bkr*72+bnc+1]=f2tf(y0.y);
    Bs[bkr*72+bnc+2]=f2tf(y0.z); Bs[bkr*72+bnc+3]=f2tf(y0.w);
    Bs[bkr*72+bnc+4]=f2tf(y1.x); Bs[bkr*72+bnc+5]=f2tf(y1.y);
    Bs[bkr*72+bnc+6]=f2tf(y1.z); Bs[bkr*72+bnc+7]=f2tf(y1.w);
    __syncthreads();
#pragma unroll
    for(int kk=0;kk<2;kk++){
      int ks=kk*8;
      unsigned a[2][4], b[4][2];
#pragma unroll
      for(int mt=0;mt<2;mt++){
        int m=m_off+16*mt+lq;
        a[mt][0]=As[(ks+lr)*72+m];
        a[mt][1]=As[(ks+lr)*72+m+8];
        a[mt][2]=As[(ks+4+lr)*72+m];
        a[mt][3]=As[(ks+4+lr)*72+m+8];
      }
#pragma unroll
      for(int nt=0;nt<4;nt++){
        int n=n_off+8*nt+lq;
        b[nt][0]=Bs[(ks+lr)*72+n];
        b[nt][1]=Bs[(ks+4+lr)*72+n];
      }
#pragma unroll
      for(int mt=0;mt<2;mt++)
#pragma unroll
        for(int nt=0;nt<4;nt++) mma8(c[mt][nt],a[mt],b[nt]);
    }
    __syncthreads();
  }
  float* Cp=g_p3+((size_t)kc*NH+h)*LM*DH;
#pragma unroll
  for(int mt=0;mt<2;mt++){
#pragma unroll
    for(int nt=0;nt<4;nt++){
      int cg=n_off+8*nt+2*lr;
#pragma unroll
      for(int half=0;half<2;half++){
        int r=row0+m_off+16*mt+lq+half*8;
        size_t off=(size_t)r*DH+cg;
        Cp[off]  =c[mt][nt][half*2];
        Cp[off+1]=c[mt][nt][half*2+1];
      }
    }
  }
}

// ------------- LayerNorm + front-pad to NPD rows ---------------------------
__global__ __launch_bounds__(256) void ln_pad_k(const float* __restrict__ hin,
    const float* __restrict__ g, const float* __restrict__ b)
{
  int row=blockIdx.x, t=threadIdx.x;
  float* out=g_xp+(size_t)row*512;
  if(row<255){ out[t]=0.f; out[t+256]=0.f; return; }
  __shared__ float red[32];
  const float* x=hin+(size_t)(row-255)*512;
  float v0=x[t], v1=x[t+256];
  float mean=bSum(v0+v1,red)*(1.f/512.f);
  float d0=v0-mean, d1=v1-mean;
  float var=bSum(d0*d0+d1*d1,red)*(1.f/512.f);
  float rs=1.f/sqrtf(var+1e-5f);
  out[t]=d0*rs*g[t]+b[t];
  out[t+256]=d1*rs*g[t+256]+b[t+256];
}

// ------------- landmarks: mean of 65 consecutive rows ----------------------
__global__ void landmarks_k()
{
  int m=blockIdx.x, h=blockIdx.y, d=threadIdx.x;
  const float* base=g_qkv+(size_t)(m*65)*1536+h*64+d;
  float sq=0.f, sk=0.f;
  for(int j=0;j<65;j++){ sq+=base[(size_t)j*1536]; sk+=base[(size_t)j*1536+512]; }
  g_ql[(h*LM+m)*DH+d]=sq*(0.125f/65.f);
  g_kl[(h*LM+m)*DH+d]=sk*(1.f/65.f);
}

// ------------- a2 = softmax(q_l @ k_l^T) -----------------------------------
__global__ __launch_bounds__(256) void a2_k()
{
  int i=blockIdx.x, h=blockIdx.y, j=threadIdx.x;
  __shared__ float q[DH]; __shared__ float red[32];
  if(j<DH) q[j]=g_ql[(h*LM+i)*DH+j];
  __syncthreads();
  const float* kr=&g_kl[(h*LM+j)*DH];
  float s=0.f;
#pragma unroll
  for(int d=0;d<DH;d++) s+=q[d]*kr[d];
  float mx=bMax(s,red);
  float p=expf(s-mx);
  float ss=bSum(p,red);
  g_a2[((size_t)(h*LM+i))*LM+j]=p/ss;
}

// ------------- pinv init: row/col-sum maxima, denom, z0 = a2^T/den ---------
__global__ __launch_bounds__(256) void sums_k()
{
  int h=blockIdx.x, t=threadIdx.x;
  __shared__ float red[32];
  const float* a=g_a2+(size_t)h*LM*LM;
  float rs=0.f, cs=0.f;
  for(int j=0;j<LM;j++){ rs+=fabsf(a[(size_t)t*LM+j]); cs+=fabsf(a[(size_t)j*LM+t]); }
  float rm=bMax(rs,red), cm=bMax(cs,red);
  if(t==0){ g_mx[h]=rm; g_mx[NH+h]=cm; }
}
__global__ void denom_k()
{
  int t=threadIdx.x;
  float rm=(t<NH)?g_mx[t]:-3.4e38f, cm=(t<NH)?g_mx[NH+t]:-3.4e38f;
  rm=wMax(rm); cm=wMax(cm);
  if(t==0) g_den=rm*cm;
}
__global__ __launch_bounds__(256) void zinit_k()
{
  int i=blockIdx.x, h=blockIdx.y, j=threadIdx.x;
  float inv=1.f/g_den;
  g_z[((size_t)h*LM+i)*LM+j]=g_a2[((size_t)h*LM+j)*LM+i]*inv;
}

// ------------- a3 row softmax over 16640 keys ------------------------------
__global__ __launch_bounds__(256) void a3soft_k()
{
  int i=blockIdx.x, h=blockIdx.y, t=threadIdx.x;
  __shared__ float red[32];
  float* p=g_a3+((size_t)h*LM+i)*NPD;
  float m=-3.4e38f;
  for(int j=t;j<NPD;j+=256) m=fmaxf(m,p[j]);
  float M=bMax(m,red);
  float s=0.f;
  for(int j=t;j<NPD;j+=256) s+=__expf(p[j]-M);
  float S=bSum(s,red);
  float inv=1.f/S;
  for(int j=t;j<NPD;j+=256) p[j]=__expf(p[j]-M)*inv;
}

__global__ void a3vred_k()
{
  int idx=blockIdx.x*256+threadIdx.x;
  float s=0.f;
  for(int kc=0;kc<KC;kc++) s+=g_p3[(size_t)kc*NH*LM*DH+idx];
  g_o3[idx]=s;
}

// ------------- fused a1@W2 + depthwise-33 residual (2 rows/iter) -----------
#define CH 128
__global__ __launch_bounds__(256) void a1res_k(const float* __restrict__ rw,
                                               int row_start, int row_cnt)
{
  extern __shared__ float sm[];
  float* kls=sm;               // 256*65 = 16640
  float* w2s=sm+16640;         // 16640
  float* vs =sm+33280;         // 160*64 = 10240 -> 43520
  float* rws=sm+43520;         // 33 (pad 40)    -> 43560
  float* qs =sm+43560;         // 128            -> 43688
  float* ps =sm+43688;         // 256            -> 43944
  float* ps2=sm+43944;         // 256            -> 44200
  float* op0=sm+44200;         // 256            -> 44456
  float* op1=sm+44456;         // 256            -> 44712
  float* red=sm+44712;         // 64             -> 44776
  int t=threadIdx.x, h=blockIdx.y;
  int i0=row_start+blockIdx.x*CH;
  int rend=row_start+row_cnt;
  for(int idx=t;idx<LM*DH;idx+=256){
    int j=idx>>6, d=idx&63;
    kls[j*65+d]=g_kl[((size_t)h*LM+j)*DH+d];
    w2s[j*65+d]=g_w2[((size_t)h*LM+j)*DH+d];
  }
  for(int idx=t;idx<160*64;idx+=256){
    int rr=idx>>6, d=idx&63, gr=i0-16+rr;
    vs[rr*64+d]=(gr>=0&&gr<NPD)?g_qkv[(size_t)gr*1536+1024+h*64+d]:0.f;
  }
  if(t<33) rws[t]=rw[h*33+t];
  __syncthreads();
  for(int ii=0;ii<CH;ii+=2){
    int i=i0+ii;
    if(i>=rend) break;
    bool v1=(i+1<rend);
    if(t<64) qs[t]=g_qkv[(size_t)i*1536+h*64+t]*0.125f;
    else if(t<128) qs[t]=v1?g_qkv[(size_t)(i+1)*1536+h*64+(t-64)]*0.125f:0.f;
    __syncthreads();
    float l0=0.f, l1=0.f;
#pragma unroll
    for(int d=0;d<DH;d++){
      float kv=kls[t*65+d];
      l0+=qs[d]*kv;
      l1+=qs[64+d]*kv;
    }
    float2 M=bMax2(l0,v1?l1:l0,red);
    float p0=__expf(l0-M.x), p1=__expf(l1-M.y);
    float2 S=bSum2(p0,p1,red);
    ps[t]=p0/S.x; ps2[t]=p1/S.y;
    __syncthreads();
    {
      int g=t>>6, d=t&63;
      float o0=0.f, o1=0.f;
#pragma unroll 8
      for(int j=g*64;j<g*64+64;j++){
        float w=w2s[j*65+d];
        o0+=ps[j]*w;
        o1+=ps2[j]*w;
      }
      op0[g*64+d]=o0;
      op1[g*64+d]=o1;
    }
    __syncthreads();
    if(t<128){
      int rr=t>>6, d=t&63;
      if(rr==0||v1){
        float* opp=rr?op1:op0;
        float o=opp[d]+opp[64+d]+opp[128+d]+opp[192+d];
#pragma unroll
        for(int tap=0;tap<33;tap++) o+=vs[(ii+rr+tap)*64+d]*rws[tap];
        g_ao[(size_t)(i+rr-255)*512+h*64+d]=o;
      }
    }
    __syncthreads();
  }
}

// ------------- PPEG: cf + dw7 + dw5 + dw3 ----------------------------------
__global__ __launch_bounds__(256) void ppeg_k(
    const float* __restrict__ w7, const float* __restrict__ b7,
    const float* __restrict__ w5, const float* __restrict__ b5,
    const float* __restrict__ w3, const float* __restrict__ b3)
{
  extern __shared__ float sm[];
  float* sin_=sm;          // 22*22*65
  float* w7s=sm+31460;     // 49*64
  float* w5s=sm+34596;     // 25*64
  float* w3s=sm+36196;     // 9*64
  float* bs =sm+36772;     // 64
  int t=threadIdx.x;
  int ty0=(blockIdx.x>>3)*16, tx0=(blockIdx.x&7)*16;
  int cbase=blockIdx.y*64;
  for(int idx=t;idx<22*22*64;idx+=256){
    int c=idx&63, pp=idx>>6, yy=pp/22, xx=pp%22;
    int gy=ty0+yy-3, gx=tx0+xx-3;
    sin_[(yy*22+xx)*65+c]=(gy>=0&&gy<128&&gx>=0&&gx<128)?
        g_h[(size_t)(1+gy*128+gx)*512+cbase+c]:0.f;
  }
  for(int idx=t;idx<49*64;idx+=256){ int c=idx&63,k=idx>>6; w7s[k*64+c]=w7[(cbase+c)*49+k]; }
  for(int idx=t;idx<25*64;idx+=256){ int c=idx&63,k=idx>>6; w5s[k*64+c]=w5[(cbase+c)*25+k]; }
  for(int idx=t;idx<9*64;idx+=256){ int c=idx&63,k=idx>>6; w3s[k*64+c]=w3[(cbase+c)*9+k]; }
  if(t<64) bs[t]=b7[cbase+t]+b5[cbase+t]+b3[cbase+t];
  __syncthreads();
  int py=t>>4, px=t&15;
  for(int c=0;c<64;c++){
    float acc=sin_[((py+3)*22+px+3)*65+c]+bs[c];
#pragma unroll
    for(int ky=0;ky<7;ky++)
#pragma unroll
      for(int kx=0;kx<7;kx++)
        acc+=sin_[((py+ky)*22+px+kx)*65+c]*w7s[(ky*7+kx)*64+c];
#pragma unroll
    for(int ky=0;ky<5;ky++)
#pragma unroll
      for(int kx=0;kx<5;kx++)
        acc+=sin_[((py+1+ky)*22+px+1+kx)*65+c]*w5s[(ky*5+kx)*64+c];
#pragma unroll
    for(int ky=0;ky<3;ky++)
#pragma unroll
      for(int kx=0;kx<3;kx++)
        acc+=sin_[((py+2+ky)*22+px+2+kx)*65+c]*w3s[(ky*3+kx)*64+c];
    g_h2[(size_t)(1+(ty0+py)*128+tx0+px)*512+cbase+c]=acc;
  }
}

// ------------- small helpers -----------------------------------------------
__global__ void clscopy_k(const float* __restrict__ cls){ g_h[threadIdx.x]=cls[threadIdx.x]; }
__global__ void row0cpy_k(){ g_h2[threadIdx.x]=g_h[threadIdx.x]; }

// ------------- final: cls out-proj + residual + LN + fc2 -------------------
__global__ __launch_bounds__(512) void final_k(
    const float* __restrict__ outw, const float* __restrict__ outb,
    const float* __restrict__ ng, const float* __restrict__ nb,
    const float* __restrict__ fw, const float* __restrict__ fb,
    float* __restrict__ out)
{
  __shared__ float sh[512]; __shared__ float red[32];
  int t=threadIdx.x;
  float acc=0.f;
  for(int k=0;k<512;k++) acc+=g_ao[k]*outw[(size_t)k*512+t];
  float row=g_h2[t]+acc+outb[t];
  float mean=bSum(row,red)*(1.f/512.f);
  float d=row-mean;
  float var=bSum(d*d,red)*(1.f/512.f);
  float y=d*(1.f/sqrtf(var+1e-5f))*ng[t]+nb[t];
  sh[t]=y;
  __syncthreads();
  if(t<4){
    float o=fb[t];
    for(int c=0;c<512;c++) o+=sh[c]*fw[c*4+t];
    out[t]=o;
  }
}

// ---------------- host orchestration ----------------------------------------
static void* sym(const void* s){ void* p=nullptr; cudaGetSymbolAddress(&p,s); return p; }

static void attn_layer(const float* hin, const float* ng, const float* nbi,
                       const float* qkvw, const float* outw, const float* outb,
                       const float* resw, int layer2,
                       float* ph, float* pxp, float* pqkv, float* pao,
                       float* pz, float* po3, float* pw2,
                       size_t a1sm)
{
  ln_pad_k<<<NPD,256>>>(hin,ng,nbi);
  gemm_tf32<0><<<dim3(1536/128,130),256>>>(pxp,qkvw,pqkv,nullptr,NPD,1536,512);
  landmarks_k<<<dim3(LM,NH),64>>>();
  a2_k<<<dim3(LM,NH),256>>>();
  sums_k<<<NH,256>>>();
  denom_k<<<1,32>>>();
  zinit_k<<<dim3(LM,NH),256>>>();
  nwt_k<<<NWT_BLOCKS,128>>>();                 // 6 Newton iters, final z in g_z
  qkT_t<<<dim3(130,2,NH),256>>>();
  a3soft_k<<<dim3(LM,NH),256>>>();
  a3v_t<<<dim3(4,NH,KC),128>>>();
  a3vred_k<<<NH*LM*DH/256,256>>>();
  g256t<<<dim3(1,4,NH),128>>>(pz,po3,pw2,64,1.f,0.f);
  if(!layer2){
    a1res_k<<<dim3((NR+CH-1)/CH,NH),256,a1sm>>>(resw,255,NR);
    gemm_tf32<2><<<dim3(4,(NR+127)/128),256>>>(pao,outw,ph,outb,NR,512,512);
  }else{
    a1res_k<<<dim3(1,NH),256,a1sm>>>(resw,255,1);
  }
}

extern "C" void kernel_launch(void* const* d_in, const int* in_sizes, int n_in,
                              void* d_out, int out_size)
{
  const float* x     =(const float*)d_in[0];
  const float* fc1w  =(const float*)d_in[1];
  const float* fc1b  =(const float*)d_in[2];
  const float* cls   =(const float*)d_in[3];
  const float* l1ng  =(const float*)d_in[4];
  const float* l1nb  =(const float*)d_in[5];
  const float* l1qkv =(const float*)d_in[6];
  const float* l1ow  =(const float*)d_in[7];
  const float* l1ob  =(const float*)d_in[8];
  const float* l1rw  =(const float*)d_in[9];

  int ppegBase, l2Base;
  if (in_sizes[10] == 25088) { ppegBase = 10; l2Base = 16; }
  else                       { l2Base = 10; ppegBase = 16; }

  const float* w7   =(const float*)d_in[ppegBase+0];
  const float* b7   =(const float*)d_in[ppegBase+1];
  const float* w5   =(const float*)d_in[ppegBase+2];
  const float* b5   =(const float*)d_in[ppegBase+3];
  const float* w3   =(const float*)d_in[ppegBase+4];
  const float* b3   =(const float*)d_in[ppegBase+5];
  const float* l2ng =(const float*)d_in[l2Base+0];
  const float* l2nb =(const float*)d_in[l2Base+1];
  const float* l2qkv=(const float*)d_in[l2Base+2];
  const float* l2ow =(const float*)d_in[l2Base+3];
  const float* l2ob =(const float*)d_in[l2Base+4];
  const float* l2rw =(const float*)d_in[l2Base+5];
  const float* nng  =(const float*)d_in[22];
  const float* nnb  =(const float*)d_in[23];
  const float* fc2w =(const float*)d_in[24];
  const float* fc2b =(const float*)d_in[25];
  float* out=(float*)d_out;

  float* ph  =(float*)sym(g_h);
  float* ph2 =(float*)sym(g_h2);
  float* pxp =(float*)sym(g_xp);
  float* pqkv=(float*)sym(g_qkv);
  float* pao =(float*)sym(g_ao);
  float* pz  =(float*)sym(g_z);
  float* po3 =(float*)sym(g_o3);
  float* pw2 =(float*)sym(g_w2);

  const size_t A1SM=44776*sizeof(float);   // ~179.1 KB
  const size_t PPSM=36836*sizeof(float);   // ~147.3 KB
  cudaFuncSetAttribute(a1res_k,cudaFuncAttributeMaxDynamicSharedMemorySize,(int)A1SM);
  cudaFuncSetAttribute(ppeg_k, cudaFuncAttributeMaxDynamicSharedMemorySize,(int)PPSM);

  // fc1 + cls
  gemm_tf32<1><<<dim3(4,128),256>>>(x,fc1w,ph+512,fc1b,16384,512,1024);
  clscopy_k<<<1,512>>>(cls);
  // layer 1
  attn_layer(ph,l1ng,l1nb,l1qkv,l1ow,l1ob,l1rw,0,
             ph,pxp,pqkv,pao,pz,po3,pw2,A1SM);
  // PPEG
  row0cpy_k<<<1,512>>>();
  ppeg_k<<<dim3(64,8),256,PPSM>>>(w7,b7,w5,b5,w3,b3);
  // layer 2 (only cls row of attention output needed)
  attn_layer(ph2,l2ng,l2nb,l2qkv,l2ow,l2ob,l2rw,1,
             ph2,pxp,pqkv,pao,pz,po3,pw2,A1SM);
  // final: out-proj row + residual + LN + fc2
  final_k<<<1,512>>>(l2ow,l2ob,nng,nnb,fc2w,fc2b,out);
}

// round 14
// speedup vs baseline: 1.6074x; 1.0706x over previous
#include <cuda_runtime.h>
#include <math.h>

#define NR  16385
#define NPD 16640
#define NH  8
#define DH  64
#define LM  256
#define KC  13          // split-K chunks for a3@v (13*1280 = 16640)

// ---------------- scratch (device globals, allocation-free) ----------------
__device__ float g_h  [NR  * 512];
__device__ float g_h2 [NR  * 512];
__device__ float g_xp [NPD * 512];
__device__ float g_qkv[NPD * 1536];
__device__ float g_ao [NR  * 512];
__device__ float g_ql [NH * LM * DH];
__device__ float g_kl [NH * LM * DH];
__device__ float g_a2 [NH * LM * LM];
__device__ float g_z  [NH * LM * LM];
__device__ float g_zb [NH * LM * LM];
__device__ float g_az [NH * LM * LM];
__device__ float g_t1 [NH * LM * LM];
__device__ float g_t2 [NH * LM * LM];
__device__ float g_a3 [NH * LM * NPD];
__device__ float g_p3 [KC * NH * LM * DH];
__device__ float g_o3 [NH * LM * DH];
__device__ float g_w2 [NH * LM * DH];
__device__ float g_mx [2 * NH];
__device__ float2 g_sm[NH * LM];   // per-row (max, 1/sum) of a3 logits
__device__ float g_den;
__device__ unsigned g_cnt;   // zero-init; self-resetting barrier counter
__device__ unsigned g_phs;   // monotone phase flag

// ---------------- reductions ----------------
__device__ __forceinline__ float wSum(float v){
#pragma unroll
  for(int o=16;o>0;o>>=1) v += __shfl_xor_sync(0xffffffffu,v,o);
  return v;
}
__device__ __forceinline__ float wMax(float v){
#pragma unroll
  for(int o=16;o>0;o>>=1) v = fmaxf(v,__shfl_xor_sync(0xffffffffu,v,o));
  return v;
}
__device__ __forceinline__ float bSum(float v, float* red){
  int w=threadIdx.x>>5, l=threadIdx.x&31, nw=(blockDim.x+31)>>5;
  v=wSum(v); if(l==0) red[w]=v; __syncthreads();
  if(w==0){ float r=(l<nw)?red[l]:0.f; r=wSum(r); if(l==0) red[0]=r; }
  __syncthreads(); float r=red[0]; __syncthreads(); return r;
}
__device__ __forceinline__ float bMax(float v, float* red){
  int w=threadIdx.x>>5, l=threadIdx.x&31, nw=(blockDim.x+31)>>5;
  v=wMax(v); if(l==0) red[w]=v; __syncthreads();
  if(w==0){ float r=(l<nw)?red[l]:-3.4e38f; r=wMax(r); if(l==0) red[0]=r; }
  __syncthreads(); float r=red[0]; __syncthreads(); return r;
}
// dual reductions (blockDim == 256)
__device__ __forceinline__ float2 bMax2(float a, float b, float* red){
  int w=threadIdx.x>>5, l=threadIdx.x&31;
#pragma unroll
  for(int o=16;o>0;o>>=1){
    a=fmaxf(a,__shfl_xor_sync(0xffffffffu,a,o));
    b=fmaxf(b,__shfl_xor_sync(0xffffffffu,b,o));
  }
  if(l==0){ red[w]=a; red[32+w]=b; }
  __syncthreads();
  if(w==0){
    float x=(l<8)?red[l]:-3.4e38f;
    float y=(l<8)?red[32+l]:-3.4e38f;
#pragma unroll
    for(int o=4;o>0;o>>=1){
      x=fmaxf(x,__shfl_xor_sync(0xffffffffu,x,o));
      y=fmaxf(y,__shfl_xor_sync(0xffffffffu,y,o));
    }
    if(l==0){ red[0]=x; red[32]=y; }
  }
  __syncthreads();
  float2 r=make_float2(red[0],red[32]);
  __syncthreads();
  return r;
}
__device__ __forceinline__ float2 bSum2(float a, float b, float* red){
  int w=threadIdx.x>>5, l=threadIdx.x&31;
#pragma unroll
  for(int o=16;o>0;o>>=1){
    a+=__shfl_xor_sync(0xffffffffu,a,o);
    b+=__shfl_xor_sync(0xffffffffu,b,o);
  }
  if(l==0){ red[w]=a; red[32+w]=b; }
  __syncthreads();
  if(w==0){
    float x=(l<8)?red[l]:0.f;
    float y=(l<8)?red[32+l]:0.f;
#pragma unroll
    for(int o=4;o>0;o>>=1){
      x+=__shfl_xor_sync(0xffffffffu,x,o);
      y+=__shfl_xor_sync(0xffffffffu,y,o);
    }
    if(l==0){ red[0]=x; red[32]=y; }
  }
  __syncthreads();
  float2 r=make_float2(red[0],red[32]);
  __syncthreads();
  return r;
}

// ---------------- TF32 mma helpers ----------------
__device__ __forceinline__ unsigned f2tf(float f){
  unsigned u; asm("cvt.rna.tf32.f32 %0, %1;" : "=r"(u) : "f"(f)); return u;
}
__device__ __forceinline__ void mma8(float* c, const unsigned* a, const unsigned* b){
  asm volatile("mma.sync.aligned.m16n8k8.row.col.f32.tf32.tf32.f32 "
    "{%0,%1,%2,%3}, {%4,%5,%6,%7}, {%8,%9}, {%0,%1,%2,%3};"
    : "+f"(c[0]),"+f"(c[1]),"+f"(c[2]),"+f"(c[3])
    : "r"(a[0]),"r"(a[1]),"r"(a[2]),"r"(a[3]), "r"(b[0]),"r"(b[1]));
}

// ---------------- TF32 GEMM (double-buffered): C=A@B (+epilogue) -----------
// MODE 0: C=AB   MODE 1: C=relu(AB+bias)   MODE 2: C += AB + bias
// BM=BN=128, BK=16, 256 threads, warp tile 32x64 (warps 4m x 2n)
template<int MODE>
__global__ __launch_bounds__(256) void gemm_tf32(
    const float* __restrict__ A, const float* __restrict__ B, float* __restrict__ Cd,
    const float* __restrict__ bias, int M, int N, int K)
{
  __shared__ unsigned As[2][16*136];
  __shared__ unsigned Bs[2][16*136];
  int t=threadIdx.x, lane=t&31, wid=t>>5;
  int row0=blockIdx.y*128, col0=blockIdx.x*128;
  int m_off=32*(wid&3), n_off=64*(wid>>2);
  int lq=lane>>2, lr=lane&3;
  int ar=t>>1, akq=(t&1)*8;
  int bkr=t>>4, bnc=(t&15)*8;
  bool aval=(row0+ar)<M;
  const float* Ap=A+(size_t)(row0+ar)*K;
  const float* Bp=B+(size_t)bkr*N+col0+bnc;

  float c[2][8][4];
#pragma unroll
  for(int mt=0;mt<2;mt++)
#pragma unroll
    for(int nt=0;nt<8;nt++)
#pragma unroll
      for(int i=0;i<4;i++) c[mt][nt][i]=0.f;

  float4 xa0,xa1,yb0,yb1;
  // prefetch k0 = 0
  xa0=make_float4(0,0,0,0); xa1=xa0;
  if(aval){ xa0=*(const float4*)(Ap+akq); xa1=*(const float4*)(Ap+akq+4); }
  yb0=*(const float4*)(Bp); yb1=*(const float4*)(Bp+4);
  {
    unsigned* as=As[0]; unsigned* bs=Bs[0];
    as[(akq+0)*136+ar]=f2tf(xa0.x); as[(akq+1)*136+ar]=f2tf(xa0.y);
    as[(akq+2)*136+ar]=f2tf(xa0.z); as[(akq+3)*136+ar]=f2tf(xa0.w);
    as[(akq+4)*136+ar]=f2tf(xa1.x); as[(akq+5)*136+ar]=f2tf(xa1.y);
    as[(akq+6)*136+ar]=f2tf(xa1.z); as[(akq+7)*136+ar]=f2tf(xa1.w);
    bs[bkr*136+bnc+0]=f2tf(yb0.x); bs[bkr*136+bnc+1]=f2tf(yb0.y);
    bs[bkr*136+bnc+2]=f2tf(yb0.z); bs[bkr*136+bnc+3]=f2tf(yb0.w);
    bs[bkr*136+bnc+4]=f2tf(yb1.x); bs[bkr*136+bnc+5]=f2tf(yb1.y);
    bs[bkr*136+bnc+6]=f2tf(yb1.z); bs[bkr*136+bnc+7]=f2tf(yb1.w);
  }
  __syncthreads();
  int nb=0;
  for(int k0=16;k0<K+16;k0+=16){
    bool more=(k0<K);
    if(more){
      xa0=make_float4(0,0,0,0); xa1=xa0;
      if(aval){ xa0=*(const float4*)(Ap+k0+akq); xa1=*(const float4*)(Ap+k0+akq+4); }
      yb0=*(const float4*)(Bp+(size_t)k0*N); yb1=*(const float4*)(Bp+(size_t)k0*N+4);
    }
    {
      const unsigned* as=As[nb]; const unsigned* bs=Bs[nb];
#pragma unroll
      for(int kk=0;kk<2;kk++){
        int ks=kk*8;
        unsigned a[2][4], b[8][2];
#pragma unroll
        for(int mt=0;mt<2;mt++){
          int m=m_off+16*mt+lq;
          a[mt][0]=as[(ks+lr)*136+m];
          a[mt][1]=as[(ks+lr)*136+m+8];
          a[mt][2]=as[(ks+4+lr)*136+m];
          a[mt][3]=as[(ks+4+lr)*136+m+8];
        }
#pragma unroll
        for(int nt=0;nt<8;nt++){
          int n=n_off+8*nt+lq;
          b[nt][0]=bs[(ks+lr)*136+n];
          b[nt][1]=bs[(ks+4+lr)*136+n];
        }
#pragma unroll
        for(int mt=0;mt<2;mt++)
#pragma unroll
          for(int nt=0;nt<8;nt++) mma8(c[mt][nt],a[mt],b[nt]);
      }
    }
    if(more){
      unsigned* as=As[nb^1]; unsigned* bs=Bs[nb^1];
      as[(akq+0)*136+ar]=f2tf(xa0.x); as[(akq+1)*136+ar]=f2tf(xa0.y);
      as[(akq+2)*136+ar]=f2tf(xa0.z); as[(akq+3)*136+ar]=f2tf(xa0.w);
      as[(akq+4)*136+ar]=f2tf(xa1.x); as[(akq+5)*136+ar]=f2tf(xa1.y);
      as[(akq+6)*136+ar]=f2tf(xa1.z); as[(akq+7)*136+ar]=f2tf(xa1.w);
      bs[bkr*136+bnc+0]=f2tf(yb0.x); bs[bkr*136+bnc+1]=f2tf(yb0.y);
      bs[bkr*136+bnc+2]=f2tf(yb0.z); bs[bkr*136+bnc+3]=f2tf(yb0.w);
      bs[bkr*136+bnc+4]=f2tf(yb1.x); bs[bkr*136+bnc+5]=f2tf(yb1.y);
      bs[bkr*136+bnc+6]=f2tf(yb1.z); bs[bkr*136+bnc+7]=f2tf(yb1.w);
      __syncthreads();
      nb^=1;
    }
  }
#pragma unroll
  for(int mt=0;mt<2;mt++){
    int rA=row0+m_off+16*mt+lq;
    int rB=rA+8;
#pragma unroll
    for(int nt=0;nt<8;nt++){
      int cg=col0+n_off+8*nt+2*lr;
#pragma unroll
      for(int half=0;half<2;half++){
        int r=half?rB:rA;
        if(r<M){
          size_t off=(size_t)r*N+cg;
          float v0=c[mt][nt][half*2], v1=c[mt][nt][half*2+1];
          if(MODE==1){
            v0+=bias[cg];   v0=v0>0.f?v0:0.f;
            v1+=bias[cg+1]; v1=v1>0.f?v1:0.f;
            Cd[off]=v0; Cd[off+1]=v1;
          }else if(MODE==2){
            Cd[off]  +=v0+bias[cg];
            Cd[off+1]+=v1+bias[cg+1];
          }else{
            Cd[off]=v0; Cd[off+1]=v1;
          }
        }
      }
    }
  }
}

// ---------------- qkT TF32: a3 logits = q_l(256x64) @ k^T ------------------
// grid (130 keys/128, 2 qrows/128, NH), 256 threads
__global__ __launch_bounds__(256) void qkT_t()
{
  __shared__ unsigned As[16*136];
  __shared__ unsigned Bs[16*136];
  int t=threadIdx.x, lane=t&31, wid=t>>5;
  int h=blockIdx.z;
  int col0=blockIdx.x*128, row0=blockIdx.y*128;
  int m_off=32*(wid&3), n_off=64*(wid>>2);
  int lq=lane>>2, lr=lane&3;
  int ar=t>>1, akq=(t&1)*8;
  int bj=t&127, kh=(t>>7)*8;
  const float* Ap=g_ql+(size_t)h*LM*DH+(size_t)(row0+ar)*64;
  const float* Bp=g_qkv+(size_t)(col0+bj)*1536+512+h*64+kh;

  float c[2][8][4];
#pragma unroll
  for(int mt=0;mt<2;mt++)
#pragma unroll
    for(int nt=0;nt<8;nt++)
#pragma unroll
      for(int i=0;i<4;i++) c[mt][nt][i]=0.f;

  for(int k0=0;k0<64;k0+=16){
    float4 x0=*(const float4*)(Ap+k0+akq);
    float4 x1=*(const float4*)(Ap+k0+akq+4);
    float4 y0=*(const float4*)(Bp+k0);
    float4 y1=*(const float4*)(Bp+k0+4);
    As[(akq+0)*136+ar]=f2tf(x0.x); As[(akq+1)*136+ar]=f2tf(x0.y);
    As[(akq+2)*136+ar]=f2tf(x0.z); As[(akq+3)*136+ar]=f2tf(x0.w);
    As[(akq+4)*136+ar]=f2tf(x1.x); As[(akq+5)*136+ar]=f2tf(x1.y);
    As[(akq+6)*136+ar]=f2tf(x1.z); As[(akq+7)*136+ar]=f2tf(x1.w);
    Bs[(kh+0)*136+bj]=f2tf(y0.x); Bs[(kh+1)*136+bj]=f2tf(y0.y);
    Bs[(kh+2)*136+bj]=f2tf(y0.z); Bs[(kh+3)*136+bj]=f2tf(y0.w);
    Bs[(kh+4)*136+bj]=f2tf(y1.x); Bs[(kh+5)*136+bj]=f2tf(y1.y);
    Bs[(kh+6)*136+bj]=f2tf(y1.z); Bs[(kh+7)*136+bj]=f2tf(y1.w);
    __syncthreads();
#pragma unroll
    for(int kk=0;kk<2;kk++){
      int ks=kk*8;
      unsigned a[2][4], b[8][2];
#pragma unroll
      for(int mt=0;mt<2;mt++){
        int m=m_off+16*mt+lq;
        a[mt][0]=As[(ks+lr)*136+m];
        a[mt][1]=As[(ks+lr)*136+m+8];
        a[mt][2]=As[(ks+4+lr)*136+m];
        a[mt][3]=As[(ks+4+lr)*136+m+8];
      }
#pragma unroll
      for(int nt=0;nt<8;nt++){
        int n=n_off+8*nt+lq;
        b[nt][0]=Bs[(ks+lr)*136+n];
        b[nt][1]=Bs[(ks+4+lr)*136+n];
      }
#pragma unroll
      for(int mt=0;mt<2;mt++)
#pragma unroll
        for(int nt=0;nt<8;nt++) mma8(c[mt][nt],a[mt],b[nt]);
    }
    __syncthreads();
  }
#pragma unroll
  for(int mt=0;mt<2;mt++){
#pragma unroll
    for(int nt=0;nt<8;nt++){
      int cg=col0+n_off+8*nt+2*lr;
#pragma unroll
      for(int half=0;half<2;half++){
        int r=row0+m_off+16*mt+lq+half*8;
        size_t off=((size_t)h*LM+r)*NPD+cg;
        g_a3[off]  =c[mt][nt][half*2];
        g_a3[off+1]=c[mt][nt][half*2+1];
      }
    }
  }
}

// ---------------- TF32 64x64 step for Newton (double-buffered) --------------
__device__ __forceinline__ void gemm64_tc(unsigned* AsB, unsigned* BsB,
    const float* __restrict__ Ah, const float* __restrict__ Bh, float* __restrict__ Ch,
    float c0, float c1, int row0, int col0)
{
  int t=threadIdx.x, lane=t&31, wid=t>>5;
  int m_off=32*(wid&1), n_off=32*(wid>>1);
  int lq=lane>>2, lr=lane&3;
  int ar=t>>1, akq=(t&1)*8;
  int bkr=t>>3, bnc=(t&7)*8;
  const float* Ap=Ah+(size_t)(row0+ar)*256;
  const float* Bp=Bh+(size_t)bkr*256+col0+bnc;
  float c[2][4][4];
#pragma unroll
  for(int mt=0;mt<2;mt++)
#pragma unroll
    for(int nt=0;nt<4;nt++)
#pragma unroll
      for(int i=0;i<4;i++) c[mt][nt][i]=0.f;

  float4 x0,x1,y0,y1;
  x0=*(const float4*)(Ap+akq);
  x1=*(const float4*)(Ap+akq+4);
  y0=*(const float4*)(Bp);
  y1=*(const float4*)(Bp+4);
  {
    unsigned* as=AsB; unsigned* bs=BsB;
    as[(akq+0)*72+ar]=f2tf(x0.x); as[(akq+1)*72+ar]=f2tf(x0.y);
    as[(akq+2)*72+ar]=f2tf(x0.z); as[(akq+3)*72+ar]=f2tf(x0.w);
    as[(akq+4)*72+ar]=f2tf(x1.x); as[(akq+5)*72+ar]=f2tf(x1.y);
    as[(akq+6)*72+ar]=f2tf(x1.z); as[(akq+7)*72+ar]=f2tf(x1.w);
    bs[bkr*72+bnc+0]=f2tf(y0.x); bs[bkr*72+bnc+1]=f2tf(y0.y);
    bs[bkr*72+bnc+2]=f2tf(y0.z); bs[bkr*72+bnc+3]=f2tf(y0.w);
    bs[bkr*72+bnc+4]=f2tf(y1.x); bs[bkr*72+bnc+5]=f2tf(y1.y);
    bs[bkr*72+bnc+6]=f2tf(y1.z); bs[bkr*72+bnc+7]=f2tf(y1.w);
  }
  __syncthreads();
  int nb=0;
  for(int k0=16;k0<256+16;k0+=16){
    bool more=(k0<256);
    if(more){
      x0=*(const float4*)(Ap+k0+akq);
      x1=*(const float4*)(Ap+k0+akq+4);
      y0=*(const float4*)(Bp+(size_t)k0*256);
      y1=*(const float4*)(Bp+(size_t)k0*256+4);
    }
    {
      const unsigned* as=AsB+nb*1152; const unsigned* bs=BsB+nb*1152;
#pragma unroll
      for(int kk=0;kk<2;kk++){
        int ks=kk*8;
        unsigned a[2][4], b[4][2];
#pragma unroll
        for(int mt=0;mt<2;mt++){
          int m=m_off+16*mt+lq;
          a[mt][0]=as[(ks+lr)*72+m];
          a[mt][1]=as[(ks+lr)*72+m+8];
          a[mt][2]=as[(ks+4+lr)*72+m];
          a[mt][3]=as[(ks+4+lr)*72+m+8];
        }
#pragma unroll
        for(int nt=0;nt<4;nt++){
          int n=n_off+8*nt+lq;
          b[nt][0]=bs[(ks+lr)*72+n];
          b[nt][1]=bs[(ks+4+lr)*72+n];
        }
#pragma unroll
        for(int mt=0;mt<2;mt++)
#pragma unroll
          for(int nt=0;nt<4;nt++) mma8(c[mt][nt],a[mt],b[nt]);
      }
    }
    if(more){
      unsigned* as=AsB+(nb^1)*1152; unsigned* bs=BsB+(nb^1)*1152;
      as[(akq+0)*72+ar]=f2tf(x0.x); as[(akq+1)*72+ar]=f2tf(x0.y);
      as[(akq+2)*72+ar]=f2tf(x0.z); as[(akq+3)*72+ar]=f2tf(x0.w);
      as[(akq+4)*72+ar]=f2tf(x1.x); as[(akq+5)*72+ar]=f2tf(x1.y);
      as[(akq+6)*72+ar]=f2tf(x1.z); as[(akq+7)*72+ar]=f2tf(x1.w);
      bs[bkr*72+bnc+0]=f2tf(y0.x); bs[bkr*72+bnc+1]=f2tf(y0.y);
      bs[bkr*72+bnc+2]=f2tf(y0.z); bs[bkr*72+bnc+3]=f2tf(y0.w);
      bs[bkr*72+bnc+4]=f2tf(y1.x); bs[bkr*72+bnc+5]=f2tf(y1.y);
      bs[bkr*72+bnc+6]=f2tf(y1.z); bs[bkr*72+bnc+7]=f2tf(y1.w);
      __syncthreads();
      nb^=1;
    }
  }
#pragma unroll
  for(int mt=0;mt<2;mt++){
#pragma unroll
    for(int nt=0;nt<4;nt++){
      int cg=col0+n_off+8*nt+2*lr;
#pragma unroll
      for(int half=0;half<2;half++){
        int r=row0+m_off+16*mt+lq+half*8;
        size_t off=(size_t)r*256+cg;
        float v0=c0*c[mt][nt][half*2], v1=c0*c[mt][nt][half*2+1];
        if(c1!=0.f){
          v0+=c1*Ah[off];
          v1+=c1*Ah[off+1];
        }
        Ch[off]=v0; Ch[off+1]=v1;
      }
    }
  }
}

// ---------------- grid barrier (self-resetting; replay-safe) ----------------
#define NWT_BLOCKS 128
__device__ __forceinline__ void gridbar(unsigned &phase){
  __syncthreads();
  if(threadIdx.x==0){
    __threadfence();
    unsigned old=atomicInc(&g_cnt,NWT_BLOCKS-1u);
    unsigned target=phase+1u;
    if(old==NWT_BLOCKS-1u){
      atomicExch(&g_phs,target);
    }else{
      while(atomicAdd(&g_phs,0u)!=target) __nanosleep(64);
    }
    __threadfence();
  }
  __syncthreads();
  phase++;
}

// ---------------- persistent Newton pinv: 6 iters x 4 GEMMs -----------------
__global__ __launch_bounds__(128) void nwt_k()
{
  __shared__ unsigned As[2*16*72];
  __shared__ unsigned Bs[2*16*72];
  __shared__ unsigned ph0;
  int t=threadIdx.x;
  int h=blockIdx.x>>4, tile=blockIdx.x&15;
  int row0=(tile>>2)*64, col0=(tile&3)*64;
  if(t==0) ph0=atomicAdd(&g_phs,0u);
  __syncthreads();
  unsigned phase=ph0;
  size_t ho=(size_t)h*65536;
  float* z =g_z +ho;
  float* zn=g_zb+ho;
#pragma unroll 1
  for(int it=0;it<6;it++){
    gemm64_tc(As,Bs,g_a2+ho,z,        g_az+ho, 1.f,  0.f,  row0,col0); gridbar(phase);
    gemm64_tc(As,Bs,g_az+ho,g_az+ho,  g_t1+ho,-1.f,  7.f,  row0,col0); gridbar(phase);
    gemm64_tc(As,Bs,g_az+ho,g_t1+ho,  g_t2+ho,-1.f, 15.f,  row0,col0); gridbar(phase);
    gemm64_tc(As,Bs,z,      g_t2+ho,  zn,     -0.25f,3.25f,row0,col0); gridbar(phase);
    float* tmp=z; z=zn; zn=tmp;
  }
}

// ---------- batched 8-head TF32 GEMM (for w2 = z@o3, N=64) ------------------
__global__ __launch_bounds__(128) void g256t(
    const float* __restrict__ A, const float* __restrict__ B, float* __restrict__ Cd,
    int N, float c0, float c1)
{
  __shared__ unsigned As[16*72];
  __shared__ unsigned Bs[16*72];
  const float* Ah=A+(size_t)blockIdx.z*65536;
  const float* Bh=B+(size_t)blockIdx.z*256*N;
  float* Ch=Cd+(size_t)blockIdx.z*256*N;
  int t=threadIdx.x, lane=t&31, wid=t>>5;
  int row0=blockIdx.y*64, col0=blockIdx.x*64;
  int m_off=32*(wid&1), n_off=32*(wid>>1);
  int lq=lane>>2, lr=lane&3;
  int ar=t>>1, akq=(t&1)*8;
  int bkr=t>>3, bnc=(t&7)*8;
  const float* Ap=Ah+(size_t)(row0+ar)*256;
  const float* Bp=Bh+(size_t)bkr*N+col0+bnc;
  float c[2][4][4];
#pragma unroll
  for(int mt=0;mt<2;mt++)
#pragma unroll
    for(int nt=0;nt<4;nt++)
#pragma unroll
      for(int i=0;i<4;i++) c[mt][nt][i]=0.f;
  for(int k0=0;k0<256;k0+=16){
    float4 x0=*(const float4*)(Ap+k0+akq);
    float4 x1=*(const float4*)(Ap+k0+akq+4);
    float4 y0=*(const float4*)(Bp+(size_t)k0*N);
    float4 y1=*(const float4*)(Bp+(size_t)k0*N+4);
    As[(akq+0)*72+ar]=f2tf(x0.x); As[(akq+1)*72+ar]=f2tf(x0.y);
    As[(akq+2)*72+ar]=f2tf(x0.z); As[(akq+3)*72+ar]=f2tf(x0.w);
    As[(akq+4)*72+ar]=f2tf(x1.x); As[(akq+5)*72+ar]=f2tf(x1.y);
    As[(akq+6)*72+ar]=f2tf(x1.z); As[(akq+7)*72+ar]=f2tf(x1.w);
    Bs[bkr*72+bnc+0]=f2tf(y0.x); Bs[bkr*72+bnc+1]=f2tf(y0.y);
    Bs[bkr*72+bnc+2]=f2tf(y0.z); Bs[bkr*72+bnc+3]=f2tf(y0.w);
    Bs[bkr*72+bnc+4]=f2tf(y1.x); Bs[bkr*72+bnc+5]=f2tf(y1.y);
    Bs[bkr*72+bnc+6]=f2tf(y1.z); Bs[bkr*72+bnc+7]=f2tf(y1.w);
    __syncthreads();
#pragma unroll
    for(int kk=0;kk<2;kk++){
      int ks=kk*8;
      unsigned a[2][4], b[4][2];
#pragma unroll
      for(int mt=0;mt<2;mt++){
        int m=m_off+16*mt+lq;
        a[mt][0]=As[(ks+lr)*72+m];
        a[mt][1]=As[(ks+lr)*72+m+8];
        a[mt][2]=As[(ks+4+lr)*72+m];
        a[mt][3]=As[(ks+4+lr)*72+m+8];
      }
#pragma unroll
      for(int nt=0;nt<4;nt++){
        int n=n_off+8*nt+lq;
        b[nt][0]=Bs[(ks+lr)*72+n];
        b[nt][1]=Bs[(ks+4+lr)*72+n];
      }
#pragma unroll
      for(int mt=0;mt<2;mt++)
#pragma unroll
        for(int nt=0;nt<4;nt++) mma8(c[mt][nt],a[mt],b[nt]);
    }
    __syncthreads();
  }
#pragma unroll
  for(int mt=0;mt<2;mt++){
#pragma unroll
    for(int nt=0;nt<4;nt++){
      int cg=col0+n_off+8*nt+2*lr;
#pragma unroll
      for(int half=0;half<2;half++){
        int r=row0+m_off+16*mt+lq+half*8;
        size_t off=(size_t)r*N+cg;
        float v0=c0*c[mt][nt][half*2], v1=c0*c[mt][nt][half*2+1];
        if(c1!=0.f){
          v0+=c1*Ah[(size_t)r*256+cg];
          v1+=c1*Ah[(size_t)r*256+cg+1];
        }
        Ch[off]=v0; Ch[off+1]=v1;
      }
    }
  }
}

// ---------------- a3v TF32 split-K with fused exp normalize -----------------
// partial = softmaxrow(a3)[:,chunk] @ v[chunk,:]; grid (4 m, NH, KC), 128 thr
__global__ __launch_bounds__(128) void a3v_t()
{
  __shared__ unsigned As[16*72];
  __shared__ unsigned Bs[16*72];
  int t=threadIdx.x, lane=t&31, wid=t>>5;
  int h=blockIdx.y, kc=blockIdx.z;
  int row0=blockIdx.x*64, kbase=kc*1280;
  int m_off=32*(wid&1), n_off=32*(wid>>1);
  int lq=lane>>2, lr=lane&3;
  int ar=t>>1, akq=(t&1)*8;
  int bkr=t>>3, bnc=(t&7)*8;
  const float* Ap=g_a3+((size_t)h*LM+row0+ar)*NPD+kbase;
  const float* Bp=g_qkv+(size_t)(kbase+bkr)*1536+1024+h*64+bnc;
  float2 ms=g_sm[h*LM+row0+ar];
  float c[2][4][4];
#pragma unroll
  for(int mt=0;mt<2;mt++)
#pragma unroll
    for(int nt=0;nt<4;nt++)
#pragma unroll
      for(int i=0;i<4;i++) c[mt][nt][i]=0.f;
  for(int k0=0;k0<1280;k0+=16){
    float4 x0=*(const float4*)(Ap+k0+akq);
    float4 x1=*(const float4*)(Ap+k0+akq+4);
    float4 y0=*(const float4*)(Bp+(size_t)k0*1536);
    float4 y1=*(const float4*)(Bp+(size_t)k0*1536+4);
    x0.x=__expf(x0.x-ms.x)*ms.y; x0.y=__expf(x0.y-ms.x)*ms.y;
    x0.z=__expf(x0.z-ms.x)*ms.y; x0.w=__expf(x0.w-ms.x)*ms.y;
    x1.x=__expf(x1.x-ms.x)*ms.y; x1.y=__expf(x1.y-ms.x)*ms.y;
    x1.z=__expf(x1.z-ms.x)*ms.y; x1.w=__expf(x1.w-ms.x)*ms.y;
    As[(akq+0)*72+ar]=f2tf(x0.x); As[(akq+1)*72+ar]=f2tf(x0.y);
    As[(akq+2)*72+ar]=f2tf(x0.z); As[(akq+3)*72+ar]=f2tf(x0.w);
    As[(akq+4)*72+ar]=f2tf(x1.x); As[(akq+5)*72+ar]=f2tf(x1.y);
    As[(akq+6)*72+ar]=f2tf(x1.z); As[(akq+7)*72+ar]=f2tf(x1.w);
    Bs[bkr*72+bnc+0]=f2tf(y0.x); Bs[bkr*72+bnc+1]=f2tf(y0.y);
    Bs[bkr*72+bnc+2]=f2tf(y0.z); Bs[bkr*72+bnc+3]=f2tf(y0.w);
    Bs[bkr*72+bnc+4]=f2tf(y1.x); Bs[bkr*72+bnc+5]=f2tf(y1.y);
    Bs[bkr*72+bnc+6]=f2tf(y1.z); Bs[bkr*72+bnc+7]=f2tf(y1.w);
    __syncthreads();
#pragma unroll
    for(int kk=0;kk<2;kk++){
      int ks=kk*8;
      unsigned a[2][4], b[4][2];
#pragma unroll
      for(int mt=0;mt<2;mt++){
        int m=m_off+16*mt+lq;
        a[mt][0]=As[(ks+lr)*72+m];
        a[mt][1]=As[(ks+lr)*72+m+8];
        a[mt][2]=As[(ks+4+lr)*72+m];
        a[mt][3]=As[(ks+4+lr)*72+m+8];
      }
#pragma unroll
      for(int nt=0;nt<4;nt++){
        int n=n_off+8*nt+lq;
        b[nt][0]=Bs[(ks+lr)*72+n];
        b[nt][1]=Bs[(ks+4+lr)*72+n];
      }
#pragma unroll
      for(int mt=0;mt<2;mt++)
#pragma unroll
        for(int nt=0;nt<4;nt++) mma8(c[mt][nt],a[mt],b[nt]);
    }
    __syncthreads();
  }
  float* Cp=g_p3+((size_t)kc*NH+h)*LM*DH;
#pragma unroll
  for(int mt=0;mt<2;mt++){
#pragma unroll
    for(int nt=0;nt<4;nt++){
      int cg=n_off+8*nt+2*lr;
#pragma unroll
      for(int half=0;half<2;half++){
        int r=row0+m_off+16*mt+lq+half*8;
        size_t off=(size_t)r*DH+cg;
        Cp[off]  =c[mt][nt][half*2];
        Cp[off+1]=c[mt][nt][half*2+1];
      }
    }
  }
}

// ------------- LayerNorm + front-pad to NPD rows ---------------------------
__global__ __launch_bounds__(256) void ln_pad_k(const float* __restrict__ hin,
    const float* __restrict__ g, const float* __restrict__ b)
{
  int row=blockIdx.x, t=threadIdx.x;
  float* out=g_xp+(size_t)row*512;
  if(row<255){ out[t]=0.f; out[t+256]=0.f; return; }
  __shared__ float red[32];
  const float* x=hin+(size_t)(row-255)*512;
  float v0=x[t], v1=x[t+256];
  float mean=bSum(v0+v1,red)*(1.f/512.f);
  float d0=v0-mean, d1=v1-mean;
  float var=bSum(d0*d0+d1*d1,red)*(1.f/512.f);
  float rs=1.f/sqrtf(var+1e-5f);
  out[t]=d0*rs*g[t]+b[t];
  out[t+256]=d1*rs*g[t+256]+b[t+256];
}

// ------------- landmarks: mean of 65 consecutive rows ----------------------
__global__ void landmarks_k()
{
  int m=blockIdx.x, h=blockIdx.y, d=threadIdx.x;
  const float* base=g_qkv+(size_t)(m*65)*1536+h*64+d;
  float sq=0.f, sk=0.f;
  for(int j=0;j<65;j++){ sq+=base[(size_t)j*1536]; sk+=base[(size_t)j*1536+512]; }
  g_ql[(h*LM+m)*DH+d]=sq*(0.125f/65.f);
  g_kl[(h*LM+m)*DH+d]=sk*(1.f/65.f);
}

// ------------- a2 = softmax(q_l @ k_l^T) -----------------------------------
__global__ __launch_bounds__(256) void a2_k()
{
  int i=blockIdx.x, h=blockIdx.y, j=threadIdx.x;
  __shared__ float q[DH]; __shared__ float red[32];
  if(j<DH) q[j]=g_ql[(h*LM+i)*DH+j];
  __syncthreads();
  const float* kr=&g_kl[(h*LM+j)*DH];
  float s=0.f;
#pragma unroll
  for(int d=0;d<DH;d++) s+=q[d]*kr[d];
  float mx=bMax(s,red);
  float p=expf(s-mx);
  float ss=bSum(p,red);
  g_a2[((size_t)(h*LM+i))*LM+j]=p/ss;
}

// ------------- pinv init: row/col-sum maxima, denom, z0 = a2^T/den ---------
__global__ __launch_bounds__(256) void sums_k()
{
  int h=blockIdx.x, t=threadIdx.x;
  __shared__ float red[32];
  const float* a=g_a2+(size_t)h*LM*LM;
  float rs=0.f, cs=0.f;
  for(int j=0;j<LM;j++){ rs+=fabsf(a[(size_t)t*LM+j]); cs+=fabsf(a[(size_t)j*LM+t]); }
  float rm=bMax(rs,red), cm=bMax(cs,red);
  if(t==0){ g_mx[h]=rm; g_mx[NH+h]=cm; }
}
__global__ void denom_k()
{
  int t=threadIdx.x;
  float rm=(t<NH)?g_mx[t]:-3.4e38f, cm=(t<NH)?g_mx[NH+t]:-3.4e38f;
  rm=wMax(rm); cm=wMax(cm);
  if(t==0) g_den=rm*cm;
}
__global__ __launch_bounds__(256) void zinit_k()
{
  int i=blockIdx.x, h=blockIdx.y, j=threadIdx.x;
  float inv=1.f/g_den;
  g_z[((size_t)h*LM+i)*LM+j]=g_a2[((size_t)h*LM+j)*LM+i]*inv;
}

// ------------- a3 row stats: single-pass online (max, 1/sum) ---------------
__global__ __launch_bounds__(256) void a3stat_k()
{
  int i=blockIdx.x, h=blockIdx.y, t=threadIdx.x;
  __shared__ float redm[64];
  const float* p=g_a3+((size_t)h*LM+i)*NPD;
  float m=-3.4e38f, s=0.f;
  for(int j=t;j<NPD;j+=256){
    float x=p[j];
    float nm=fmaxf(m,x);
    s=s*__expf(m-nm)+__expf(x-nm);
    m=nm;
  }
#pragma unroll
  for(int o=16;o>0;o>>=1){
    float om=__shfl_xor_sync(0xffffffffu,m,o);
    float os=__shfl_xor_sync(0xffffffffu,s,o);
    float nm=fmaxf(m,om);
    s=s*__expf(m-nm)+os*__expf(om-nm);
    m=nm;
  }
  int w=t>>5, l=t&31;
  if(l==0){ redm[w]=m; redm[32+w]=s; }
  __syncthreads();
  if(t==0){
    float M=redm[0], S=redm[32];
#pragma unroll
    for(int k=1;k<8;k++){
      float om=redm[k], os=redm[32+k];
      float nm=fmaxf(M,om);
      S=S*__expf(M-nm)+os*__expf(om-nm);
      M=nm;
    }
    g_sm[h*LM+i]=make_float2(M,1.f/S);
  }
}

__global__ void a3vred_k()
{
  int idx=blockIdx.x*256+threadIdx.x;
  float s=0.f;
  for(int kc=0;kc<KC;kc++) s+=g_p3[(size_t)kc*NH*LM*DH+idx];
  g_o3[idx]=s;
}

// ------------- fused a1@W2 + depthwise-33 residual (2 rows/iter) -----------
#define CH 128
__global__ __launch_bounds__(256) void a1res_k(const float* __restrict__ rw,
                                               int row_start, int row_cnt)
{
  extern __shared__ float sm[];
  float* kls=sm;               // 256*65 = 16640
  float* w2s=sm+16640;         // 16640
  float* vs =sm+33280;         // 160*64 = 10240 -> 43520
  float* rws=sm+43520;         // 33 (pad 40)    -> 43560
  float* qs =sm+43560;         // 128            -> 43688
  float* ps =sm+43688;         // 256            -> 43944
  float* ps2=sm+43944;         // 256            -> 44200
  float* op0=sm+44200;         // 256            -> 44456
  float* op1=sm+44456;         // 256            -> 44712
  float* red=sm+44712;         // 64             -> 44776
  int t=threadIdx.x, h=blockIdx.y;
  int i0=row_start+blockIdx.x*CH;
  int rend=row_start+row_cnt;
  for(int idx=t;idx<LM*DH;idx+=256){
    int j=idx>>6, d=idx&63;
    kls[j*65+d]=g_kl[((size_t)h*LM+j)*DH+d];
    w2s[j*65+d]=g_w2[((size_t)h*LM+j)*DH+d];
  }
  for(int idx=t;idx<160*64;idx+=256){
    int rr=idx>>6, d=idx&63, gr=i0-16+rr;
    vs[rr*64+d]=(gr>=0&&gr<NPD)?g_qkv[(size_t)gr*1536+1024+h*64+d]:0.f;
  }
  if(t<33) rws[t]=rw[h*33+t];
  __syncthreads();
  for(int ii=0;ii<CH;ii+=2){
    int i=i0+ii;
    if(i>=rend) break;
    bool v1=(i+1<rend);
    if(t<64) qs[t]=g_qkv[(size_t)i*1536+h*64+t]*0.125f;
    else if(t<128) qs[t]=v1?g_qkv[(size_t)(i+1)*1536+h*64+(t-64)]*0.125f:0.f;
    __syncthreads();
    float l0=0.f, l1=0.f;
#pragma unroll
    for(int d=0;d<DH;d++){
      float kv=kls[t*65+d];
      l0+=qs[d]*kv;
      l1+=qs[64+d]*kv;
    }
    float2 M=bMax2(l0,v1?l1:l0,red);
    float p0=__expf(l0-M.x), p1=__expf(l1-M.y);
    float2 S=bSum2(p0,p1,red);
    ps[t]=p0/S.x; ps2[t]=p1/S.y;
    __syncthreads();
    {
      int g=t>>6, d=t&63;
      float o0=0.f, o1=0.f;
#pragma unroll 8
      for(int j=g*64;j<g*64+64;j++){
        float w=w2s[j*65+d];
        o0+=ps[j]*w;
        o1+=ps2[j]*w;
      }
      op0[g*64+d]=o0;
      op1[g*64+d]=o1;
    }
    __syncthreads();
    if(t<128){
      int rr=t>>6, d=t&63;
      if(rr==0||v1){
        float* opp=rr?op1:op0;
        float o=opp[d]+opp[64+d]+opp[128+d]+opp[192+d];
#pragma unroll
        for(int tap=0;tap<33;tap++) o+=vs[(ii+rr+tap)*64+d]*rws[tap];
        g_ao[(size_t)(i+rr-255)*512+h*64+d]=o;
      }
    }
    __syncthreads();
  }
}

// ------------- PPEG: cf + dw7 + dw5 + dw3 ----------------------------------
__global__ __launch_bounds__(256) void ppeg_k(
    const float* __restrict__ w7, const float* __restrict__ b7,
    const float* __restrict__ w5, const float* __restrict__ b5,
    const float* __restrict__ w3, const float* __restrict__ b3)
{
  extern __shared__ float sm[];
  float* sin_=sm;          // 22*22*65
  float* w7s=sm+31460;     // 49*64
  float* w5s=sm+34596;     // 25*64
  float* w3s=sm+36196;     // 9*64
  float* bs =sm+36772;     // 64
  int t=threadIdx.x;
  int ty0=(blockIdx.x>>3)*16, tx0=(blockIdx.x&7)*16;
  int cbase=blockIdx.y*64;
  for(int idx=t;idx<22*22*64;idx+=256){
    int c=idx&63, pp=idx>>6, yy=pp/22, xx=pp%22;
    int gy=ty0+yy-3, gx=tx0+xx-3;
    sin_[(yy*22+xx)*65+c]=(gy>=0&&gy<128&&gx>=0&&gx<128)?
        g_h[(size_t)(1+gy*128+gx)*512+cbase+c]:0.f;
  }
  for(int idx=t;idx<49*64;idx+=256){ int c=idx&63,k=idx>>6; w7s[k*64+c]=w7[(cbase+c)*49+k]; }
  for(int idx=t;idx<25*64;idx+=256){ int c=idx&63,k=idx>>6; w5s[k*64+c]=w5[(cbase+c)*25+k]; }
  for(int idx=t;idx<9*64;idx+=256){ int c=idx&63,k=idx>>6; w3s[k*64+c]=w3[(cbase+c)*9+k]; }
  if(t<64) bs[t]=b7[cbase+t]+b5[cbase+t]+b3[cbase+t];
  __syncthreads();
  int py=t>>4, px=t&15;
  for(int c=0;c<64;c++){
    float acc=sin_[((py+3)*22+px+3)*65+c]+bs[c];
#pragma unroll
    for(int ky=0;ky<7;ky++)
#pragma unroll
      for(int kx=0;kx<7;kx++)
        acc+=sin_[((py+ky)*22+px+kx)*65+c]*w7s[(ky*7+kx)*64+c];
#pragma unroll
    for(int ky=0;ky<5;ky++)
#pragma unroll
      for(int kx=0;kx<5;kx++)
        acc+=sin_[((py+1+ky)*22+px+1+kx)*65+c]*w5s[(ky*5+kx)*64+c];
#pragma unroll
    for(int ky=0;ky<3;ky++)
#pragma unroll
      for(int kx=0;kx<3;kx++)
        acc+=sin_[((py+2+ky)*22+px+2+kx)*65+c]*w3s[(ky*3+kx)*64+c];
    g_h2[(size_t)(1+(ty0+py)*128+tx0+px)*512+cbase+c]=acc;
  }
}

// ------------- small helpers -----------------------------------------------
__global__ void clscopy_k(const float* __restrict__ cls){ g_h[threadIdx.x]=cls[threadIdx.x]; }
__global__ void row0cpy_k(){ g_h2[threadIdx.x]=g_h[threadIdx.x]; }

// ------------- final: cls out-proj + residual + LN + fc2 -------------------
__global__ __launch_bounds__(512) void final_k(
    const float* __restrict__ outw, const float* __restrict__ outb,
    const float* __restrict__ ng, const float* __restrict__ nb,
    const float* __restrict__ fw, const float* __restrict__ fb,
    float* __restrict__ out)
{
  __shared__ float sh[512]; __shared__ float red[32];
  int t=threadIdx.x;
  float acc=0.f;
  for(int k=0;k<512;k++) acc+=g_ao[k]*outw[(size_t)k*512+t];
  float row=g_h2[t]+acc+outb[t];
  float mean=bSum(row,red)*(1.f/512.f);
  float d=row-mean;
  float var=bSum(d*d,red)*(1.f/512.f);
  float y=d*(1.f/sqrtf(var+1e-5f))*ng[t]+nb[t];
  sh[t]=y;
  __syncthreads();
  if(t<4){
    float o=fb[t];
    for(int c=0;c<512;c++) o+=sh[c]*fw[c*4+t];
    out[t]=o;
  }
}

// ---------------- host orchestration ----------------------------------------
static void* sym(const void* s){ void* p=nullptr; cudaGetSymbolAddress(&p,s); return p; }

static void attn_layer(const float* hin, const float* ng, const float* nbi,
                       const float* qkvw, const float* outw, const float* outb,
                       const float* resw, int layer2,
                       float* ph, float* pxp, float* pqkv, float* pao,
                       float* pz, float* po3, float* pw2,
                       size_t a1sm)
{
  ln_pad_k<<<NPD,256>>>(hin,ng,nbi);
  gemm_tf32<0><<<dim3(1536/128,130),256>>>(pxp,qkvw,pqkv,nullptr,NPD,1536,512);
  landmarks_k<<<dim3(LM,NH),64>>>();
  a2_k<<<dim3(LM,NH),256>>>();
  sums_k<<<NH,256>>>();
  denom_k<<<1,32>>>();
  zinit_k<<<dim3(LM,NH),256>>>();
  nwt_k<<<NWT_BLOCKS,128>>>();                 // 6 Newton iters, final z in g_z
  qkT_t<<<dim3(130,2,NH),256>>>();
  a3stat_k<<<dim3(LM,NH),256>>>();
  a3v_t<<<dim3(4,NH,KC),128>>>();
  a3vred_k<<<NH*LM*DH/256,256>>>();
  g256t<<<dim3(1,4,NH),128>>>(pz,po3,pw2,64,1.f,0.f);
  if(!layer2){
    a1res_k<<<dim3((NR+CH-1)/CH,NH),256,a1sm>>>(resw,255,NR);
    gemm_tf32<2><<<dim3(4,(NR+127)/128),256>>>(pao,outw,ph,outb,NR,512,512);
  }else{
    a1res_k<<<dim3(1,NH),256,a1sm>>>(resw,255,1);
  }
}

extern "C" void kernel_launch(void* const* d_in, const int* in_sizes, int n_in,
                              void* d_out, int out_size)
{
  const float* x     =(const float*)d_in[0];
  const float* fc1w  =(const float*)d_in[1];
  const float* fc1b  =(const float*)d_in[2];
  const float* cls   =(const float*)d_in[3];
  const float* l1ng  =(const float*)d_in[4];
  const float* l1nb  =(const float*)d_in[5];
  const float* l1qkv =(const float*)d_in[6];
  const float* l1ow  =(const float*)d_in[7];
  const float* l1ob  =(const float*)d_in[8];
  const float* l1rw  =(const float*)d_in[9];

  int ppegBase, l2Base;
  if (in_sizes[10] == 25088) { ppegBase = 10; l2Base = 16; }
  else                       { l2Base = 10; ppegBase = 16; }

  const float* w7   =(const float*)d_in[ppegBase+0];
  const float* b7   =(const float*)d_in[ppegBase+1];
  const float* w5   =(const float*)d_in[ppegBase+2];
  const float* b5   =(const float*)d_in[ppegBase+3];
  const float* w3   =(const float*)d_in[ppegBase+4];
  const float* b3   =(const float*)d_in[ppegBase+5];
  const float* l2ng =(const float*)d_in[l2Base+0];
  const float* l2nb =(const float*)d_in[l2Base+1];
  const float* l2qkv=(const float*)d_in[l2Base+2];
  const float* l2ow =(const float*)d_in[l2Base+3];
  const float* l2ob =(const float*)d_in[l2Base+4];
  const float* l2rw =(const float*)d_in[l2Base+5];
  const float* nng  =(const float*)d_in[22];
  const float* nnb  =(const float*)d_in[23];
  const float* fc2w =(const float*)d_in[24];
  const float* fc2b =(const float*)d_in[25];
  float* out=(float*)d_out;

  float* ph  =(float*)sym(g_h);
  float* ph2 =(float*)sym(g_h2);
  float* pxp =(float*)sym(g_xp);
  float* pqkv=(float*)sym(g_qkv);
  float* pao =(float*)sym(g_ao);
  float* pz  =(float*)sym(g_z);
  float* po3 =(float*)sym(g_o3);
  float* pw2 =(float*)sym(g_w2);

  const size_t A1SM=44776*sizeof(float);   // ~179.1 KB
  const size_t PPSM=36836*sizeof(float);   // ~147.3 KB
  cudaFuncSetAttribute(a1res_k,cudaFuncAttributeMaxDynamicSharedMemorySize,(int)A1SM);
  cudaFuncSetAttribute(ppeg_k, cudaFuncAttributeMaxDynamicSharedMemorySize,(int)PPSM);

  // fc1 + cls
  gemm_tf32<1><<<dim3(4,128),256>>>(x,fc1w,ph+512,fc1b,16384,512,1024);
  clscopy_k<<<1,512>>>(cls);
  // layer 1
  attn_layer(ph,l1ng,l1nb,l1qkv,l1ow,l1ob,l1rw,0,
             ph,pxp,pqkv,pao,pz,po3,pw2,A1SM);
  // PPEG
  row0cpy_k<<<1,512>>>();
  ppeg_k<<<dim3(64,8),256,PPSM>>>(w7,b7,w5,b5,w3,b3);
  // layer 2 (only cls row of attention output needed)
  attn_layer(ph2,l2ng,l2nb,l2qkv,l2ow,l2ob,l2rw,1,
             ph2,pxp,pqkv,pao,pz,po3,pw2,A1SM);
  // final: out-proj row + residual + LN + fc2
  final_k<<<1,512>>>(l2ow,l2ob,nng,nnb,fc2w,fc2b,out);
}

// round 16
// speedup vs baseline: 1.6855x; 1.0486x over previous
#include <cuda_runtime.h>
#include <math.h>

#define NR  16385
#define NPD 16640
#define NH  8
#define DH  64
#define LM  256
#define KC  26          // key chunks for flash a3 (26*640 = 16640)
#define CHK 640
#define NSUB 10         // 640/64 sub-tiles

// ---------------- scratch (device globals, allocation-free) ----------------
__device__ float g_h  [NR  * 512];
__device__ float g_h2 [NR  * 512];
__device__ float g_xp [NPD * 512];
__device__ float g_qkv[NPD * 1536];
__device__ float g_ao [NR  * 512];
__device__ float g_ql [NH * LM * DH];
__device__ float g_kl [NH * LM * DH];
__device__ float g_a2 [NH * LM * LM];
__device__ float g_z  [NH * LM * LM];
__device__ float g_zb [NH * LM * LM];
__device__ float g_az [NH * LM * LM];
__device__ float g_t1 [NH * LM * LM];
__device__ float g_t2 [NH * LM * LM];
__device__ float g_p3 [KC * NH * LM * DH];
__device__ float2 g_ms2[KC * NH * LM];
__device__ float g_o3 [NH * LM * DH];
__device__ float g_w2 [NH * LM * DH];
__device__ float g_mx [2 * NH];
__device__ float g_den;
__device__ unsigned g_cnt;   // zero-init; self-resetting barrier counter
__device__ unsigned g_phs;   // monotone phase flag

// ---------------- reductions ----------------
__device__ __forceinline__ float wSum(float v){
#pragma unroll
  for(int o=16;o>0;o>>=1) v += __shfl_xor_sync(0xffffffffu,v,o);
  return v;
}
__device__ __forceinline__ float wMax(float v){
#pragma unroll
  for(int o=16;o>0;o>>=1) v = fmaxf(v,__shfl_xor_sync(0xffffffffu,v,o));
  return v;
}
__device__ __forceinline__ float bSum(float v, float* red){
  int w=threadIdx.x>>5, l=threadIdx.x&31, nw=(blockDim.x+31)>>5;
  v=wSum(v); if(l==0) red[w]=v; __syncthreads();
  if(w==0){ float r=(l<nw)?red[l]:0.f; r=wSum(r); if(l==0) red[0]=r; }
  __syncthreads(); float r=red[0]; __syncthreads(); return r;
}
__device__ __forceinline__ float bMax(float v, float* red){
  int w=threadIdx.x>>5, l=threadIdx.x&31, nw=(blockDim.x+31)>>5;
  v=wMax(v); if(l==0) red[w]=v; __syncthreads();
  if(w==0){ float r=(l<nw)?red[l]:-3.4e38f; r=wMax(r); if(l==0) red[0]=r; }
  __syncthreads(); float r=red[0]; __syncthreads(); return r;
}
__device__ __forceinline__ float2 bMax2(float a, float b, float* red){
  int w=threadIdx.x>>5, l=threadIdx.x&31;
#pragma unroll
  for(int o=16;o>0;o>>=1){
    a=fmaxf(a,__shfl_xor_sync(0xffffffffu,a,o));
    b=fmaxf(b,__shfl_xor_sync(0xffffffffu,b,o));
  }
  if(l==0){ red[w]=a; red[32+w]=b; }
  __syncthreads();
  if(w==0){
    float x=(l<8)?red[l]:-3.4e38f;
    float y=(l<8)?red[32+l]:-3.4e38f;
#pragma unroll
    for(int o=4;o>0;o>>=1){
      x=fmaxf(x,__shfl_xor_sync(0xffffffffu,x,o));
      y=fmaxf(y,__shfl_xor_sync(0xffffffffu,y,o));
    }
    if(l==0){ red[0]=x; red[32]=y; }
  }
  __syncthreads();
  float2 r=make_float2(red[0],red[32]);
  __syncthreads();
  return r;
}
__device__ __forceinline__ float2 bSum2(float a, float b, float* red){
  int w=threadIdx.x>>5, l=threadIdx.x&31;
#pragma unroll
  for(int o=16;o>0;o>>=1){
    a+=__shfl_xor_sync(0xffffffffu,a,o);
    b+=__shfl_xor_sync(0xffffffffu,b,o);
  }
  if(l==0){ red[w]=a; red[32+w]=b; }
  __syncthreads();
  if(w==0){
    float x=(l<8)?red[l]:0.f;
    float y=(l<8)?red[32+l]:0.f;
#pragma unroll
    for(int o=4;o>0;o>>=1){
      x+=__shfl_xor_sync(0xffffffffu,x,o);
      y+=__shfl_xor_sync(0xffffffffu,y,o);
    }
    if(l==0){ red[0]=x; red[32]=y; }
  }
  __syncthreads();
  float2 r=make_float2(red[0],red[32]);
  __syncthreads();
  return r;
}

// ---------------- TF32 mma helpers ----------------
__device__ __forceinline__ unsigned f2tf(float f){
  unsigned u; asm("cvt.rna.tf32.f32 %0, %1;" : "=r"(u) : "f"(f)); return u;
}
__device__ __forceinline__ void mma8(float* c, const unsigned* a, const unsigned* b){
  asm volatile("mma.sync.aligned.m16n8k8.row.col.f32.tf32.tf32.f32 "
    "{%0,%1,%2,%3}, {%4,%5,%6,%7}, {%8,%9}, {%0,%1,%2,%3};"
    : "+f"(c[0]),"+f"(c[1]),"+f"(c[2]),"+f"(c[3])
    : "r"(a[0]),"r"(a[1]),"r"(a[2]),"r"(a[3]), "r"(b[0]),"r"(b[1]));
}

// ---------------- TF32 GEMM (double-buffered): C=A@B (+epilogue) -----------
template<int MODE>
__global__ __launch_bounds__(256) void gemm_tf32(
    const float* __restrict__ A, const float* __restrict__ B, float* __restrict__ Cd,
    const float* __restrict__ bias, int M, int N, int K)
{
  __shared__ unsigned As[2][16*136];
  __shared__ unsigned Bs[2][16*136];
  int t=threadIdx.x, lane=t&31, wid=t>>5;
  int row0=blockIdx.y*128, col0=blockIdx.x*128;
  int m_off=32*(wid&3), n_off=64*(wid>>2);
  int lq=lane>>2, lr=lane&3;
  int ar=t>>1, akq=(t&1)*8;
  int bkr=t>>4, bnc=(t&15)*8;
  bool aval=(row0+ar)<M;
  const float* Ap=A+(size_t)(row0+ar)*K;
  const float* Bp=B+(size_t)bkr*N+col0+bnc;

  float c[2][8][4];
#pragma unroll
  for(int mt=0;mt<2;mt++)
#pragma unroll
    for(int nt=0;nt<8;nt++)
#pragma unroll
      for(int i=0;i<4;i++) c[mt][nt][i]=0.f;

  float4 xa0,xa1,yb0,yb1;
  xa0=make_float4(0,0,0,0); xa1=xa0;
  if(aval){ xa0=*(const float4*)(Ap+akq); xa1=*(const float4*)(Ap+akq+4); }
  yb0=*(const float4*)(Bp); yb1=*(const float4*)(Bp+4);
  {
    unsigned* as=As[0]; unsigned* bs=Bs[0];
    as[(akq+0)*136+ar]=f2tf(xa0.x); as[(akq+1)*136+ar]=f2tf(xa0.y);
    as[(akq+2)*136+ar]=f2tf(xa0.z); as[(akq+3)*136+ar]=f2tf(xa0.w);
    as[(akq+4)*136+ar]=f2tf(xa1.x); as[(akq+5)*136+ar]=f2tf(xa1.y);
    as[(akq+6)*136+ar]=f2tf(xa1.z); as[(akq+7)*136+ar]=f2tf(xa1.w);
    *(uint4*)&bs[bkr*136+bnc]  =make_uint4(f2tf(yb0.x),f2tf(yb0.y),f2tf(yb0.z),f2tf(yb0.w));
    *(uint4*)&bs[bkr*136+bnc+4]=make_uint4(f2tf(yb1.x),f2tf(yb1.y),f2tf(yb1.z),f2tf(yb1.w));
  }
  __syncthreads();
  int nb=0;
  for(int k0=16;k0<K+16;k0+=16){
    bool more=(k0<K);
    if(more){
      xa0=make_float4(0,0,0,0); xa1=xa0;
      if(aval){ xa0=*(const float4*)(Ap+k0+akq); xa1=*(const float4*)(Ap+k0+akq+4); }
      yb0=*(const float4*)(Bp+(size_t)k0*N); yb1=*(const float4*)(Bp+(size_t)k0*N+4);
    }
    {
      const unsigned* as=As[nb]; const unsigned* bs=Bs[nb];
#pragma unroll
      for(int kk=0;kk<2;kk++){
        int ks=kk*8;
        unsigned a[2][4], b[8][2];
#pragma unroll
        for(int mt=0;mt<2;mt++){
          int m=m_off+16*mt+lq;
          a[mt][0]=as[(ks+lr)*136+m];
          a[mt][1]=as[(ks+lr)*136+m+8];
          a[mt][2]=as[(ks+4+lr)*136+m];
          a[mt][3]=as[(ks+4+lr)*136+m+8];
        }
#pragma unroll
        for(int nt=0;nt<8;nt++){
          int n=n_off+8*nt+lq;
          b[nt][0]=bs[(ks+lr)*136+n];
          b[nt][1]=bs[(ks+4+lr)*136+n];
        }
#pragma unroll
        for(int mt=0;mt<2;mt++)
#pragma unroll
          for(int nt=0;nt<8;nt++) mma8(c[mt][nt],a[mt],b[nt]);
      }
    }
    if(more){
      unsigned* as=As[nb^1]; unsigned* bs=Bs[nb^1];
      as[(akq+0)*136+ar]=f2tf(xa0.x); as[(akq+1)*136+ar]=f2tf(xa0.y);
      as[(akq+2)*136+ar]=f2tf(xa0.z); as[(akq+3)*136+ar]=f2tf(xa0.w);
      as[(akq+4)*136+ar]=f2tf(xa1.x); as[(akq+5)*136+ar]=f2tf(xa1.y);
      as[(akq+6)*136+ar]=f2tf(xa1.z); as[(akq+7)*136+ar]=f2tf(xa1.w);
      *(uint4*)&bs[bkr*136+bnc]  =make_uint4(f2tf(yb0.x),f2tf(yb0.y),f2tf(yb0.z),f2tf(yb0.w));
      *(uint4*)&bs[bkr*136+bnc+4]=make_uint4(f2tf(yb1.x),f2tf(yb1.y),f2tf(yb1.z),f2tf(yb1.w));
      __syncthreads();
      nb^=1;
    }
  }
#pragma unroll
  for(int mt=0;mt<2;mt++){
    int rA=row0+m_off+16*mt+lq;
    int rB=rA+8;
#pragma unroll
    for(int nt=0;nt<8;nt++){
      int cg=col0+n_off+8*nt+2*lr;
#pragma unroll
      for(int half=0;half<2;half++){
        int r=half?rB:rA;
        if(r<M){
          size_t off=(size_t)r*N+cg;
          float v0=c[mt][nt][half*2], v1=c[mt][nt][half*2+1];
          if(MODE==1){
            v0+=bias[cg];   v0=v0>0.f?v0:0.f;
            v1+=bias[cg+1]; v1=v1>0.f?v1:0.f;
            Cd[off]=v0; Cd[off+1]=v1;
          }else if(MODE==2){
            Cd[off]  +=v0+bias[cg];
            Cd[off+1]+=v1+bias[cg+1];
          }else{
            Cd[off]=v0; Cd[off+1]=v1;
          }
        }
      }
    }
  }
}

// ---------------- fused flash a3: o3 partials = softmax(q_l@k^T)@v ---------
// grid (2 row-halves, NH, KC), 128 threads (4 warps, 32 rows/warp)
__global__ __launch_bounds__(128) void a3f_k()
{
  extern __shared__ unsigned smu[];
  unsigned* Qs=smu;                 // 128*68 = 8704
  unsigned* Ks=smu+8704;            // 64*68  = 4352
  unsigned* Vs=smu+13056;           // 64*72  = 4608
  unsigned* Ps=smu+17664;           // 128*68 = 8704  -> total 26368 u
  int t=threadIdx.x, lane=t&31, wid=t>>5;
  int r0=blockIdx.x*128, h=blockIdx.y, kc=blockIdx.z;
  int key0=kc*CHK;
  int m_off=32*wid;
  int lq=lane>>2, lr=lane&3;

  // load Q tile (rows r0..r0+127), row t
  {
    const float* qp=g_ql+((size_t)h*LM + r0+t)*DH;
#pragma unroll
    for(int d=0;d<64;d+=4){
      float4 v=*(const float4*)(qp+d);
      *(uint4*)&Qs[t*68+d]=make_uint4(f2tf(v.x),f2tf(v.y),f2tf(v.z),f2tf(v.w));
    }
  }

  float c2[2][8][4];
#pragma unroll
  for(int mt=0;mt<2;mt++)
#pragma unroll
    for(int nt=0;nt<8;nt++)
#pragma unroll
      for(int i=0;i<4;i++) c2[mt][nt][i]=0.f;
  float rm[2][2]={{-3.4e38f,-3.4e38f},{-3.4e38f,-3.4e38f}};
  float rs[2][2]={{0.f,0.f},{0.f,0.f}};

  for(int sub=0;sub<NSUB;sub++){
    __syncthreads();
    // load K,V sub-tile: 64 keys x 64 dh  (smem row = krow, gmem row = gkey)
    {
      int krow=t>>1;                       // 0..63 (smem row)
      int gkey=key0+sub*64+krow;           // global key row
      int ch=(t&1)*32;
      const float* kp=g_qkv+(size_t)gkey*1536+512+h*64+ch;
      const float* vp=kp+512;
#pragma unroll
      for(int d=0;d<32;d+=4){
        float4 kv=*(const float4*)(kp+d);
        *(uint4*)&Ks[krow*68+ch+d]=make_uint4(f2tf(kv.x),f2tf(kv.y),f2tf(kv.z),f2tf(kv.w));
        float4 vv=*(const float4*)(vp+d);
        *(uint4*)&Vs[krow*72+ch+d]=make_uint4(f2tf(vv.x),f2tf(vv.y),f2tf(vv.z),f2tf(vv.w));
      }
    }
    __syncthreads();
    // gemm1: S = Q(128x64) @ K^T(64keys)
    float c1[2][8][4];
#pragma unroll
    for(int mt=0;mt<2;mt++)
#pragma unroll
      for(int nt=0;nt<8;nt++)
#pragma unroll
        for(int i=0;i<4;i++) c1[mt][nt][i]=0.f;
#pragma unroll
    for(int ks=0;ks<64;ks+=8){
      unsigned a[2][4], b[8][2];
#pragma unroll
      for(int mt=0;mt<2;mt++){
        int m=m_off+16*mt+lq;
        a[mt][0]=Qs[m*68+ks+lr];
        a[mt][1]=Qs[(m+8)*68+ks+lr];
        a[mt][2]=Qs[m*68+ks+4+lr];
        a[mt][3]=Qs[(m+8)*68+ks+4+lr];
      }
#pragma unroll
      for(int nt=0;nt<8;nt++){
        int n=8*nt+lq;
        b[nt][0]=Ks[n*68+ks+lr];
        b[nt][1]=Ks[n*68+ks+4+lr];
      }
#pragma unroll
      for(int mt=0;mt<2;mt++)
#pragma unroll
        for(int nt=0;nt<8;nt++) mma8(c1[mt][nt],a[mt],b[nt]);
    }
    // online softmax (register-resident stats; redundant across lr lanes)
#pragma unroll
    for(int mt=0;mt<2;mt++){
#pragma unroll
      for(int half=0;half<2;half++){
        float v=-3.4e38f;
#pragma unroll
        for(int nt=0;nt<8;nt++)
          v=fmaxf(v,fmaxf(c1[mt][nt][half*2],c1[mt][nt][half*2+1]));
        v=fmaxf(v,__shfl_xor_sync(0xffffffffu,v,1));
        v=fmaxf(v,__shfl_xor_sync(0xffffffffu,v,2));
        float mo=rm[mt][half];
        float mn=fmaxf(mo,v);
        float f=__expf(mo-mn);
        int row=m_off+16*mt+lq+8*half;
        float psum=0.f;
#pragma unroll
        for(int nt=0;nt<8;nt++){
          float p0=__expf(c1[mt][nt][half*2]-mn);
          float p1=__expf(c1[mt][nt][half*2+1]-mn);
          psum+=p0+p1;
          Ps[row*68+8*nt+2*lr]  =f2tf(p0);
          Ps[row*68+8*nt+2*lr+1]=f2tf(p1);
        }
        psum+=__shfl_xor_sync(0xffffffffu,psum,1);
        psum+=__shfl_xor_sync(0xffffffffu,psum,2);
        rs[mt][half]=rs[mt][half]*f+psum;
        rm[mt][half]=mn;
#pragma unroll
        for(int nt=0;nt<8;nt++){
          c2[mt][nt][half*2]  *=f;
          c2[mt][nt][half*2+1]*=f;
        }
      }
    }
    __syncwarp();
    // gemm2: c2 += P(128x64keys) @ V(64keys x 64dh)
#pragma unroll
    for(int ks=0;ks<64;ks+=8){
      unsigned a[2][4], b[8][2];
#pragma unroll
      for(int mt=0;mt<2;mt++){
        int m=m_off+16*mt+lq;
        a[mt][0]=Ps[m*68+ks+lr];
        a[mt][1]=Ps[(m+8)*68+ks+lr];
        a[mt][2]=Ps[m*68+ks+4+lr];
        a[mt][3]=Ps[(m+8)*68+ks+4+lr];
      }
#pragma unroll
      for(int nt=0;nt<8;nt++){
        int n=8*nt+lq;
        b[nt][0]=Vs[(ks+lr)*72+n];
        b[nt][1]=Vs[(ks+4+lr)*72+n];
      }
#pragma unroll
      for(int mt=0;mt<2;mt++)
#pragma unroll
        for(int nt=0;nt<8;nt++) mma8(c2[mt][nt],a[mt],b[nt]);
    }
  }
  // epilogue: unnormalized partial o + (m, s)
  float* Cp=g_p3+((size_t)(kc*NH+h))*LM*DH;
#pragma unroll
  for(int mt=0;mt<2;mt++)
#pragma unroll
    for(int nt=0;nt<8;nt++)
#pragma unroll
      for(int half=0;half<2;half++){
        int row=r0+m_off+16*mt+lq+8*half;
        Cp[(size_t)row*DH+8*nt+2*lr]  =c2[mt][nt][half*2];
        Cp[(size_t)row*DH+8*nt+2*lr+1]=c2[mt][nt][half*2+1];
      }
  if(lr==0){
#pragma unroll
    for(int mt=0;mt<2;mt++)
#pragma unroll
      for(int half=0;half<2;half++){
        int row=m_off+16*mt+lq+8*half;
        g_ms2[(kc*NH+h)*LM + r0+row]=make_float2(rm[mt][half],rs[mt][half]);
      }
  }
}

// ---------------- merge flash partials -> o3 --------------------------------
__global__ void a3mrg_k()   // grid (LM, NH), 64 threads
{
  int i=blockIdx.x, h=blockIdx.y, d=threadIdx.x;
  float M=-3.4e38f;
#pragma unroll 1
  for(int kc=0;kc<KC;kc++) M=fmaxf(M, g_ms2[(kc*NH+h)*LM+i].x);
  float S=0.f, acc=0.f;
#pragma unroll 1
  for(int kc=0;kc<KC;kc++){
    float2 ms=g_ms2[(kc*NH+h)*LM+i];
    float w=__expf(ms.x-M);
    S+=ms.y*w;
    acc+=g_p3[((size_t)(kc*NH+h))*LM*DH + (size_t)i*DH + d]*w;
  }
  g_o3[((size_t)h*LM+i)*DH+d]=acc/S;
}

// ---------------- TF32 64x64 step for Newton (double-buffered) --------------
__device__ __forceinline__ void gemm64_tc(unsigned* AsB, unsigned* BsB,
    const float* __restrict__ Ah, const float* __restrict__ Bh, float* __restrict__ Ch,
    float c0, float c1, int row0, int col0)
{
  int t=threadIdx.x, lane=t&31, wid=t>>5;
  int m_off=32*(wid&1), n_off=32*(wid>>1);
  int lq=lane>>2, lr=lane&3;
  int ar=t>>1, akq=(t&1)*8;
  int bkr=t>>3, bnc=(t&7)*8;
  const float* Ap=Ah+(size_t)(row0+ar)*256;
  const float* Bp=Bh+(size_t)bkr*256+col0+bnc;
  float c[2][4][4];
#pragma unroll
  for(int mt=0;mt<2;mt++)
#pragma unroll
    for(int nt=0;nt<4;nt++)
#pragma unroll
      for(int i=0;i<4;i++) c[mt][nt][i]=0.f;

  float4 x0,x1,y0,y1;
  x0=*(const float4*)(Ap+akq);
  x1=*(const float4*)(Ap+akq+4);
  y0=*(const float4*)(Bp);
  y1=*(const float4*)(Bp+4);
  {
    unsigned* as=AsB; unsigned* bs=BsB;
    as[(akq+0)*72+ar]=f2tf(x0.x); as[(akq+1)*72+ar]=f2tf(x0.y);
    as[(akq+2)*72+ar]=f2tf(x0.z); as[(akq+3)*72+ar]=f2tf(x0.w);
    as[(akq+4)*72+ar]=f2tf(x1.x); as[(akq+5)*72+ar]=f2tf(x1.y);
    as[(akq+6)*72+ar]=f2tf(x1.z); as[(akq+7)*72+ar]=f2tf(x1.w);
    *(uint4*)&bs[bkr*72+bnc]  =make_uint4(f2tf(y0.x),f2tf(y0.y),f2tf(y0.z),f2tf(y0.w));
    *(uint4*)&bs[bkr*72+bnc+4]=make_uint4(f2tf(y1.x),f2tf(y1.y),f2tf(y1.z),f2tf(y1.w));
  }
  __syncthreads();
  int nb=0;
  for(int k0=16;k0<256+16;k0+=16){
    bool more=(k0<256);
    if(more){
      x0=*(const float4*)(Ap+k0+akq);
      x1=*(const float4*)(Ap+k0+akq+4);
      y0=*(const float4*)(Bp+(size_t)k0*256);
      y1=*(const float4*)(Bp+(size_t)k0*256+4);
    }
    {
      const unsigned* as=AsB+nb*1152; const unsigned* bs=BsB+nb*1152;
#pragma unroll
      for(int kk=0;kk<2;kk++){
        int ks=kk*8;
        unsigned a[2][4], b[4][2];
#pragma unroll
        for(int mt=0;mt<2;mt++){
          int m=m_off+16*mt+lq;
          a[mt][0]=as[(ks+lr)*72+m];
          a[mt][1]=as[(ks+lr)*72+m+8];
          a[mt][2]=as[(ks+4+lr)*72+m];
          a[mt][3]=as[(ks+4+lr)*72+m+8];
        }
#pragma unroll
        for(int nt=0;nt<4;nt++){
          int n=n_off+8*nt+lq;
          b[nt][0]=bs[(ks+lr)*72+n];
          b[nt][1]=bs[(ks+4+lr)*72+n];
        }
#pragma unroll
        for(int mt=0;mt<2;mt++)
#pragma unroll
          for(int nt=0;nt<4;nt++) mma8(c[mt][nt],a[mt],b[nt]);
      }
    }
    if(more){
      unsigned* as=AsB+(nb^1)*1152; unsigned* bs=BsB+(nb^1)*1152;
      as[(akq+0)*72+ar]=f2tf(x0.x); as[(akq+1)*72+ar]=f2tf(x0.y);
      as[(akq+2)*72+ar]=f2tf(x0.z); as[(akq+3)*72+ar]=f2tf(x0.w);
      as[(akq+4)*72+ar]=f2tf(x1.x); as[(akq+5)*72+ar]=f2tf(x1.y);
      as[(akq+6)*72+ar]=f2tf(x1.z); as[(akq+7)*72+ar]=f2tf(x1.w);
      *(uint4*)&bs[bkr*72+bnc]  =make_uint4(f2tf(y0.x),f2tf(y0.y),f2tf(y0.z),f2tf(y0.w));
      *(uint4*)&bs[bkr*72+bnc+4]=make_uint4(f2tf(y1.x),f2tf(y1.y),f2tf(y1.z),f2tf(y1.w));
      __syncthreads();
      nb^=1;
    }
  }
#pragma unroll
  for(int mt=0;mt<2;mt++){
#pragma unroll
    for(int nt=0;nt<4;nt++){
      int cg=col0+n_off+8*nt+2*lr;
#pragma unroll
      for(int half=0;half<2;half++){
        int r=row0+m_off+16*mt+lq+half*8;
        size_t off=(size_t)r*256+cg;
        float v0=c0*c[mt][nt][half*2], v1=c0*c[mt][nt][half*2+1];
        if(c1!=0.f){
          v0+=c1*Ah[off];
          v1+=c1*Ah[off+1];
        }
        Ch[off]=v0; Ch[off+1]=v1;
      }
    }
  }
}

// ---------------- grid barrier (self-resetting; replay-safe) ----------------
#define NWT_BLOCKS 128
__device__ __forceinline__ void gridbar(unsigned &phase){
  __syncthreads();
  if(threadIdx.x==0){
    __threadfence();
    unsigned old=atomicInc(&g_cnt,NWT_BLOCKS-1u);
    unsigned target=phase+1u;
    if(old==NWT_BLOCKS-1u){
      atomicExch(&g_phs,target);
    }else{
      while(atomicAdd(&g_phs,0u)!=target) __nanosleep(64);
    }
    __threadfence();
  }
  __syncthreads();
  phase++;
}

// ---------------- persistent Newton pinv: 6 iters x 4 GEMMs -----------------
__global__ __launch_bounds__(128) void nwt_k()
{
  __shared__ unsigned As[2*16*72];
  __shared__ unsigned Bs[2*16*72];
  __shared__ unsigned ph0;
  int t=threadIdx.x;
  int h=blockIdx.x>>4, tile=blockIdx.x&15;
  int row0=(tile>>2)*64, col0=(tile&3)*64;
  if(t==0) ph0=atomicAdd(&g_phs,0u);
  __syncthreads();
  unsigned phase=ph0;
  size_t ho=(size_t)h*65536;
  float* z =g_z +ho;
  float* zn=g_zb+ho;
#pragma unroll 1
  for(int it=0;it<6;it++){
    gemm64_tc(As,Bs,g_a2+ho,z,        g_az+ho, 1.f,  0.f,  row0,col0); gridbar(phase);
    gemm64_tc(As,Bs,g_az+ho,g_az+ho,  g_t1+ho,-1.f,  7.f,  row0,col0); gridbar(phase);
    gemm64_tc(As,Bs,g_az+ho,g_t1+ho,  g_t2+ho,-1.f, 15.f,  row0,col0); gridbar(phase);
    gemm64_tc(As,Bs,z,      g_t2+ho,  zn,     -0.25f,3.25f,row0,col0); gridbar(phase);
    float* tmp=z; z=zn; zn=tmp;
  }
}

// ---------- batched 8-head TF32 GEMM (for w2 = z@o3, N=64) ------------------
__global__ __launch_bounds__(128) void g256t(
    const float* __restrict__ A, const float* __restrict__ B, float* __restrict__ Cd,
    int N, float c0, float c1)
{
  __shared__ unsigned As[16*72];
  __shared__ unsigned Bs[16*72];
  const float* Ah=A+(size_t)blockIdx.z*65536;
  const float* Bh=B+(size_t)blockIdx.z*256*N;
  float* Ch=Cd+(size_t)blockIdx.z*256*N;
  int t=threadIdx.x, lane=t&31, wid=t>>5;
  int row0=blockIdx.y*64, col0=blockIdx.x*64;
  int m_off=32*(wid&1), n_off=32*(wid>>1);
  int lq=lane>>2, lr=lane&3;
  int ar=t>>1, akq=(t&1)*8;
  int bkr=t>>3, bnc=(t&7)*8;
  const float* Ap=Ah+(size_t)(row0+ar)*256;
  const float* Bp=Bh+(size_t)bkr*N+col0+bnc;
  float c[2][4][4];
#pragma unroll
  for(int mt=0;mt<2;mt++)
#pragma unroll
    for(int nt=0;nt<4;nt++)
#pragma unroll
      for(int i=0;i<4;i++) c[mt][nt][i]=0.f;
  for(int k0=0;k0<256;k0+=16){
    float4 x0=*(const float4*)(Ap+k0+akq);
    float4 x1=*(const float4*)(Ap+k0+akq+4);
    float4 y0=*(const float4*)(Bp+(size_t)k0*N);
    float4 y1=*(const float4*)(Bp+(size_t)k0*N+4);
    As[(akq+0)*72+ar]=f2tf(x0.x); As[(akq+1)*72+ar]=f2tf(x0.y);
    As[(akq+2)*72+ar]=f2tf(x0.z); As[(akq+3)*72+ar]=f2tf(x0.w);
    As[(akq+4)*72+ar]=f2tf(x1.x); As[(akq+5)*72+ar]=f2tf(x1.y);
    As[(akq+6)*72+ar]=f2tf(x1.z); As[(akq+7)*72+ar]=f2tf(x1.w);
    *(uint4*)&Bs[bkr*72+bnc]  =make_uint4(f2tf(y0.x),f2tf(y0.y),f2tf(y0.z),f2tf(y0.w));
    *(uint4*)&Bs[bkr*72+bnc+4]=make_uint4(f2tf(y1.x),f2tf(y1.y),f2tf(y1.z),f2tf(y1.w));
    __syncthreads();
#pragma unroll
    for(int kk=0;kk<2;kk++){
      int ks=kk*8;
      unsigned a[2][4], b[4][2];
#pragma unroll
      for(int mt=0;mt<2;mt++){
        int m=m_off+16*mt+lq;
        a[mt][0]=As[(ks+lr)*72+m];
        a[mt][1]=As[(ks+lr)*72+m+8];
        a[mt][2]=As[(ks+4+lr)*72+m];
        a[mt][3]=As[(ks+4+lr)*72+m+8];
      }
#pragma unroll
      for(int nt=0;nt<4;nt++){
        int n=n_off+8*nt+lq;
        b[nt][0]=Bs[(ks+lr)*72+n];
        b[nt][1]=Bs[(ks+4+lr)*72+n];
      }
#pragma unroll
      for(int mt=0;mt<2;mt++)
#pragma unroll
        for(int nt=0;nt<4;nt++) mma8(c[mt][nt],a[mt],b[nt]);
    }
    __syncthreads();
  }
#pragma unroll
  for(int mt=0;mt<2;mt++){
#pragma unroll
    for(int nt=0;nt<4;nt++){
      int cg=col0+n_off+8*nt+2*lr;
#pragma unroll
      for(int half=0;half<2;half++){
        int r=row0+m_off+16*mt+lq+half*8;
        size_t off=(size_t)r*N+cg;
        float v0=c0*c[mt][nt][half*2], v1=c0*c[mt][nt][half*2+1];
        if(c1!=0.f){
          v0+=c1*Ah[(size_t)r*256+cg];
          v1+=c1*Ah[(size_t)r*256+cg+1];
        }
        Ch[off]=v0; Ch[off+1]=v1;
      }
    }
  }
}

// ------------- LayerNorm + front-pad to NPD rows ---------------------------
__global__ __launch_bounds__(256) void ln_pad_k(const float* __restrict__ hin,
    const float* __restrict__ g, const float* __restrict__ b)
{
  int row=blockIdx.x, t=threadIdx.x;
  float* out=g_xp+(size_t)row*512;
  if(row<255){ out[t]=0.f; out[t+256]=0.f; return; }
  __shared__ float red[32];
  const float* x=hin+(size_t)(row-255)*512;
  float v0=x[t], v1=x[t+256];
  float mean=bSum(v0+v1,red)*(1.f/512.f);
  float d0=v0-mean, d1=v1-mean;
  float var=bSum(d0*d0+d1*d1,red)*(1.f/512.f);
  float rs=1.f/sqrtf(var+1e-5f);
  out[t]=d0*rs*g[t]+b[t];
  out[t+256]=d1*rs*g[t+256]+b[t+256];
}

// ------------- landmarks: mean of 65 consecutive rows ----------------------
__global__ void landmarks_k()
{
  int m=blockIdx.x, h=blockIdx.y, d=threadIdx.x;
  const float* base=g_qkv+(size_t)(m*65)*1536+h*64+d;
  float sq=0.f, sk=0.f;
  for(int j=0;j<65;j++){ sq+=base[(size_t)j*1536]; sk+=base[(size_t)j*1536+512]; }
  g_ql[(h*LM+m)*DH+d]=sq*(0.125f/65.f);
  g_kl[(h*LM+m)*DH+d]=sk*(1.f/65.f);
}

// ------------- a2 = softmax(q_l @ k_l^T) -----------------------------------
__global__ __launch_bounds__(256) void a2_k()
{
  int i=blockIdx.x, h=blockIdx.y, j=threadIdx.x;
  __shared__ float q[DH]; __shared__ float red[32];
  if(j<DH) q[j]=g_ql[(h*LM+i)*DH+j];
  __syncthreads();
  const float* kr=&g_kl[(h*LM+j)*DH];
  float s=0.f;
#pragma unroll
  for(int d=0;d<DH;d++) s+=q[d]*kr[d];
  float mx=bMax(s,red);
  float p=expf(s-mx);
  float ss=bSum(p,red);
  g_a2[((size_t)(h*LM+i))*LM+j]=p/ss;
}

// ------------- pinv init: row/col-sum maxima, denom, z0 = a2^T/den ---------
__global__ __launch_bounds__(256) void sums_k()
{
  int h=blockIdx.x, t=threadIdx.x;
  __shared__ float red[32];
  const float* a=g_a2+(size_t)h*LM*LM;
  float rs=0.f, cs=0.f;
  for(int j=0;j<LM;j++){ rs+=fabsf(a[(size_t)t*LM+j]); cs+=fabsf(a[(size_t)j*LM+t]); }
  float rm=bMax(rs,red), cm=bMax(cs,red);
  if(t==0){ g_mx[h]=rm; g_mx[NH+h]=cm; }
}
__global__ void denom_k()
{
  int t=threadIdx.x;
  float rm=(t<NH)?g_mx[t]:-3.4e38f, cm=(t<NH)?g_mx[NH+t]:-3.4e38f;
  rm=wMax(rm); cm=wMax(cm);
  if(t==0) g_den=rm*cm;
}
__global__ __launch_bounds__(256) void zinit_k()
{
  int i=blockIdx.x, h=blockIdx.y, j=threadIdx.x;
  float inv=1.f/g_den;
  g_z[((size_t)h*LM+i)*LM+j]=g_a2[((size_t)h*LM+j)*LM+i]*inv;
}

// ------------- fused a1@W2 + depthwise-33 residual (2 rows/iter) -----------
#define CH 128
__global__ __launch_bounds__(256) void a1res_k(const float* __restrict__ rw,
                                               int row_start, int row_cnt)
{
  extern __shared__ float sm[];
  float* kls=sm;               // 256*65 = 16640
  float* w2s=sm+16640;         // 16640
  float* vs =sm+33280;         // 160*64 = 10240 -> 43520
  float* rws=sm+43520;         // 33 (pad 40)    -> 43560
  float* qs =sm+43560;         // 128            -> 43688
  float* ps =sm+43688;         // 256            -> 43944
  float* ps2=sm+43944;         // 256            -> 44200
  float* op0=sm+44200;         // 256            -> 44456
  float* op1=sm+44456;         // 256            -> 44712
  float* red=sm+44712;         // 64             -> 44776
  int t=threadIdx.x, h=blockIdx.y;
  int i0=row_start+blockIdx.x*CH;
  int rend=row_start+row_cnt;
  for(int idx=t;idx<LM*DH;idx+=256){
    int j=idx>>6, d=idx&63;
    kls[j*65+d]=g_kl[((size_t)h*LM+j)*DH+d];
    w2s[j*65+d]=g_w2[((size_t)h*LM+j)*DH+d];
  }
  for(int idx=t;idx<160*64;idx+=256){
    int rr=idx>>6, d=idx&63, gr=i0-16+rr;
    vs[rr*64+d]=(gr>=0&&gr<NPD)?g_qkv[(size_t)gr*1536+1024+h*64+d]:0.f;
  }
  if(t<33) rws[t]=rw[h*33+t];
  __syncthreads();
  for(int ii=0;ii<CH;ii+=2){
    int i=i0+ii;
    if(i>=rend) break;
    bool v1=(i+1<rend);
    if(t<64) qs[t]=g_qkv[(size_t)i*1536+h*64+t]*0.125f;
    else if(t<128) qs[t]=v1?g_qkv[(size_t)(i+1)*1536+h*64+(t-64)]*0.125f:0.f;
    __syncthreads();
    float l0=0.f, l1=0.f;
#pragma unroll
    for(int d=0;d<DH;d++){
      float kv=kls[t*65+d];
      l0+=qs[d]*kv;
      l1+=qs[64+d]*kv;
    }
    float2 M=bMax2(l0,v1?l1:l0,red);
    float p0=__expf(l0-M.x), p1=__expf(l1-M.y);
    float2 S=bSum2(p0,p1,red);
    ps[t]=p0/S.x; ps2[t]=p1/S.y;
    __syncthreads();
    {
      int g=t>>6, d=t&63;
      float o0=0.f, o1=0.f;
#pragma unroll 8
      for(int j=g*64;j<g*64+64;j++){
        float w=w2s[j*65+d];
        o0+=ps[j]*w;
        o1+=ps2[j]*w;
      }
      op0[g*64+d]=o0;
      op1[g*64+d]=o1;
    }
    __syncthreads();
    if(t<128){
      int rr=t>>6, d=t&63;
      if(rr==0||v1){
        float* opp=rr?op1:op0;
        float o=opp[d]+opp[64+d]+opp[128+d]+opp[192+d];
#pragma unroll
        for(int tap=0;tap<33;tap++) o+=vs[(ii+rr+tap)*64+d]*rws[tap];
        g_ao[(size_t)(i+rr-255)*512+h*64+d]=o;
      }
    }
    __syncthreads();
  }
}

// ------------- PPEG: cf + dw7 + dw5 + dw3 ----------------------------------
__global__ __launch_bounds__(256) void ppeg_k(
    const float* __restrict__ w7, const float* __restrict__ b7,
    const float* __restrict__ w5, const float* __restrict__ b5,
    const float* __restrict__ w3, const float* __restrict__ b3)
{
  extern __shared__ float sm[];
  float* sin_=sm;          // 22*22*65
  float* w7s=sm+31460;     // 49*64
  float* w5s=sm+34596;     // 25*64
  float* w3s=sm+36196;     // 9*64
  float* bs =sm+36772;     // 64
  int t=threadIdx.x;
  int ty0=(blockIdx.x>>3)*16, tx0=(blockIdx.x&7)*16;
  int cbase=blockIdx.y*64;
  for(int idx=t;idx<22*22*64;idx+=256){
    int c=idx&63, pp=idx>>6, yy=pp/22, xx=pp%22;
    int gy=ty0+yy-3, gx=tx0+xx-3;
    sin_[(yy*22+xx)*65+c]=(gy>=0&&gy<128&&gx>=0&&gx<128)?
        g_h[(size_t)(1+gy*128+gx)*512+cbase+c]:0.f;
  }
  for(int idx=t;idx<49*64;idx+=256){ int c=idx&63,k=idx>>6; w7s[k*64+c]=w7[(cbase+c)*49+k]; }
  for(int idx=t;idx<25*64;idx+=256){ int c=idx&63,k=idx>>6; w5s[k*64+c]=w5[(cbase+c)*25+k]; }
  for(int idx=t;idx<9*64;idx+=256){ int c=idx&63,k=idx>>6; w3s[k*64+c]=w3[(cbase+c)*9+k]; }
  if(t<64) bs[t]=b7[cbase+t]+b5[cbase+t]+b3[cbase+t];
  __syncthreads();
  int py=t>>4, px=t&15;
  for(int c=0;c<64;c++){
    float acc=sin_[((py+3)*22+px+3)*65+c]+bs[c];
#pragma unroll
    for(int ky=0;ky<7;ky++)
#pragma unroll
      for(int kx=0;kx<7;kx++)
        acc+=sin_[((py+ky)*22+px+kx)*65+c]*w7s[(ky*7+kx)*64+c];
#pragma unroll
    for(int ky=0;ky<5;ky++)
#pragma unroll
      for(int kx=0;kx<5;kx++)
        acc+=sin_[((py+1+ky)*22+px+1+kx)*65+c]*w5s[(ky*5+kx)*64+c];
#pragma unroll
    for(int ky=0;ky<3;ky++)
#pragma unroll
      for(int kx=0;kx<3;kx++)
        acc+=sin_[((py+2+ky)*22+px+2+kx)*65+c]*w3s[(ky*3+kx)*64+c];
    g_h2[(size_t)(1+(ty0+py)*128+tx0+px)*512+cbase+c]=acc;
  }
}

// ------------- small helpers -----------------------------------------------
__global__ void clscopy_k(const float* __restrict__ cls){ g_h[threadIdx.x]=cls[threadIdx.x]; }
__global__ void row0cpy_k(){ g_h2[threadIdx.x]=g_h[threadIdx.x]; }

// ------------- final: cls out-proj + residual + LN + fc2 -------------------
__global__ __launch_bounds__(512) void final_k(
    const float* __restrict__ outw, const float* __restrict__ outb,
    const float* __restrict__ ng, const float* __restrict__ nb,
    const float* __restrict__ fw, const float* __restrict__ fb,
    float* __restrict__ out)
{
  __shared__ float sh[512]; __shared__ float red[32];
  int t=threadIdx.x;
  float acc=0.f;
  for(int k=0;k<512;k++) acc+=g_ao[k]*outw[(size_t)k*512+t];
  float row=g_h2[t]+acc+outb[t];
  float mean=bSum(row,red)*(1.f/512.f);
  float d=row-mean;
  float var=bSum(d*d,red)*(1.f/512.f);
  float y=d*(1.f/sqrtf(var+1e-5f))*ng[t]+nb[t];
  sh[t]=y;
  __syncthreads();
  if(t<4){
    float o=fb[t];
    for(int c=0;c<512;c++) o+=sh[c]*fw[c*4+t];
    out[t]=o;
  }
}

// ---------------- host orchestration ----------------------------------------
static void* sym(const void* s){ void* p=nullptr; cudaGetSymbolAddress(&p,s); return p; }

static void attn_layer(const float* hin, const float* ng, const float* nbi,
                       const float* qkvw, const float* outw, const float* outb,
                       const float* resw, int layer2,
                       float* ph, float* pxp, float* pqkv, float* pao,
                       float* pz, float* po3, float* pw2,
                       size_t a1sm, size_t a3sm)
{
  ln_pad_k<<<NPD,256>>>(hin,ng,nbi);
  gemm_tf32<0><<<dim3(1536/128,130),256>>>(pxp,qkvw,pqkv,nullptr,NPD,1536,512);
  landmarks_k<<<dim3(LM,NH),64>>>();
  a2_k<<<dim3(LM,NH),256>>>();
  sums_k<<<NH,256>>>();
  denom_k<<<1,32>>>();
  zinit_k<<<dim3(LM,NH),256>>>();
  nwt_k<<<NWT_BLOCKS,128>>>();                 // 6 Newton iters, final z in g_z
  a3f_k<<<dim3(2,NH,KC),128,a3sm>>>();         // fused flash a3 partials
  a3mrg_k<<<dim3(LM,NH),64>>>();               // merge -> o3
  g256t<<<dim3(1,4,NH),128>>>(pz,po3,pw2,64,1.f,0.f);
  if(!layer2){
    a1res_k<<<dim3((NR+CH-1)/CH,NH),256,a1sm>>>(resw,255,NR);
    gemm_tf32<2><<<dim3(4,(NR+127)/128),256>>>(pao,outw,ph,outb,NR,512,512);
  }else{
    a1res_k<<<dim3(1,NH),256,a1sm>>>(resw,255,1);
  }
}

extern "C" void kernel_launch(void* const* d_in, const int* in_sizes, int n_in,
                              void* d_out, int out_size)
{
  const float* x     =(const float*)d_in[0];
  const float* fc1w  =(const float*)d_in[1];
  const float* fc1b  =(const float*)d_in[2];
  const float* cls   =(const float*)d_in[3];
  const float* l1ng  =(const float*)d_in[4];
  const float* l1nb  =(const float*)d_in[5];
  const float* l1qkv =(const float*)d_in[6];
  const float* l1ow  =(const float*)d_in[7];
  const float* l1ob  =(const float*)d_in[8];
  const float* l1rw  =(const float*)d_in[9];

  int ppegBase, l2Base;
  if (in_sizes[10] == 25088) { ppegBase = 10; l2Base = 16; }
  else                       { l2Base = 10; ppegBase = 16; }

  const float* w7   =(const float*)d_in[ppegBase+0];
  const float* b7   =(const float*)d_in[ppegBase+1];
  const float* w5   =(const float*)d_in[ppegBase+2];
  const float* b5   =(const float*)d_in[ppegBase+3];
  const float* w3   =(const float*)d_in[ppegBase+4];
  const float* b3   =(const float*)d_in[ppegBase+5];
  const float* l2ng =(const float*)d_in[l2Base+0];
  const float* l2nb =(const float*)d_in[l2Base+1];
  const float* l2qkv=(const float*)d_in[l2Base+2];
  const float* l2ow =(const float*)d_in[l2Base+3];
  const float* l2ob =(const float*)d_in[l2Base+4];
  const float* l2rw =(const float*)d_in[l2Base+5];
  const float* nng  =(const float*)d_in[22];
  const float* nnb  =(const float*)d_in[23];
  const float* fc2w =(const float*)d_in[24];
  const float* fc2b =(const float*)d_in[25];
  float* out=(float*)d_out;

  float* ph  =(float*)sym(g_h);
  float* ph2 =(float*)sym(g_h2);
  float* pxp =(float*)sym(g_xp);
  float* pqkv=(float*)sym(g_qkv);
  float* pao =(float*)sym(g_ao);
  float* pz  =(float*)sym(g_z);
  float* po3 =(float*)sym(g_o3);
  float* pw2 =(float*)sym(g_w2);

  const size_t A1SM=44776*sizeof(float);   // ~179.1 KB
  const size_t PPSM=36836*sizeof(float);   // ~147.3 KB
  const size_t A3SM=26368*sizeof(unsigned);// ~105.5 KB
  cudaFuncSetAttribute(a1res_k,cudaFuncAttributeMaxDynamicSharedMemorySize,(int)A1SM);
  cudaFuncSetAttribute(ppeg_k, cudaFuncAttributeMaxDynamicSharedMemorySize,(int)PPSM);
  cudaFuncSetAttribute(a3f_k,  cudaFuncAttributeMaxDynamicSharedMemorySize,(int)A3SM);

  // fc1 + cls
  gemm_tf32<1><<<dim3(4,128),256>>>(x,fc1w,ph+512,fc1b,16384,512,1024);
  clscopy_k<<<1,512>>>(cls);
  // layer 1
  attn_layer(ph,l1ng,l1nb,l1qkv,l1ow,l1ob,l1rw,0,
             ph,pxp,pqkv,pao,pz,po3,pw2,A1SM,A3SM);
  // PPEG
  row0cpy_k<<<1,512>>>();
  ppeg_k<<<dim3(64,8),256,PPSM>>>(w7,b7,w5,b5,w3,b3);
  // layer 2 (only cls row of attention output needed)
  attn_layer(ph2,l2ng,l2nb,l2qkv,l2ow,l2ob,l2rw,1,
             ph2,pxp,pqkv,pao,pz,po3,pw2,A1SM,A3SM);
  // final: out-proj row + residual + LN + fc2
  final_k<<<1,512>>>(l2ow,l2ob,nng,nnb,fc2w,fc2b,out);
}

// round 17
// speedup vs baseline: 2.2208x; 1.3176x over previous
#include <cuda_runtime.h>
#include <math.h>

#define NR  16385
#define NPD 16640
#define NH  8
#define DH  64
#define LM  256
#define KC  26          // key chunks for flash a3 (26*640 = 16640)
#define CHK 640
#define NSUB 10         // 640/64 sub-tiles

// ---------------- scratch (device globals, allocation-free) ----------------
__device__ float g_h  [NR  * 512];
__device__ float g_h2 [NR  * 512];
__device__ float g_xp [NPD * 512];
__device__ float g_qkv[NPD * 1536];
__device__ float g_ao [NR  * 512];
__device__ float g_ql [NH * LM * DH];
__device__ float g_kl [NH * LM * DH];
__device__ float g_a2 [NH * LM * LM];
__device__ float g_z  [NH * LM * LM];
__device__ float g_zb [NH * LM * LM];
__device__ float g_az [NH * LM * LM];
__device__ float g_t1 [NH * LM * LM];
__device__ float g_t2 [NH * LM * LM];
__device__ float g_p3 [KC * NH * LM * DH];
__device__ float2 g_ms2[KC * NH * LM];
__device__ float g_o3 [NH * LM * DH];
__device__ float g_w2 [NH * LM * DH];
__device__ float g_mx [2 * NH];
__device__ float g_den;
__device__ unsigned g_cnt;   // zero-init; self-resetting barrier counter
__device__ unsigned g_phs;   // monotone phase flag

// ---------------- reductions ----------------
__device__ __forceinline__ float wSum(float v){
#pragma unroll
  for(int o=16;o>0;o>>=1) v += __shfl_xor_sync(0xffffffffu,v,o);
  return v;
}
__device__ __forceinline__ float wMax(float v){
#pragma unroll
  for(int o=16;o>0;o>>=1) v = fmaxf(v,__shfl_xor_sync(0xffffffffu,v,o));
  return v;
}
__device__ __forceinline__ float bSum(float v, float* red){
  int w=threadIdx.x>>5, l=threadIdx.x&31, nw=(blockDim.x+31)>>5;
  v=wSum(v); if(l==0) red[w]=v; __syncthreads();
  if(w==0){ float r=(l<nw)?red[l]:0.f; r=wSum(r); if(l==0) red[0]=r; }
  __syncthreads(); float r=red[0]; __syncthreads(); return r;
}
__device__ __forceinline__ float bMax(float v, float* red){
  int w=threadIdx.x>>5, l=threadIdx.x&31, nw=(blockDim.x+31)>>5;
  v=wMax(v); if(l==0) red[w]=v; __syncthreads();
  if(w==0){ float r=(l<nw)?red[l]:-3.4e38f; r=wMax(r); if(l==0) red[0]=r; }
  __syncthreads(); float r=red[0]; __syncthreads(); return r;
}

// ---------------- TF32 mma helpers ----------------
__device__ __forceinline__ unsigned f2tf(float f){
  unsigned u; asm("cvt.rna.tf32.f32 %0, %1;" : "=r"(u) : "f"(f)); return u;
}
__device__ __forceinline__ void mma8(float* c, const unsigned* a, const unsigned* b){
  asm volatile("mma.sync.aligned.m16n8k8.row.col.f32.tf32.tf32.f32 "
    "{%0,%1,%2,%3}, {%4,%5,%6,%7}, {%8,%9}, {%0,%1,%2,%3};"
    : "+f"(c[0]),"+f"(c[1]),"+f"(c[2]),"+f"(c[3])
    : "r"(a[0]),"r"(a[1]),"r"(a[2]),"r"(a[3]), "r"(b[0]),"r"(b[1]));
}

// ------- TF32 GEMM, 64x64 warp tiles, double-buffered: C=A@B (+epilogue) ---
// MODE 0: C=AB   MODE 1: C=relu(AB+bias)   MODE 2: C += AB + bias
// BM=BN=128, BK=16, 128 threads (4 warps 2x2), warp tile 64x64
template<int MODE>
__global__ __launch_bounds__(128) void gemm_tf32(
    const float* __restrict__ A, const float* __restrict__ B, float* __restrict__ Cd,
    const float* __restrict__ bias, int M, int N, int K)
{
  __shared__ unsigned As[2][128*20];   // [row][k] stride 20
  __shared__ unsigned Bs[2][16*136];   // [k][n]  stride 136
  int t=threadIdx.x, lane=t&31, wid=t>>5;
  int row0=blockIdx.y*128, col0=blockIdx.x*128;
  int m_off=64*(wid&1), n_off=64*(wid>>1);
  int lq=lane>>2, lr=lane&3;
  int ar=t;                       // A loader: one row per thread, 16 k
  int bkr=t>>3, bnc=(t&7)*16;     // B loader: k-row, 16 n cols
  bool aval=(row0+ar)<M;
  const float* Ap=A+(size_t)(row0+ar)*K;
  const float* Bp=B+(size_t)bkr*N+col0+bnc;

  float c[4][8][4];
#pragma unroll
  for(int mt=0;mt<4;mt++)
#pragma unroll
    for(int nt=0;nt<8;nt++)
#pragma unroll
      for(int i=0;i<4;i++) c[mt][nt][i]=0.f;

  float4 xa[4], yb[4];
#pragma unroll
  for(int i=0;i<4;i++){
    xa[i]=aval?*(const float4*)(Ap+4*i):make_float4(0,0,0,0);
    yb[i]=*(const float4*)(Bp+4*i);
  }
  {
    unsigned* as=As[0]; unsigned* bs=Bs[0];
#pragma unroll
    for(int i=0;i<4;i++){
      *(uint4*)&as[ar*20+4*i]=make_uint4(f2tf(xa[i].x),f2tf(xa[i].y),f2tf(xa[i].z),f2tf(xa[i].w));
      *(uint4*)&bs[bkr*136+bnc+4*i]=make_uint4(f2tf(yb[i].x),f2tf(yb[i].y),f2tf(yb[i].z),f2tf(yb[i].w));
    }
  }
  __syncthreads();
  int nb=0;
  for(int k0=16;k0<K+16;k0+=16){
    bool more=(k0<K);
    if(more){
#pragma unroll
      for(int i=0;i<4;i++){
        xa[i]=aval?*(const float4*)(Ap+k0+4*i):make_float4(0,0,0,0);
        yb[i]=*(const float4*)(Bp+(size_t)k0*N+4*i);
      }
    }
    {
      const unsigned* as=As[nb]; const unsigned* bs=Bs[nb];
#pragma unroll
      for(int kk=0;kk<2;kk++){
        int ks=kk*8;
        unsigned a[4][4], b[8][2];
#pragma unroll
        for(int mt=0;mt<4;mt++){
          int m=m_off+16*mt+lq;
          a[mt][0]=as[m*20+ks+lr];
          a[mt][1]=as[(m+8)*20+ks+lr];
          a[mt][2]=as[m*20+ks+4+lr];
          a[mt][3]=as[(m+8)*20+ks+4+lr];
        }
#pragma unroll
        for(int nt=0;nt<8;nt++){
          int n=n_off+8*nt+lq;
          b[nt][0]=bs[(ks+lr)*136+n];
          b[nt][1]=bs[(ks+4+lr)*136+n];
        }
#pragma unroll
        for(int mt=0;mt<4;mt++)
#pragma unroll
          for(int nt=0;nt<8;nt++) mma8(c[mt][nt],a[mt],b[nt]);
      }
    }
    if(more){
      unsigned* as=As[nb^1]; unsigned* bs=Bs[nb^1];
#pragma unroll
      for(int i=0;i<4;i++){
        *(uint4*)&as[ar*20+4*i]=make_uint4(f2tf(xa[i].x),f2tf(xa[i].y),f2tf(xa[i].z),f2tf(xa[i].w));
        *(uint4*)&bs[bkr*136+bnc+4*i]=make_uint4(f2tf(yb[i].x),f2tf(yb[i].y),f2tf(yb[i].z),f2tf(yb[i].w));
      }
      __syncthreads();
      nb^=1;
    }
  }
#pragma unroll
  for(int mt=0;mt<4;mt++){
    int rA=row0+m_off+16*mt+lq;
#pragma unroll
    for(int nt=0;nt<8;nt++){
      int cg=col0+n_off+8*nt+2*lr;
#pragma unroll
      for(int half=0;half<2;half++){
        int r=rA+half*8;
        if(r<M){
          size_t off=(size_t)r*N+cg;
          float v0=c[mt][nt][half*2], v1=c[mt][nt][half*2+1];
          if(MODE==1){
            v0+=bias[cg];   v0=v0>0.f?v0:0.f;
            v1+=bias[cg+1]; v1=v1>0.f?v1:0.f;
            Cd[off]=v0; Cd[off+1]=v1;
          }else if(MODE==2){
            Cd[off]  +=v0+bias[cg];
            Cd[off+1]+=v1+bias[cg+1];
          }else{
            Cd[off]=v0; Cd[off+1]=v1;
          }
        }
      }
    }
  }
}

// ---------------- fused flash a3: o3 partials = softmax(q_l@k^T)@v ---------
// grid (2 row-halves, NH, KC), 128 threads (4 warps, 32 rows/warp)
__global__ __launch_bounds__(128) void a3f_k()
{
  extern __shared__ unsigned smu[];
  unsigned* Qs=smu;                 // 128*68 = 8704
  unsigned* Ks=smu+8704;            // 64*68  = 4352
  unsigned* Vs=smu+13056;           // 64*72  = 4608
  unsigned* Ps=smu+17664;           // 128*68 = 8704  -> total 26368 u
  int t=threadIdx.x, lane=t&31, wid=t>>5;
  int r0=blockIdx.x*128, h=blockIdx.y, kc=blockIdx.z;
  int key0=kc*CHK;
  int m_off=32*wid;
  int lq=lane>>2, lr=lane&3;

  {
    const float* qp=g_ql+((size_t)h*LM + r0+t)*DH;
#pragma unroll
    for(int d=0;d<64;d+=4){
      float4 v=*(const float4*)(qp+d);
      *(uint4*)&Qs[t*68+d]=make_uint4(f2tf(v.x),f2tf(v.y),f2tf(v.z),f2tf(v.w));
    }
  }

  float c2[2][8][4];
#pragma unroll
  for(int mt=0;mt<2;mt++)
#pragma unroll
    for(int nt=0;nt<8;nt++)
#pragma unroll
      for(int i=0;i<4;i++) c2[mt][nt][i]=0.f;
  float rm[2][2]={{-3.4e38f,-3.4e38f},{-3.4e38f,-3.4e38f}};
  float rs[2][2]={{0.f,0.f},{0.f,0.f}};

  for(int sub=0;sub<NSUB;sub++){
    __syncthreads();
    {
      int krow=t>>1;
      int gkey=key0+sub*64+krow;
      int ch=(t&1)*32;
      const float* kp=g_qkv+(size_t)gkey*1536+512+h*64+ch;
      const float* vp=kp+512;
#pragma unroll
      for(int d=0;d<32;d+=4){
        float4 kv=*(const float4*)(kp+d);
        *(uint4*)&Ks[krow*68+ch+d]=make_uint4(f2tf(kv.x),f2tf(kv.y),f2tf(kv.z),f2tf(kv.w));
        float4 vv=*(const float4*)(vp+d);
        *(uint4*)&Vs[krow*72+ch+d]=make_uint4(f2tf(vv.x),f2tf(vv.y),f2tf(vv.z),f2tf(vv.w));
      }
    }
    __syncthreads();
    float c1[2][8][4];
#pragma unroll
    for(int mt=0;mt<2;mt++)
#pragma unroll
      for(int nt=0;nt<8;nt++)
#pragma unroll
        for(int i=0;i<4;i++) c1[mt][nt][i]=0.f;
#pragma unroll
    for(int ks=0;ks<64;ks+=8){
      unsigned a[2][4], b[8][2];
#pragma unroll
      for(int mt=0;mt<2;mt++){
        int m=m_off+16*mt+lq;
        a[mt][0]=Qs[m*68+ks+lr];
        a[mt][1]=Qs[(m+8)*68+ks+lr];
        a[mt][2]=Qs[m*68+ks+4+lr];
        a[mt][3]=Qs[(m+8)*68+ks+4+lr];
      }
#pragma unroll
      for(int nt=0;nt<8;nt++){
        int n=8*nt+lq;
        b[nt][0]=Ks[n*68+ks+lr];
        b[nt][1]=Ks[n*68+ks+4+lr];
      }
#pragma unroll
      for(int mt=0;mt<2;mt++)
#pragma unroll
        for(int nt=0;nt<8;nt++) mma8(c1[mt][nt],a[mt],b[nt]);
    }
#pragma unroll
    for(int mt=0;mt<2;mt++){
#pragma unroll
      for(int half=0;half<2;half++){
        float v=-3.4e38f;
#pragma unroll
        for(int nt=0;nt<8;nt++)
          v=fmaxf(v,fmaxf(c1[mt][nt][half*2],c1[mt][nt][half*2+1]));
        v=fmaxf(v,__shfl_xor_sync(0xffffffffu,v,1));
        v=fmaxf(v,__shfl_xor_sync(0xffffffffu,v,2));
        float mo=rm[mt][half];
        float mn=fmaxf(mo,v);
        float f=__expf(mo-mn);
        int row=m_off+16*mt+lq+8*half;
        float psum=0.f;
#pragma unroll
        for(int nt=0;nt<8;nt++){
          float p0=__expf(c1[mt][nt][half*2]-mn);
          float p1=__expf(c1[mt][nt][half*2+1]-mn);
          psum+=p0+p1;
          Ps[row*68+8*nt+2*lr]  =f2tf(p0);
          Ps[row*68+8*nt+2*lr+1]=f2tf(p1);
        }
        psum+=__shfl_xor_sync(0xffffffffu,psum,1);
        psum+=__shfl_xor_sync(0xffffffffu,psum,2);
        rs[mt][half]=rs[mt][half]*f+psum;
        rm[mt][half]=mn;
#pragma unroll
        for(int nt=0;nt<8;nt++){
          c2[mt][nt][half*2]  *=f;
          c2[mt][nt][half*2+1]*=f;
        }
      }
    }
    __syncwarp();
#pragma unroll
    for(int ks=0;ks<64;ks+=8){
      unsigned a[2][4], b[8][2];
#pragma unroll
      for(int mt=0;mt<2;mt++){
        int m=m_off+16*mt+lq;
        a[mt][0]=Ps[m*68+ks+lr];
        a[mt][1]=Ps[(m+8)*68+ks+lr];
        a[mt][2]=Ps[m*68+ks+4+lr];
        a[mt][3]=Ps[(m+8)*68+ks+4+lr];
      }
#pragma unroll
      for(int nt=0;nt<8;nt++){
        int n=8*nt+lq;
        b[nt][0]=Vs[(ks+lr)*72+n];
        b[nt][1]=Vs[(ks+4+lr)*72+n];
      }
#pragma unroll
      for(int mt=0;mt<2;mt++)
#pragma unroll
        for(int nt=0;nt<8;nt++) mma8(c2[mt][nt],a[mt],b[nt]);
    }
  }
  float* Cp=g_p3+((size_t)(kc*NH+h))*LM*DH;
#pragma unroll
  for(int mt=0;mt<2;mt++)
#pragma unroll
    for(int nt=0;nt<8;nt++)
#pragma unroll
      for(int half=0;half<2;half++){
        int row=r0+m_off+16*mt+lq+8*half;
        Cp[(size_t)row*DH+8*nt+2*lr]  =c2[mt][nt][half*2];
        Cp[(size_t)row*DH+8*nt+2*lr+1]=c2[mt][nt][half*2+1];
      }
  if(lr==0){
#pragma unroll
    for(int mt=0;mt<2;mt++)
#pragma unroll
      for(int half=0;half<2;half++){
        int row=m_off+16*mt+lq+8*half;
        g_ms2[(kc*NH+h)*LM + r0+row]=make_float2(rm[mt][half],rs[mt][half]);
      }
  }
}

// ---------------- merge flash partials -> o3 --------------------------------
__global__ void a3mrg_k()   // grid (LM, NH), 64 threads
{
  int i=blockIdx.x, h=blockIdx.y, d=threadIdx.x;
  float M=-3.4e38f;
#pragma unroll 1
  for(int kc=0;kc<KC;kc++) M=fmaxf(M, g_ms2[(kc*NH+h)*LM+i].x);
  float S=0.f, acc=0.f;
#pragma unroll 1
  for(int kc=0;kc<KC;kc++){
    float2 ms=g_ms2[(kc*NH+h)*LM+i];
    float w=__expf(ms.x-M);
    S+=ms.y*w;
    acc+=g_p3[((size_t)(kc*NH+h))*LM*DH + (size_t)i*DH + d]*w;
  }
  g_o3[((size_t)h*LM+i)*DH+d]=acc/S;
}

// -------- fused flash a1: out = softmax(q@k_l^T)@W2 + depthwise-33 ---------
// grid (ceil(rows/128), NH), 128 threads; 4 sub-tiles of 64 landmarks
__global__ __launch_bounds__(128) void a1f_k(const float* __restrict__ rw,
                                             int row_start, int row_cnt)
{
  extern __shared__ unsigned smu[];
  unsigned* Qs=smu;                  // 128*68 = 8704
  unsigned* Ks=smu+8704;             // 64*68  = 4352  -> 13056
  unsigned* Ws=smu+13056;            // 64*72  = 4608  -> 17664
  unsigned* Ps=smu+17664;            // 128*68 = 8704  -> 26368
  float* vs=(float*)(smu+26368);     // 160*64 = 10240 -> 36608
  float* rws=(float*)(smu+36608);    // 33            -> 36648
  int t=threadIdx.x, lane=t&31, wid=t>>5;
  int h=blockIdx.y;
  int i0=row_start+blockIdx.x*128;
  int rend=row_start+row_cnt;
  int m_off=32*wid;
  int lq=lane>>2, lr=lane&3;

  // Q rows i0..i0+127 (scaled by 1/8); zero-guard beyond NPD
  {
    int gi=i0+t;
    if(gi<NPD){
      const float* qp=g_qkv+(size_t)gi*1536+h*64;
#pragma unroll
      for(int d=0;d<64;d+=4){
        float4 v=*(const float4*)(qp+d);
        *(uint4*)&Qs[t*68+d]=make_uint4(f2tf(v.x*0.125f),f2tf(v.y*0.125f),f2tf(v.z*0.125f),f2tf(v.w*0.125f));
      }
    }else{
#pragma unroll
      for(int d=0;d<64;d+=4)
        *(uint4*)&Qs[t*68+d]=make_uint4(0,0,0,0);
    }
  }
  // conv v window: rows i0-16 .. i0+143
  for(int idx=t;idx<2560;idx+=128){
    int rr=idx>>4, c4=(idx&15)*4;
    int gr=i0-16+rr;
    float4 v=make_float4(0,0,0,0);
    if(gr>=0&&gr<NPD) v=*(const float4*)(g_qkv+(size_t)gr*1536+1024+h*64+c4);
    *(float4*)&vs[rr*64+c4]=v;
  }
  if(t<33) rws[t]=rw[h*33+t];

  float c2[2][8][4];
#pragma unroll
  for(int mt=0;mt<2;mt++)
#pragma unroll
    for(int nt=0;nt<8;nt++)
#pragma unroll
      for(int i=0;i<4;i++) c2[mt][nt][i]=0.f;
  float rm[2][2]={{-3.4e38f,-3.4e38f},{-3.4e38f,-3.4e38f}};
  float rs[2][2]={{0.f,0.f},{0.f,0.f}};

  for(int sub=0;sub<4;sub++){
    __syncthreads();
    {
      int krow=t>>1;
      int ch=(t&1)*32;
      const float* kp=g_kl+((size_t)h*LM+sub*64+krow)*DH+ch;
      const float* wp=g_w2+((size_t)h*LM+sub*64+krow)*DH+ch;
#pragma unroll
      for(int d=0;d<32;d+=4){
        float4 kv=*(const float4*)(kp+d);
        *(uint4*)&Ks[krow*68+ch+d]=make_uint4(f2tf(kv.x),f2tf(kv.y),f2tf(kv.z),f2tf(kv.w));
        float4 wv=*(const float4*)(wp+d);
        *(uint4*)&Ws[krow*72+ch+d]=make_uint4(f2tf(wv.x),f2tf(wv.y),f2tf(wv.z),f2tf(wv.w));
      }
    }
    __syncthreads();
    float c1[2][8][4];
#pragma unroll
    for(int mt=0;mt<2;mt++)
#pragma unroll
      for(int nt=0;nt<8;nt++)
#pragma unroll
        for(int i=0;i<4;i++) c1[mt][nt][i]=0.f;
#pragma unroll
    for(int ks=0;ks<64;ks+=8){
      unsigned a[2][4], b[8][2];
#pragma unroll
      for(int mt=0;mt<2;mt++){
        int m=m_off+16*mt+lq;
        a[mt][0]=Qs[m*68+ks+lr];
        a[mt][1]=Qs[(m+8)*68+ks+lr];
        a[mt][2]=Qs[m*68+ks+4+lr];
        a[mt][3]=Qs[(m+8)*68+ks+4+lr];
      }
#pragma unroll
      for(int nt=0;nt<8;nt++){
        int n=8*nt+lq;
        b[nt][0]=Ks[n*68+ks+lr];
        b[nt][1]=Ks[n*68+ks+4+lr];
      }
#pragma unroll
      for(int mt=0;mt<2;mt++)
#pragma unroll
        for(int nt=0;nt<8;nt++) mma8(c1[mt][nt],a[mt],b[nt]);
    }
#pragma unroll
    for(int mt=0;mt<2;mt++){
#pragma unroll
      for(int half=0;half<2;half++){
        float v=-3.4e38f;
#pragma unroll
        for(int nt=0;nt<8;nt++)
          v=fmaxf(v,fmaxf(c1[mt][nt][half*2],c1[mt][nt][half*2+1]));
        v=fmaxf(v,__shfl_xor_sync(0xffffffffu,v,1));
        v=fmaxf(v,__shfl_xor_sync(0xffffffffu,v,2));
        float mo=rm[mt][half];
        float mn=fmaxf(mo,v);
        float f=__expf(mo-mn);
        int row=m_off+16*mt+lq+8*half;
        float psum=0.f;
#pragma unroll
        for(int nt=0;nt<8;nt++){
          float p0=__expf(c1[mt][nt][half*2]-mn);
          float p1=__expf(c1[mt][nt][half*2+1]-mn);
          psum+=p0+p1;
          Ps[row*68+8*nt+2*lr]  =f2tf(p0);
          Ps[row*68+8*nt+2*lr+1]=f2tf(p1);
        }
        psum+=__shfl_xor_sync(0xffffffffu,psum,1);
        psum+=__shfl_xor_sync(0xffffffffu,psum,2);
        rs[mt][half]=rs[mt][half]*f+psum;
        rm[mt][half]=mn;
#pragma unroll
        for(int nt=0;nt<8;nt++){
          c2[mt][nt][half*2]  *=f;
          c2[mt][nt][half*2+1]*=f;
        }
      }
    }
    __syncwarp();
#pragma unroll
    for(int ks=0;ks<64;ks+=8){
      unsigned a[2][4], b[8][2];
#pragma unroll
      for(int mt=0;mt<2;mt++){
        int m=m_off+16*mt+lq;
        a[mt][0]=Ps[m*68+ks+lr];
        a[mt][1]=Ps[(m+8)*68+ks+lr];
        a[mt][2]=Ps[m*68+ks+4+lr];
        a[mt][3]=Ps[(m+8)*68+ks+4+lr];
      }
#pragma unroll
      for(int nt=0;nt<8;nt++){
        int n=8*nt+lq;
        b[nt][0]=Ws[(ks+lr)*72+n];
        b[nt][1]=Ws[(ks+4+lr)*72+n];
      }
#pragma unroll
      for(int mt=0;mt<2;mt++)
#pragma unroll
        for(int nt=0;nt<8;nt++) mma8(c2[mt][nt],a[mt],b[nt]);
    }
  }
  // normalize into Ps (fp32 view) — each warp owns its 32 rows
  __syncthreads();
  float* Pf=(float*)Ps;
#pragma unroll
  for(int mt=0;mt<2;mt++)
#pragma unroll
    for(int half=0;half<2;half++){
      float inv=1.f/rs[mt][half];
      int row=m_off+16*mt+lq+8*half;
#pragma unroll
      for(int nt=0;nt<8;nt++){
        Pf[row*68+8*nt+2*lr]  =c2[mt][nt][half*2]*inv;
        Pf[row*68+8*nt+2*lr+1]=c2[mt][nt][half*2+1]*inv;
      }
    }
  __syncthreads();
  // conv + store: d-major mapping (conflict-free, coalesced)
  {
    int d=t&63, rsel=t>>6;
    for(int rr=rsel;rr<128;rr+=2){
      int gi=i0+rr;
      if(gi>=row_start&&gi<rend){
        float o=Pf[rr*68+d];
#pragma unroll
        for(int tap=0;tap<33;tap++) o+=vs[(rr+tap)*64+d]*rws[tap];
        g_ao[(size_t)(gi-255)*512+h*64+d]=o;
      }
    }
  }
}

// ---------------- TF32 64x64 step for Newton (double-buffered) --------------
__device__ __forceinline__ void gemm64_tc(unsigned* AsB, unsigned* BsB,
    const float* __restrict__ Ah, const float* __restrict__ Bh, float* __restrict__ Ch,
    float c0, float c1, int row0, int col0)
{
  int t=threadIdx.x, lane=t&31, wid=t>>5;
  int m_off=32*(wid&1), n_off=32*(wid>>1);
  int lq=lane>>2, lr=lane&3;
  int ar=t>>1, akq=(t&1)*8;
  int bkr=t>>3, bnc=(t&7)*8;
  const float* Ap=Ah+(size_t)(row0+ar)*256;
  const float* Bp=Bh+(size_t)bkr*256+col0+bnc;
  float c[2][4][4];
#pragma unroll
  for(int mt=0;mt<2;mt++)
#pragma unroll
    for(int nt=0;nt<4;nt++)
#pragma unroll
      for(int i=0;i<4;i++) c[mt][nt][i]=0.f;

  float4 x0,x1,y0,y1;
  x0=*(const float4*)(Ap+akq);
  x1=*(const float4*)(Ap+akq+4);
  y0=*(const float4*)(Bp);
  y1=*(const float4*)(Bp+4);
  {
    unsigned* as=AsB; unsigned* bs=BsB;
    as[(akq+0)*72+ar]=f2tf(x0.x); as[(akq+1)*72+ar]=f2tf(x0.y);
    as[(akq+2)*72+ar]=f2tf(x0.z); as[(akq+3)*72+ar]=f2tf(x0.w);
    as[(akq+4)*72+ar]=f2tf(x1.x); as[(akq+5)*72+ar]=f2tf(x1.y);
    as[(akq+6)*72+ar]=f2tf(x1.z); as[(akq+7)*72+ar]=f2tf(x1.w);
    *(uint4*)&bs[bkr*72+bnc]  =make_uint4(f2tf(y0.x),f2tf(y0.y),f2tf(y0.z),f2tf(y0.w));
    *(uint4*)&bs[bkr*72+bnc+4]=make_uint4(f2tf(y1.x),f2tf(y1.y),f2tf(y1.z),f2tf(y1.w));
  }
  __syncthreads();
  int nb=0;
  for(int k0=16;k0<256+16;k0+=16){
    bool more=(k0<256);
    if(more){
      x0=*(const float4*)(Ap+k0+akq);
      x1=*(const float4*)(Ap+k0+akq+4);
      y0=*(const float4*)(Bp+(size_t)k0*256);
      y1=*(const float4*)(Bp+(size_t)k0*256+4);
    }
    {
      const unsigned* as=AsB+nb*1152; const unsigned* bs=BsB+nb*1152;
#pragma unroll
      for(int kk=0;kk<2;kk++){
        int ks=kk*8;
        unsigned a[2][4], b[4][2];
#pragma unroll
        for(int mt=0;mt<2;mt++){
          int m=m_off+16*mt+lq;
          a[mt][0]=as[(ks+lr)*72+m];
          a[mt][1]=as[(ks+lr)*72+m+8];
          a[mt][2]=as[(ks+4+lr)*72+m];
          a[mt][3]=as[(ks+4+lr)*72+m+8];
        }
#pragma unroll
        for(int nt=0;nt<4;nt++){
          int n=n_off+8*nt+lq;
          b[nt][0]=bs[(ks+lr)*72+n];
          b[nt][1]=bs[(ks+4+lr)*72+n];
        }
#pragma unroll
        for(int mt=0;mt<2;mt++)
#pragma unroll
          for(int nt=0;nt<4;nt++) mma8(c[mt][nt],a[mt],b[nt]);
      }
    }
    if(more){
      unsigned* as=AsB+(nb^1)*1152; unsigned* bs=BsB+(nb^1)*1152;
      as[(akq+0)*72+ar]=f2tf(x0.x); as[(akq+1)*72+ar]=f2tf(x0.y);
      as[(akq+2)*72+ar]=f2tf(x0.z); as[(akq+3)*72+ar]=f2tf(x0.w);
      as[(akq+4)*72+ar]=f2tf(x1.x); as[(akq+5)*72+ar]=f2tf(x1.y);
      as[(akq+6)*72+ar]=f2tf(x1.z); as[(akq+7)*72+ar]=f2tf(x1.w);
      *(uint4*)&bs[bkr*72+bnc]  =make_uint4(f2tf(y0.x),f2tf(y0.y),f2tf(y0.z),f2tf(y0.w));
      *(uint4*)&bs[bkr*72+bnc+4]=make_uint4(f2tf(y1.x),f2tf(y1.y),f2tf(y1.z),f2tf(y1.w));
      __syncthreads();
      nb^=1;
    }
  }
#pragma unroll
  for(int mt=0;mt<2;mt++){
#pragma unroll
    for(int nt=0;nt<4;nt++){
      int cg=col0+n_off+8*nt+2*lr;
#pragma unroll
      for(int half=0;half<2;half++){
        int r=row0+m_off+16*mt+lq+half*8;
        size_t off=(size_t)r*256+cg;
        float v0=c0*c[mt][nt][half*2], v1=c0*c[mt][nt][half*2+1];
        if(c1!=0.f){
          v0+=c1*Ah[off];
          v1+=c1*Ah[off+1];
        }
        Ch[off]=v0; Ch[off+1]=v1;
      }
    }
  }
}

// ---------------- grid barrier (self-resetting; replay-safe) ----------------
#define NWT_BLOCKS 128
__device__ __forceinline__ void gridbar(unsigned &phase){
  __syncthreads();
  if(threadIdx.x==0){
    __threadfence();
    unsigned old=atomicInc(&g_cnt,NWT_BLOCKS-1u);
    unsigned target=phase+1u;
    if(old==NWT_BLOCKS-1u){
      atomicExch(&g_phs,target);
    }else{
      while(atomicAdd(&g_phs,0u)!=target) __nanosleep(64);
    }
    __threadfence();
  }
  __syncthreads();
  phase++;
}

// ---------------- persistent Newton pinv: 6 iters x 4 GEMMs -----------------
__global__ __launch_bounds__(128) void nwt_k()
{
  __shared__ unsigned As[2*16*72];
  __shared__ unsigned Bs[2*16*72];
  __shared__ unsigned ph0;
  int t=threadIdx.x;
  int h=blockIdx.x>>4, tile=blockIdx.x&15;
  int row0=(tile>>2)*64, col0=(tile&3)*64;
  if(t==0) ph0=atomicAdd(&g_phs,0u);
  __syncthreads();
  unsigned phase=ph0;
  size_t ho=(size_t)h*65536;
  float* z =g_z +ho;
  float* zn=g_zb+ho;
#pragma unroll 1
  for(int it=0;it<6;it++){
    gemm64_tc(As,Bs,g_a2+ho,z,        g_az+ho, 1.f,  0.f,  row0,col0); gridbar(phase);
    gemm64_tc(As,Bs,g_az+ho,g_az+ho,  g_t1+ho,-1.f,  7.f,  row0,col0); gridbar(phase);
    gemm64_tc(As,Bs,g_az+ho,g_t1+ho,  g_t2+ho,-1.f, 15.f,  row0,col0); gridbar(phase);
    gemm64_tc(As,Bs,z,      g_t2+ho,  zn,     -0.25f,3.25f,row0,col0); gridbar(phase);
    float* tmp=z; z=zn; zn=tmp;
  }
}

// ---------- batched 8-head TF32 GEMM (for w2 = z@o3, N=64) ------------------
__global__ __launch_bounds__(128) void g256t(
    const float* __restrict__ A, const float* __restrict__ B, float* __restrict__ Cd,
    int N, float c0, float c1)
{
  __shared__ unsigned As[16*72];
  __shared__ unsigned Bs[16*72];
  const float* Ah=A+(size_t)blockIdx.z*65536;
  const float* Bh=B+(size_t)blockIdx.z*256*N;
  float* Ch=Cd+(size_t)blockIdx.z*256*N;
  int t=threadIdx.x, lane=t&31, wid=t>>5;
  int row0=blockIdx.y*64, col0=blockIdx.x*64;
  int m_off=32*(wid&1), n_off=32*(wid>>1);
  int lq=lane>>2, lr=lane&3;
  int ar=t>>1, akq=(t&1)*8;
  int bkr=t>>3, bnc=(t&7)*8;
  const float* Ap=Ah+(size_t)(row0+ar)*256;
  const float* Bp=Bh+(size_t)bkr*N+col0+bnc;
  float c[2][4][4];
#pragma unroll
  for(int mt=0;mt<2;mt++)
#pragma unroll
    for(int nt=0;nt<4;nt++)
#pragma unroll
      for(int i=0;i<4;i++) c[mt][nt][i]=0.f;
  for(int k0=0;k0<256;k0+=16){
    float4 x0=*(const float4*)(Ap+k0+akq);
    float4 x1=*(const float4*)(Ap+k0+akq+4);
    float4 y0=*(const float4*)(Bp+(size_t)k0*N);
    float4 y1=*(const float4*)(Bp+(size_t)k0*N+4);
    As[(akq+0)*72+ar]=f2tf(x0.x); As[(akq+1)*72+ar]=f2tf(x0.y);
    As[(akq+2)*72+ar]=f2tf(x0.z); As[(akq+3)*72+ar]=f2tf(x0.w);
    As[(akq+4)*72+ar]=f2tf(x1.x); As[(akq+5)*72+ar]=f2tf(x1.y);
    As[(akq+6)*72+ar]=f2tf(x1.z); As[(akq+7)*72+ar]=f2tf(x1.w);
    *(uint4*)&Bs[bkr*72+bnc]  =make_uint4(f2tf(y0.x),f2tf(y0.y),f2tf(y0.z),f2tf(y0.w));
    *(uint4*)&Bs[bkr*72+bnc+4]=make_uint4(f2tf(y1.x),f2tf(y1.y),f2tf(y1.z),f2tf(y1.w));
    __syncthreads();
#pragma unroll
    for(int kk=0;kk<2;kk++){
      int ks=kk*8;
      unsigned a[2][4], b[4][2];
#pragma unroll
      for(int mt=0;mt<2;mt++){
        int m=m_off+16*mt+lq;
        a[mt][0]=As[(ks+lr)*72+m];
        a[mt][1]=As[(ks+lr)*72+m+8];
        a[mt][2]=As[(ks+4+lr)*72+m];
        a[mt][3]=As[(ks+4+lr)*72+m+8];
      }
#pragma unroll
      for(int nt=0;nt<4;nt++){
        int n=n_off+8*nt+lq;
        b[nt][0]=Bs[(ks+lr)*72+n];
        b[nt][1]=Bs[(ks+4+lr)*72+n];
      }
#pragma unroll
      for(int mt=0;mt<2;mt++)
#pragma unroll
        for(int nt=0;nt<4;nt++) mma8(c[mt][nt],a[mt],b[nt]);
    }
    __syncthreads();
  }
#pragma unroll
  for(int mt=0;mt<2;mt++){
#pragma unroll
    for(int nt=0;nt<4;nt++){
      int cg=col0+n_off+8*nt+2*lr;
#pragma unroll
      for(int half=0;half<2;half++){
        int r=row0+m_off+16*mt+lq+half*8;
        size_t off=(size_t)r*N+cg;
        float v0=c0*c[mt][nt][half*2], v1=c0*c[mt][nt][half*2+1];
        if(c1!=0.f){
          v0+=c1*Ah[(size_t)r*256+cg];
          v1+=c1*Ah[(size_t)r*256+cg+1];
        }
        Ch[off]=v0; Ch[off+1]=v1;
      }
    }
  }
}

// ------------- LayerNorm + front-pad to NPD rows ---------------------------
__global__ __launch_bounds__(256) void ln_pad_k(const float* __restrict__ hin,
    const float* __restrict__ g, const float* __restrict__ b)
{
  int row=blockIdx.x, t=threadIdx.x;
  float* out=g_xp+(size_t)row*512;
  if(row<255){ out[t]=0.f; out[t+256]=0.f; return; }
  __shared__ float red[32];
  const float* x=hin+(size_t)(row-255)*512;
  float v0=x[t], v1=x[t+256];
  float mean=bSum(v0+v1,red)*(1.f/512.f);
  float d0=v0-mean, d1=v1-mean;
  float var=bSum(d0*d0+d1*d1,red)*(1.f/512.f);
  float rs=1.f/sqrtf(var+1e-5f);
  out[t]=d0*rs*g[t]+b[t];
  out[t+256]=d1*rs*g[t+256]+b[t+256];
}

// ------------- landmarks: mean of 65 consecutive rows ----------------------
__global__ void landmarks_k()
{
  int m=blockIdx.x, h=blockIdx.y, d=threadIdx.x;
  const float* base=g_qkv+(size_t)(m*65)*1536+h*64+d;
  float sq=0.f, sk=0.f;
  for(int j=0;j<65;j++){ sq+=base[(size_t)j*1536]; sk+=base[(size_t)j*1536+512]; }
  g_ql[(h*LM+m)*DH+d]=sq*(0.125f/65.f);
  g_kl[(h*LM+m)*DH+d]=sk*(1.f/65.f);
}

// ------------- a2 = softmax(q_l @ k_l^T) -----------------------------------
__global__ __launch_bounds__(256) void a2_k()
{
  int i=blockIdx.x, h=blockIdx.y, j=threadIdx.x;
  __shared__ float q[DH]; __shared__ float red[32];
  if(j<DH) q[j]=g_ql[(h*LM+i)*DH+j];
  __syncthreads();
  const float* kr=&g_kl[(h*LM+j)*DH];
  float s=0.f;
#pragma unroll
  for(int d=0;d<DH;d++) s+=q[d]*kr[d];
  float mx=bMax(s,red);
  float p=expf(s-mx);
  float ss=bSum(p,red);
  g_a2[((size_t)(h*LM+i))*LM+j]=p/ss;
}

// ------------- pinv init: row/col-sum maxima, denom, z0 = a2^T/den ---------
__global__ __launch_bounds__(256) void sums_k()
{
  int h=blockIdx.x, t=threadIdx.x;
  __shared__ float red[32];
  const float* a=g_a2+(size_t)h*LM*LM;
  float rs=0.f, cs=0.f;
  for(int j=0;j<LM;j++){ rs+=fabsf(a[(size_t)t*LM+j]); cs+=fabsf(a[(size_t)j*LM+t]); }
  float rm=bMax(rs,red), cm=bMax(cs,red);
  if(t==0){ g_mx[h]=rm; g_mx[NH+h]=cm; }
}
__global__ void denom_k()
{
  int t=threadIdx.x;
  float rm=(t<NH)?g_mx[t]:-3.4e38f, cm=(t<NH)?g_mx[NH+t]:-3.4e38f;
  rm=wMax(rm); cm=wMax(cm);
  if(t==0) g_den=rm*cm;
}
__global__ __launch_bounds__(256) void zinit_k()
{
  int i=blockIdx.x, h=blockIdx.y, j=threadIdx.x;
  float inv=1.f/g_den;
  g_z[((size_t)h*LM+i)*LM+j]=g_a2[((size_t)h*LM+j)*LM+i]*inv;
}

// ------------- PPEG: cf + dw7 + dw5 + dw3 ----------------------------------
__global__ __launch_bounds__(256) void ppeg_k(
    const float* __restrict__ w7, const float* __restrict__ b7,
    const float* __restrict__ w5, const float* __restrict__ b5,
    const float* __restrict__ w3, const float* __restrict__ b3)
{
  extern __shared__ float sm[];
  float* sin_=sm;          // 22*22*65
  float* w7s=sm+31460;     // 49*64
  float* w5s=sm+34596;     // 25*64
  float* w3s=sm+36196;     // 9*64
  float* bs =sm+36772;     // 64
  int t=threadIdx.x;
  int ty0=(blockIdx.x>>3)*16, tx0=(blockIdx.x&7)*16;
  int cbase=blockIdx.y*64;
  for(int idx=t;idx<22*22*64;idx+=256){
    int c=idx&63, pp=idx>>6, yy=pp/22, xx=pp%22;
    int gy=ty0+yy-3, gx=tx0+xx-3;
    sin_[(yy*22+xx)*65+c]=(gy>=0&&gy<128&&gx>=0&&gx<128)?
        g_h[(size_t)(1+gy*128+gx)*512+cbase+c]:0.f;
  }
  for(int idx=t;idx<49*64;idx+=256){ int c=idx&63,k=idx>>6; w7s[k*64+c]=w7[(cbase+c)*49+k]; }
  for(int idx=t;idx<25*64;idx+=256){ int c=idx&63,k=idx>>6; w5s[k*64+c]=w5[(cbase+c)*25+k]; }
  for(int idx=t;idx<9*64;idx+=256){ int c=idx&63,k=idx>>6; w3s[k*64+c]=w3[(cbase+c)*9+k]; }
  if(t<64) bs[t]=b7[cbase+t]+b5[cbase+t]+b3[cbase+t];
  __syncthreads();
  int py=t>>4, px=t&15;
  for(int c=0;c<64;c++){
    float acc=sin_[((py+3)*22+px+3)*65+c]+bs[c];
#pragma unroll
    for(int ky=0;ky<7;ky++)
#pragma unroll
      for(int kx=0;kx<7;kx++)
        acc+=sin_[((py+ky)*22+px+kx)*65+c]*w7s[(ky*7+kx)*64+c];
#pragma unroll
    for(int ky=0;ky<5;ky++)
#pragma unroll
      for(int kx=0;kx<5;kx++)
        acc+=sin_[((py+1+ky)*22+px+1+kx)*65+c]*w5s[(ky*5+kx)*64+c];
#pragma unroll
    for(int ky=0;ky<3;ky++)
#pragma unroll
      for(int kx=0;kx<3;kx++)
        acc+=sin_[((py+2+ky)*22+px+2+kx)*65+c]*w3s[(ky*3+kx)*64+c];
    g_h2[(size_t)(1+(ty0+py)*128+tx0+px)*512+cbase+c]=acc;
  }
}

// ------------- small helpers -----------------------------------------------
__global__ void clscopy_k(const float* __restrict__ cls){ g_h[threadIdx.x]=cls[threadIdx.x]; }
__global__ void row0cpy_k(){ g_h2[threadIdx.x]=g_h[threadIdx.x]; }

// ------------- final: cls out-proj + residual + LN + fc2 -------------------
__global__ __launch_bounds__(512) void final_k(
    const float* __restrict__ outw, const float* __restrict__ outb,
    const float* __restrict__ ng, const float* __restrict__ nb,
    const float* __restrict__ fw, const float* __restrict__ fb,
    float* __restrict__ out)
{
  __shared__ float sh[512]; __shared__ float red[32];
  int t=threadIdx.x;
  float acc=0.f;
  for(int k=0;k<512;k++) acc+=g_ao[k]*outw[(size_t)k*512+t];
  float row=g_h2[t]+acc+outb[t];
  float mean=bSum(row,red)*(1.f/512.f);
  float d=row-mean;
  float var=bSum(d*d,red)*(1.f/512.f);
  float y=d*(1.f/sqrtf(var+1e-5f))*ng[t]+nb[t];
  sh[t]=y;
  __syncthreads();
  if(t<4){
    float o=fb[t];
    for(int c=0;c<512;c++) o+=sh[c]*fw[c*4+t];
    out[t]=o;
  }
}

// ---------------- host orchestration ----------------------------------------
static void* sym(const void* s){ void* p=nullptr; cudaGetSymbolAddress(&p,s); return p; }

static void attn_layer(const float* hin, const float* ng, const float* nbi,
                       const float* qkvw, const float* outw, const float* outb,
                       const float* resw, int layer2,
                       float* ph, float* pxp, float* pqkv, float* pao,
                       float* pz, float* po3, float* pw2,
                       size_t a1sm, size_t a3sm)
{
  ln_pad_k<<<NPD,256>>>(hin,ng,nbi);
  gemm_tf32<0><<<dim3(1536/128,130),128>>>(pxp,qkvw,pqkv,nullptr,NPD,1536,512);
  landmarks_k<<<dim3(LM,NH),64>>>();
  a2_k<<<dim3(LM,NH),256>>>();
  sums_k<<<NH,256>>>();
  denom_k<<<1,32>>>();
  zinit_k<<<dim3(LM,NH),256>>>();
  nwt_k<<<NWT_BLOCKS,128>>>();                 // 6 Newton iters, final z in g_z
  a3f_k<<<dim3(2,NH,KC),128,a3sm>>>();         // fused flash a3 partials
  a3mrg_k<<<dim3(LM,NH),64>>>();               // merge -> o3
  g256t<<<dim3(1,4,NH),128>>>(pz,po3,pw2,64,1.f,0.f);
  if(!layer2){
    a1f_k<<<dim3((NR+127)/128,NH),128,a1sm>>>(resw,255,NR);
    gemm_tf32<2><<<dim3(4,(NR+127)/128),128>>>(pao,outw,ph,outb,NR,512,512);
  }else{
    a1f_k<<<dim3(1,NH),128,a1sm>>>(resw,255,1);
  }
}

extern "C" void kernel_launch(void* const* d_in, const int* in_sizes, int n_in,
                              void* d_out, int out_size)
{
  const float* x     =(const float*)d_in[0];
  const float* fc1w  =(const float*)d_in[1];
  const float* fc1b  =(const float*)d_in[2];
  const float* cls   =(const float*)d_in[3];
  const float* l1ng  =(const float*)d_in[4];
  const float* l1nb  =(const float*)d_in[5];
  const float* l1qkv =(const float*)d_in[6];
  const float* l1ow  =(const float*)d_in[7];
  const float* l1ob  =(const float*)d_in[8];
  const float* l1rw  =(const float*)d_in[9];

  int ppegBase, l2Base;
  if (in_sizes[10] == 25088) { ppegBase = 10; l2Base = 16; }
  else                       { l2Base = 10; ppegBase = 16; }

  const float* w7   =(const float*)d_in[ppegBase+0];
  const float* b7   =(const float*)d_in[ppegBase+1];
  const float* w5   =(const float*)d_in[ppegBase+2];
  const float* b5   =(const float*)d_in[ppegBase+3];
  const float* w3   =(const float*)d_in[ppegBase+4];
  const float* b3   =(const float*)d_in[ppegBase+5];
  const float* l2ng =(const float*)d_in[l2Base+0];
  const float* l2nb =(const float*)d_in[l2Base+1];
  const float* l2qkv=(const float*)d_in[l2Base+2];
  const float* l2ow =(const float*)d_in[l2Base+3];
  const float* l2ob =(const float*)d_in[l2Base+4];
  const float* l2rw =(const float*)d_in[l2Base+5];
  const float* nng  =(const float*)d_in[22];
  const float* nnb  =(const float*)d_in[23];
  const float* fc2w =(const float*)d_in[24];
  const float* fc2b =(const float*)d_in[25];
  float* out=(float*)d_out;

  float* ph  =(float*)sym(g_h);
  float* ph2 =(float*)sym(g_h2);
  float* pxp =(float*)sym(g_xp);
  float* pqkv=(float*)sym(g_qkv);
  float* pao =(float*)sym(g_ao);
  float* pz  =(float*)sym(g_z);
  float* po3 =(float*)sym(g_o3);
  float* pw2 =(float*)sym(g_w2);

  const size_t A1SM=36648*sizeof(unsigned);  // ~146.6 KB
  const size_t PPSM=36836*sizeof(float);     // ~147.3 KB
  const size_t A3SM=26368*sizeof(unsigned);  // ~105.5 KB
  cudaFuncSetAttribute(a1f_k, cudaFuncAttributeMaxDynamicSharedMemorySize,(int)A1SM);
  cudaFuncSetAttribute(ppeg_k,cudaFuncAttributeMaxDynamicSharedMemorySize,(int)PPSM);
  cudaFuncSetAttribute(a3f_k, cudaFuncAttributeMaxDynamicSharedMemorySize,(int)A3SM);

  // fc1 + cls
  gemm_tf32<1><<<dim3(4,128),128>>>(x,fc1w,ph+512,fc1b,16384,512,1024);
  clscopy_k<<<1,512>>>(cls);
  // layer 1
  attn_layer(ph,l1ng,l1nb,l1qkv,l1ow,l1ob,l1rw,0,
             ph,pxp,pqkv,pao,pz,po3,pw2,A1SM,A3SM);
  // PPEG
  row0cpy_k<<<1,512>>>();
  ppeg_k<<<dim3(64,8),256,PPSM>>>(w7,b7,w5,b5,w3,b3);
  // layer 2 (only cls row of attention output needed)
  attn_layer(ph2,l2ng,l2nb,l2qkv,l2ow,l2ob,l2rw,1,
             ph2,pxp,pqkv,pao,pz,po3,pw2,A1SM,A3SM);
  // final: out-proj row + residual + LN + fc2
  final_k<<<1,512>>>(l2ow,l2ob,nng,nnb,fc2w,fc2b,out);
}